// round 5
// baseline (speedup 1.0000x reference)
#include <cuda_runtime.h>
#include <math.h>
#include <stdint.h>

#define EMB 1024
#define D0PAD 1032          // 1026 padded to multiple of 8
#define MAXN 22016          // 22000 nodes padded to multiple of 128
#define RELSLOT 2048        // 2000 relations padded; fwd rows [0,2048), rev rows [2048,4096)
#define MAXE2 40960
#define MAX_TIES 1024

// ----------------------------------------------------------------------------
// Static scratch (no allocations allowed)
// ----------------------------------------------------------------------------
__device__ float g_h0[(size_t)MAXN * D0PAD];
__device__ float g_wself1p[(size_t)D0PAD * EMB];
__device__ float g_wmsgA1p[(size_t)D0PAD * EMB];
__device__ float g_relcat[(size_t)2 * RELSLOT * EMB];
__device__ float g_revh[(size_t)RELSLOT * EMB];
__device__ float g_Q[(size_t)2 * RELSLOT * EMB];
__device__ float g_Pself[(size_t)MAXN * EMB];
__device__ float g_Pmsg[(size_t)MAXN * EMB];
__device__ float g_agg[(size_t)MAXN * EMB];
__device__ float g_hnode[(size_t)MAXN * 2 * EMB];   // [h1 | h2]
__device__ float g_AB[(size_t)MAXN * 2 * EMB];      // [Asrc | Bdst]
__device__ float g_deg[MAXN];
__device__ float g_qb[EMB];
__device__ float g_y[MAXE2];
__device__ unsigned g_T;
__device__ int g_rem;
__device__ int g_tie[MAX_TIES];

// ----------------------------------------------------------------------------
// SGEMM: C[M,N] = A[M,K] @ B[K,N] (+bias)(+relu). M%128==0, N%128==0, K%8==0.
// 128x128 tile, BK=8, 256 threads, 8x8/thread, FFMA2 inner product.
// ----------------------------------------------------------------------------
__global__ __launch_bounds__(256, 2)
void sgemm_kernel(const float* __restrict__ A, int lda,
                  const float* __restrict__ B, int ldb,
                  float* __restrict__ C, int ldc,
                  int K, const float* __restrict__ bias, int dorelu)
{
    __shared__ __align__(16) float As[8][128];
    __shared__ __align__(16) float Bs[8][128];
    const int tid  = threadIdx.x;
    const int tcol = tid & 15;
    const int trow = tid >> 4;
    const int brow0 = blockIdx.y * 128;
    const int bcol0 = blockIdx.x * 128;
    const int aRow = tid >> 1;
    const int aCol = (tid & 1) * 4;
    const int bRow = tid >> 5;
    const int bCol = (tid & 31) * 4;
    const float* Ap = A + (size_t)(brow0 + aRow) * lda + aCol;
    const float* Bp = B + (size_t)bRow * ldb + bcol0 + bCol;

    unsigned long long acc[4][8];
#pragma unroll
    for (int m = 0; m < 4; m++)
#pragma unroll
        for (int n = 0; n < 8; n++) acc[m][n] = 0ull;

    for (int k0 = 0; k0 < K; k0 += 8) {
        float4 a4 = *reinterpret_cast<const float4*>(Ap);
        float4 b4 = *reinterpret_cast<const float4*>(Bp);
        As[aCol + 0][aRow] = a4.x;
        As[aCol + 1][aRow] = a4.y;
        As[aCol + 2][aRow] = a4.z;
        As[aCol + 3][aRow] = a4.w;
        *reinterpret_cast<float4*>(&Bs[bRow][bCol]) = b4;
        __syncthreads();
#pragma unroll
        for (int k = 0; k < 8; k++) {
            unsigned long long a2[4];
#pragma unroll
            for (int m = 0; m < 4; m++)
                a2[m] = *reinterpret_cast<const unsigned long long*>(&As[k][trow * 8 + 2 * m]);
            float4 b0 = *reinterpret_cast<const float4*>(&Bs[k][tcol * 8]);
            float4 b1 = *reinterpret_cast<const float4*>(&Bs[k][tcol * 8 + 4]);
            unsigned long long bb[8];
            asm("mov.b64 %0,{%1,%1};" : "=l"(bb[0]) : "f"(b0.x));
            asm("mov.b64 %0,{%1,%1};" : "=l"(bb[1]) : "f"(b0.y));
            asm("mov.b64 %0,{%1,%1};" : "=l"(bb[2]) : "f"(b0.z));
            asm("mov.b64 %0,{%1,%1};" : "=l"(bb[3]) : "f"(b0.w));
            asm("mov.b64 %0,{%1,%1};" : "=l"(bb[4]) : "f"(b1.x));
            asm("mov.b64 %0,{%1,%1};" : "=l"(bb[5]) : "f"(b1.y));
            asm("mov.b64 %0,{%1,%1};" : "=l"(bb[6]) : "f"(b1.z));
            asm("mov.b64 %0,{%1,%1};" : "=l"(bb[7]) : "f"(b1.w));
#pragma unroll
            for (int m = 0; m < 4; m++)
#pragma unroll
                for (int n = 0; n < 8; n++)
                    asm("fma.rn.f32x2 %0, %1, %2, %0;"
                        : "+l"(acc[m][n]) : "l"(a2[m]), "l"(bb[n]));
        }
        __syncthreads();
        Ap += 8;
        Bp += (size_t)8 * ldb;
    }

    const int c0 = bcol0 + tcol * 8;
    float bz[8];
    if (bias) {
        float4 v0 = *reinterpret_cast<const float4*>(bias + c0);
        float4 v1 = *reinterpret_cast<const float4*>(bias + c0 + 4);
        bz[0]=v0.x; bz[1]=v0.y; bz[2]=v0.z; bz[3]=v0.w;
        bz[4]=v1.x; bz[5]=v1.y; bz[6]=v1.z; bz[7]=v1.w;
    } else {
#pragma unroll
        for (int n = 0; n < 8; n++) bz[n] = 0.f;
    }
#pragma unroll
    for (int m = 0; m < 4; m++) {
        float lo[8], hi[8];
#pragma unroll
        for (int n = 0; n < 8; n++)
            asm("mov.b64 {%0,%1}, %2;" : "=f"(lo[n]), "=f"(hi[n]) : "l"(acc[m][n]));
        int r0 = brow0 + trow * 8 + 2 * m;
#pragma unroll
        for (int n = 0; n < 8; n++) {
            lo[n] += bz[n];
            hi[n] += bz[n];
            if (dorelu) { lo[n] = fmaxf(lo[n], 0.f); hi[n] = fmaxf(hi[n], 0.f); }
        }
        float* Crow0 = C + (size_t)r0 * ldc + c0;
        float* Crow1 = C + (size_t)(r0 + 1) * ldc + c0;
        *reinterpret_cast<float4*>(Crow0)     = make_float4(lo[0], lo[1], lo[2], lo[3]);
        *reinterpret_cast<float4*>(Crow0 + 4) = make_float4(lo[4], lo[5], lo[6], lo[7]);
        *reinterpret_cast<float4*>(Crow1)     = make_float4(hi[0], hi[1], hi[2], hi[3]);
        *reinterpret_cast<float4*>(Crow1 + 4) = make_float4(hi[4], hi[5], hi[6], hi[7]);
    }
}

// ----------------------------------------------------------------------------
// Small helper kernels
// ----------------------------------------------------------------------------
__global__ void zero_kernel(float4* p, int n4) {
    int i = blockIdx.x * blockDim.x + threadIdx.x;
    int stride = gridDim.x * blockDim.x;
    float4 z = make_float4(0.f, 0.f, 0.f, 0.f);
    for (; i < n4; i += stride) p[i] = z;
}

__global__ void build_h0_kernel(const float* __restrict__ entity,
                                const float* __restrict__ nontext,
                                const float* __restrict__ topic,
                                int n_text, int n_nodes)
{
    int n = blockIdx.x;
    if (n >= n_nodes) return;
    float* dst = g_h0 + (size_t)n * D0PAD;
    const float* src = (n < n_text) ? (entity + (size_t)n * EMB) : nontext;
    for (int j = threadIdx.x; j < D0PAD; j += blockDim.x) {
        float v;
        if (j < EMB)          v = src[j];
        else if (j < EMB + 2) v = topic[(size_t)n * 2 + (j - EMB)];
        else                  v = 0.f;
        dst[j] = v;
    }
}

__global__ void padw_kernel(const float* __restrict__ in, float* __restrict__ out, int krows) {
    int i = blockIdx.x * blockDim.x + threadIdx.x;
    if (i >= D0PAD * EMB) return;
    int row = i / EMB;
    out[i] = (row < krows) ? in[i] : 0.f;
}

__global__ void relcat_kernel(const float* __restrict__ rel, int n_rel) {
    int i = blockIdx.x * blockDim.x + threadIdx.x;
    if (i >= RELSLOT * EMB) return;
    int row = i / EMB;
    g_relcat[i] = (row < n_rel) ? rel[i] : 0.f;
}

__global__ void deg_kernel(const int* __restrict__ h_id, const int* __restrict__ t_id, int E) {
    int i = blockIdx.x * blockDim.x + threadIdx.x;
    if (i >= 2 * E) return;
    int dst = (i < E) ? t_id[i] : h_id[i - E];
    atomicAdd(&g_deg[dst], 1.0f);
}

// msg = relu(Pmsg[src] + Q[rel]); agg[dst] += msg  (bias folded into Pmsg)
__global__ void edge_msg_kernel(const int* __restrict__ h_id, const int* __restrict__ t_id,
                                const int* __restrict__ r_id, int E)
{
    int e = blockIdx.x;
    int src, dst, rel;
    if (e < E) { src = h_id[e]; dst = t_id[e]; rel = r_id[e]; }
    else { int e2 = e - E; src = t_id[e2]; dst = h_id[e2]; rel = RELSLOT + r_id[e2]; }
    int j = threadIdx.x;  // 256 threads, one float4 each
    const float4 pv = reinterpret_cast<const float4*>(g_Pmsg + (size_t)src * EMB)[j];
    const float4 qv = reinterpret_cast<const float4*>(g_Q + (size_t)rel * EMB)[j];
    float4 m;
    m.x = fmaxf(pv.x + qv.x, 0.f);
    m.y = fmaxf(pv.y + qv.y, 0.f);
    m.z = fmaxf(pv.z + qv.z, 0.f);
    m.w = fmaxf(pv.w + qv.w, 0.f);
    atomicAdd(reinterpret_cast<float4*>(g_agg + (size_t)dst * EMB) + j, m);
}

// h = relu(Pself + agg/max(deg,1)) -> hnode[:, layer*EMB : ]
__global__ void node_update_kernel(int n_nodes, int layer) {
    int i = blockIdx.x * blockDim.x + threadIdx.x;   // float4 index
    int total = n_nodes * (EMB / 4);
    if (i >= total) return;
    int n = i >> 8;        // EMB/4 = 256
    int j4 = i & 255;
    float inv = 1.0f / fmaxf(g_deg[n], 1.0f);
    float4 ps = reinterpret_cast<const float4*>(g_Pself + (size_t)n * EMB)[j4];
    float4 ag = reinterpret_cast<const float4*>(g_agg + (size_t)n * EMB)[j4];
    float4 v;
    v.x = fmaxf(ps.x + ag.x * inv, 0.f);
    v.y = fmaxf(ps.y + ag.y * inv, 0.f);
    v.z = fmaxf(ps.z + ag.z * inv, 0.f);
    v.w = fmaxf(ps.w + ag.w * inv, 0.f);
    reinterpret_cast<float4*>(g_hnode + (size_t)n * 2 * EMB + (size_t)layer * EMB)[j4] = v;
}

// qb[j] = sum_k q[k] * pred_w1[k, j] + pred_b1[j]   (first EMB rows of pred_w1)
__global__ void qb_kernel(const float* __restrict__ q, const float* __restrict__ predw1,
                          const float* __restrict__ predb1)
{
    int j = blockIdx.x * blockDim.x + threadIdx.x;
    if (j >= EMB) return;
    float acc = 0.f;
    for (int k = 0; k < EMB; k++) acc += q[k] * predw1[(size_t)k * EMB + j];
    g_qb[j] = acc + predb1[j];
}

// ----------------------------------------------------------------------------
// Threefry2x32 (JAX key(42)) + Gumbel — PARTITIONABLE counter scheme:
// element e -> counter u64 e -> (x0 = e>>32 = 0, x1 = e); 32-bit out = y0 ^ y1.
// ----------------------------------------------------------------------------
__device__ __forceinline__ void threefry2x32(unsigned k0, unsigned k1,
                                             unsigned& x0, unsigned& x1)
{
    unsigned ks2 = k0 ^ k1 ^ 0x1BD11BDAu;
    x0 += k0; x1 += k1;
#define TFR(r) { x0 += x1; x1 = (x1 << (r)) | (x1 >> (32 - (r))); x1 ^= x0; }
    TFR(13) TFR(15) TFR(26) TFR(6)
    x0 += k1;  x1 += ks2 + 1u;
    TFR(17) TFR(29) TFR(16) TFR(24)
    x0 += ks2; x1 += k0 + 2u;
    TFR(13) TFR(15) TFR(26) TFR(6)
    x0 += k0;  x1 += k1 + 3u;
    TFR(17) TFR(29) TFR(16) TFR(24)
    x0 += k1;  x1 += ks2 + 4u;
    TFR(13) TFR(15) TFR(26) TFR(6)
    x0 += ks2; x1 += k0 + 5u;
#undef TFR
}

__device__ __forceinline__ float gumbel_noise(int e) {
    unsigned x0 = 0u;                 // high 32 bits of the u64 counter
    unsigned x1 = (unsigned)e;        // low 32 bits
    threefry2x32(0u, 42u, x0, x1);
    unsigned bits = x0 ^ x1;          // 32-bit partitionable output
    float f = __uint_as_float((bits >> 9) | 0x3f800000u) - 1.0f;  // [0,1)
    float u = fmaxf(1e-10f, f + 1e-10f);
    return -logf(-logf(u));
}

// y = relu(qb + A[src] + R[rel] + B[dst]) . w2 + b2 + gumbel
__global__ void edge_logits_kernel(const int* __restrict__ h_id, const int* __restrict__ t_id,
                                   const int* __restrict__ r_id, int E,
                                   const float* __restrict__ w2, const float* __restrict__ b2)
{
    int e = blockIdx.x;
    int src, dst, rel;
    if (e < E) { src = h_id[e]; dst = t_id[e]; rel = r_id[e]; }
    else { int e2 = e - E; src = t_id[e2]; dst = h_id[e2]; rel = RELSLOT + r_id[e2]; }
    int tid = threadIdx.x;  // 256
    float4 a  = reinterpret_cast<const float4*>(g_AB + (size_t)src * 2 * EMB)[tid];
    float4 b  = reinterpret_cast<const float4*>(g_AB + (size_t)dst * 2 * EMB + EMB)[tid];
    float4 rr = reinterpret_cast<const float4*>(g_Q + (size_t)rel * EMB)[tid];
    float4 qv = reinterpret_cast<const float4*>(g_qb)[tid];
    float4 w  = reinterpret_cast<const float4*>(w2)[tid];
    float acc = fmaxf(qv.x + a.x + rr.x + b.x, 0.f) * w.x
              + fmaxf(qv.y + a.y + rr.y + b.y, 0.f) * w.y
              + fmaxf(qv.z + a.z + rr.z + b.z, 0.f) * w.z
              + fmaxf(qv.w + a.w + rr.w + b.w, 0.f) * w.w;
#pragma unroll
    for (int o = 16; o; o >>= 1) acc += __shfl_xor_sync(0xffffffffu, acc, o);
    __shared__ float sred[8];
    if ((tid & 31) == 0) sred[tid >> 5] = acc;
    __syncthreads();
    if (tid == 0) {
        float s = 0.f;
#pragma unroll
        for (int wdx = 0; wdx < 8; wdx++) s += sred[wdx];
        g_y[e] = s + b2[0] + gumbel_noise(e);
    }
}

// ----------------------------------------------------------------------------
// Exact top-K via single-block radix select (order-preserving uint keys)
// ----------------------------------------------------------------------------
__device__ __forceinline__ unsigned f2key(float v) {
    unsigned b = __float_as_uint(v);
    return (b & 0x80000000u) ? ~b : (b | 0x80000000u);
}

__global__ void topk_kernel(int n, int K) {
    __shared__ unsigned hist[256];
    __shared__ unsigned s_prefix;
    __shared__ int s_krem;
    __shared__ int s_cnt;
    int tid = threadIdx.x;
    if (tid == 0) { s_prefix = 0; s_krem = K; s_cnt = 0; }
    __syncthreads();
    for (int pass = 3; pass >= 0; pass--) {
        int shift = pass * 8;
        if (tid < 256) hist[tid] = 0;
        __syncthreads();
        unsigned prefix = s_prefix;
        for (int i = tid; i < n; i += blockDim.x) {
            unsigned key = f2key(g_y[i]);
            bool match = (pass == 3) || ((key >> (shift + 8)) == (prefix >> (shift + 8)));
            if (match) atomicAdd(&hist[(key >> shift) & 255], 1u);
        }
        __syncthreads();
        if (tid == 0) {
            int krem = s_krem;
            unsigned cum = 0;
            int b = 255;
            for (; b >= 0; b--) {
                if (cum + hist[b] >= (unsigned)krem) break;
                cum += hist[b];
            }
            if (b < 0) b = 0;
            s_prefix = prefix | ((unsigned)b << shift);
            s_krem = krem - (int)cum;
        }
        __syncthreads();
    }
    unsigned T = s_prefix;
    int rem = s_krem;
    for (int i = tid; i < n; i += blockDim.x) {
        if (f2key(g_y[i]) == T) {
            int p = atomicAdd(&s_cnt, 1);
            if (p < MAX_TIES) g_tie[p] = i;
        }
    }
    __syncthreads();
    if (tid == 0) {
        int c = s_cnt < MAX_TIES ? s_cnt : MAX_TIES;
        for (int a = 1; a < c; a++) {        // ascending index (top_k tie rule)
            int v = g_tie[a];
            int b = a - 1;
            while (b >= 0 && g_tie[b] > v) { g_tie[b + 1] = g_tie[b]; b--; }
            g_tie[b + 1] = v;
        }
        if (rem > c) rem = c;
        if (rem < 0) rem = 0;
        g_T = T;
        g_rem = rem;
    }
}

__global__ void output_kernel(float* __restrict__ out, int n) {
    int i = blockIdx.x * blockDim.x + threadIdx.x;
    if (i >= n) return;
    unsigned key = f2key(g_y[i]);
    float o = 0.f;
    unsigned T = g_T;
    if (key > T) o = 1.f;
    else if (key == T) {
        int rem = g_rem;
        for (int t = 0; t < rem; t++)
            if (g_tie[t] == i) { o = 1.f; break; }
    }
    out[i] = o;
}

// ----------------------------------------------------------------------------
// Launch
// ----------------------------------------------------------------------------
static void launch_gemm(const float* A, int lda, const float* B, int ldb,
                        float* C, int ldc, int M, int N, int K,
                        const float* bias, int relu)
{
    dim3 grid(N / 128, M / 128);
    sgemm_kernel<<<grid, 256>>>(A, lda, B, ldb, C, ldc, K, bias, relu);
}

extern "C" void kernel_launch(void* const* d_in, const int* in_sizes, int n_in,
                              void* d_out, int out_size)
{
    const int* h_id = (const int*)d_in[0];
    const int* t_id = (const int*)d_in[1];
    const int* r_id = (const int*)d_in[2];
    // index 3 is the scalar num_non_text_entities if present (n_in == 25)
    const int s = (n_in >= 25) ? 1 : 0;
    const int b0 = 3 + s;
    const float* q_emb   = (const float*)d_in[b0 + 0];
    const float* entity  = (const float*)d_in[b0 + 1];
    const float* rel     = (const float*)d_in[b0 + 2];
    const float* topic   = (const float*)d_in[b0 + 3];
    const float* nontext = (const float*)d_in[b0 + 4];
    const float* wself1  = (const float*)d_in[b0 + 5];
    const float* bself1  = (const float*)d_in[b0 + 6];
    const float* wmsg1   = (const float*)d_in[b0 + 7];
    const float* bmsg1   = (const float*)d_in[b0 + 8];
    const float* wself2  = (const float*)d_in[b0 + 9];
    const float* bself2  = (const float*)d_in[b0 + 10];
    const float* wmsg2   = (const float*)d_in[b0 + 11];
    const float* bmsg2   = (const float*)d_in[b0 + 12];
    const float* revw1   = (const float*)d_in[b0 + 13];
    const float* revb1   = (const float*)d_in[b0 + 14];
    const float* revw2   = (const float*)d_in[b0 + 15];
    const float* revb2   = (const float*)d_in[b0 + 16];
    const float* predw1  = (const float*)d_in[b0 + 17];
    const float* predb1  = (const float*)d_in[b0 + 18];
    const float* predw2  = (const float*)d_in[b0 + 19];
    const float* predb2  = (const float*)d_in[b0 + 20];

    const int E       = in_sizes[0];
    const int n_text  = in_sizes[b0 + 1] / EMB;
    const int n_rel   = in_sizes[b0 + 2] / EMB;
    const int n_nodes = in_sizes[b0 + 3] / 2;
    const int d0      = in_sizes[b0 + 5] / EMB;   // 1026
    const int E2      = 2 * E;
    if (n_nodes > MAXN || E2 > MAXE2 || n_rel > RELSLOT || d0 > D0PAD) return;

    float *p_h0, *p_wself1p, *p_wmsgA1p, *p_relcat, *p_revh, *p_Q,
          *p_Pself, *p_Pmsg, *p_agg, *p_hnode, *p_AB, *p_deg;
    cudaGetSymbolAddress((void**)&p_h0,      g_h0);
    cudaGetSymbolAddress((void**)&p_wself1p, g_wself1p);
    cudaGetSymbolAddress((void**)&p_wmsgA1p, g_wmsgA1p);
    cudaGetSymbolAddress((void**)&p_relcat,  g_relcat);
    cudaGetSymbolAddress((void**)&p_revh,    g_revh);
    cudaGetSymbolAddress((void**)&p_Q,       g_Q);
    cudaGetSymbolAddress((void**)&p_Pself,   g_Pself);
    cudaGetSymbolAddress((void**)&p_Pmsg,    g_Pmsg);
    cudaGetSymbolAddress((void**)&p_agg,     g_agg);
    cudaGetSymbolAddress((void**)&p_hnode,   g_hnode);
    cudaGetSymbolAddress((void**)&p_AB,      g_AB);
    cudaGetSymbolAddress((void**)&p_deg,     g_deg);

    // ---- prep ----
    zero_kernel<<<1024, 256>>>((float4*)p_agg, MAXN * EMB / 4);
    zero_kernel<<<32, 256>>>((float4*)p_deg, MAXN / 4);
    build_h0_kernel<<<n_nodes, 256>>>(entity, nontext, topic, n_text, n_nodes);
    padw_kernel<<<(D0PAD * EMB + 255) / 256, 256>>>(wself1, p_wself1p, d0);
    padw_kernel<<<(D0PAD * EMB + 255) / 256, 256>>>(wmsg1, p_wmsgA1p, d0);
    relcat_kernel<<<(RELSLOT * EMB + 255) / 256, 256>>>(rel, n_rel);
    deg_kernel<<<(E2 + 255) / 256, 256>>>(h_id, t_id, E);

    // reverse-relation MLP: rev table into g_relcat rows [RELSLOT, 2*RELSLOT)
    launch_gemm(p_relcat, EMB, revw1, EMB, p_revh, EMB, RELSLOT, EMB, EMB, revb1, 1);
    launch_gemm(p_revh, EMB, revw2, EMB, p_relcat + (size_t)RELSLOT * EMB, EMB,
                RELSLOT, EMB, EMB, revb2, 0);

    // ---- SAGE layer 1 ----
    launch_gemm(p_relcat, EMB, wmsg1 + (size_t)d0 * EMB, EMB, p_Q, EMB,
                2 * RELSLOT, EMB, EMB, nullptr, 0);
    launch_gemm(p_h0, D0PAD, p_wmsgA1p, EMB, p_Pmsg, EMB, MAXN, EMB, D0PAD, bmsg1, 0);
    launch_gemm(p_h0, D0PAD, p_wself1p, EMB, p_Pself, EMB, MAXN, EMB, D0PAD, bself1, 0);
    edge_msg_kernel<<<E2, 256>>>(h_id, t_id, r_id, E);
    node_update_kernel<<<(n_nodes * (EMB / 4) + 255) / 256, 256>>>(n_nodes, 0);

    // ---- SAGE layer 2 ----
    zero_kernel<<<1024, 256>>>((float4*)p_agg, MAXN * EMB / 4);
    launch_gemm(p_relcat, EMB, wmsg2 + (size_t)EMB * EMB, EMB, p_Q, EMB,
                2 * RELSLOT, EMB, EMB, nullptr, 0);
    launch_gemm(p_hnode, 2 * EMB, wmsg2, EMB, p_Pmsg, EMB, MAXN, EMB, EMB, bmsg2, 0);
    launch_gemm(p_hnode, 2 * EMB, wself2, EMB, p_Pself, EMB, MAXN, EMB, EMB, bself2, 0);
    edge_msg_kernel<<<E2, 256>>>(h_id, t_id, r_id, E);
    node_update_kernel<<<(n_nodes * (EMB / 4) + 255) / 256, 256>>>(n_nodes, 1);

    // ---- predictor projections ----
    // pred_w1 rows: [0,EMB)=q, [EMB,3EMB)=h_node[src], [3EMB,4EMB)=h_r, [4EMB,6EMB)=h_node[dst]
    launch_gemm(p_relcat, EMB, predw1 + (size_t)3 * EMB * EMB, EMB, p_Q, EMB,
                2 * RELSLOT, EMB, EMB, nullptr, 0);
    launch_gemm(p_hnode, 2 * EMB, predw1 + (size_t)EMB * EMB, EMB, p_AB, 2 * EMB,
                MAXN, EMB, 2 * EMB, nullptr, 0);
    launch_gemm(p_hnode, 2 * EMB, predw1 + (size_t)4 * EMB * EMB, EMB, p_AB + EMB, 2 * EMB,
                MAXN, EMB, 2 * EMB, nullptr, 0);
    qb_kernel<<<4, 256>>>(q_emb, predw1, predb1);

    // ---- edge logits + gumbel + exact top-K ----
    edge_logits_kernel<<<E2, 256>>>(h_id, t_id, r_id, E, predw2, predb2);
    topk_kernel<<<1, 1024>>>(E2, 512);
    output_kernel<<<(E2 + 255) / 256, 256>>>((float*)d_out, E2);
}

// round 12
// speedup vs baseline: 1.7398x; 1.7398x over previous
#include <cuda_runtime.h>
#include <cuda_bf16.h>
#include <math.h>
#include <stdint.h>

#define EMB 1024
#define D0PAD 1032
#define MAXN 22016
#define RELSLOT 2048
#define MAXE2 40960
#define MAX_TIES 1024
#define KPMAX 6144

// ---------------- mma.sync GEMM tile config ----------------
#define BM 128
#define BN 128
#define BKP 20            // uint32 (bf16 pairs) per smem row: 16 + 4 pad
#define BUFU 5120         // uint32 per buffer (A 2560 + B 2560)

// ----------------------------------------------------------------------------
// Static scratch
// ----------------------------------------------------------------------------
__device__ float g_h0[(size_t)MAXN * D0PAD];
__device__ float g_relcat[(size_t)2 * RELSLOT * EMB];
__device__ float g_revh[(size_t)RELSLOT * EMB];
__device__ float g_Q[(size_t)2 * RELSLOT * EMB];
__device__ float g_Pself[(size_t)MAXN * EMB];
__device__ float g_Pmsg[(size_t)MAXN * EMB];
__device__ float g_agg[(size_t)MAXN * EMB];
__device__ float g_hnode[(size_t)MAXN * 2 * EMB];   // [h1 | h2]
__device__ float g_AB[(size_t)MAXN * 2 * EMB];      // [Asrc | Bdst]
__device__ float g_deg[MAXN];
__device__ float g_qb[EMB];
__device__ float g_y[MAXE2];
__device__ unsigned g_T;
__device__ int g_rem;
__device__ int g_tie[MAX_TIES];
// bf16 split operand buffers
__device__ __nv_bfloat16 g_sa[(size_t)MAXN * KPMAX];           // A' big
__device__ __nv_bfloat16 g_sarel[(size_t)2 * RELSLOT * 3072];  // relcat A' (reused 3x)
__device__ __nv_bfloat16 g_sb[(size_t)EMB * KPMAX];            // B'

// ----------------------------------------------------------------------------
// bf16 split GEMM via mma.sync.m16n8k16 (HMMA — baseline PTX, no 'a' features)
// C[M,N] = A'[M,KP] · B'[N,KP]^T  (+bias)(+relu).  M%128==0, N%128==0, KP%32==0.
// grid = (N/128, M/128), 256 threads = 8 warps (2 m x 4 n), warp tile 64x32.
// ----------------------------------------------------------------------------
__global__ __launch_bounds__(256, 2)
void gemm_mma(const __nv_bfloat16* __restrict__ A, const __nv_bfloat16* __restrict__ B,
              float* __restrict__ C, int ldc, int KP,
              const float* __restrict__ bias, int dorelu)
{
    __shared__ uint32_t sm[2 * BUFU];   // 40 KB
    const int tid  = threadIdx.x;
    const int wid  = tid >> 5;
    const int lane = tid & 31;
    const int bm0 = blockIdx.y * BM;
    const int bn0 = blockIdx.x * BN;
    const int wm0 = (wid & 1) * 64;
    const int wn0 = (wid >> 1) * 32;
    const int g = lane >> 2;      // 0..7
    const int q = lane & 3;       // 0..3

    // global load indices: 512 uint4 per operand tile, 2 per thread
    const int r0 = tid >> 2, kq0 = tid & 3;            // u = tid
    const int r1 = (tid + 256) >> 2, kq1 = tid & 3;    // u = tid+256

    float c[4][4][4];
#pragma unroll
    for (int ma = 0; ma < 4; ma++)
#pragma unroll
        for (int na = 0; na < 4; na++)
#pragma unroll
            for (int i = 0; i < 4; i++) c[ma][na][i] = 0.f;

    const int nchunk = KP >> 5;

    // prologue: load chunk 0 into buf 0
    {
        uint4 a0 = *reinterpret_cast<const uint4*>(A + (size_t)(bm0 + r0) * KP + kq0 * 8);
        uint4 a1 = *reinterpret_cast<const uint4*>(A + (size_t)(bm0 + r1) * KP + kq1 * 8);
        uint4 b0 = *reinterpret_cast<const uint4*>(B + (size_t)(bn0 + r0) * KP + kq0 * 8);
        uint4 b1 = *reinterpret_cast<const uint4*>(B + (size_t)(bn0 + r1) * KP + kq1 * 8);
        *reinterpret_cast<uint4*>(&sm[r0 * BKP + kq0 * 4]) = a0;
        *reinterpret_cast<uint4*>(&sm[r1 * BKP + kq1 * 4]) = a1;
        *reinterpret_cast<uint4*>(&sm[2560 + r0 * BKP + kq0 * 4]) = b0;
        *reinterpret_cast<uint4*>(&sm[2560 + r1 * BKP + kq1 * 4]) = b1;
    }
    __syncthreads();

    for (int ck = 0; ck < nchunk; ck++) {
        const int cur = ck & 1;
        uint4 pa0, pa1, pb0, pb1;
        const bool more = (ck + 1 < nchunk);
        if (more) {
            const int kc = (ck + 1) * 32;
            pa0 = *reinterpret_cast<const uint4*>(A + (size_t)(bm0 + r0) * KP + kc + kq0 * 8);
            pa1 = *reinterpret_cast<const uint4*>(A + (size_t)(bm0 + r1) * KP + kc + kq1 * 8);
            pb0 = *reinterpret_cast<const uint4*>(B + (size_t)(bn0 + r0) * KP + kc + kq0 * 8);
            pb1 = *reinterpret_cast<const uint4*>(B + (size_t)(bn0 + r1) * KP + kc + kq1 * 8);
        }

        const uint32_t* Ab = sm + cur * BUFU;
        const uint32_t* Bb = Ab + 2560;
#pragma unroll
        for (int s = 0; s < 2; s++) {
            const int kp = s * 8 + q;
            uint32_t af[4][4], bf[4][2];
#pragma unroll
            for (int ma = 0; ma < 4; ma++) {
                const int r = wm0 + ma * 16 + g;
                af[ma][0] = Ab[r * BKP + kp];
                af[ma][1] = Ab[(r + 8) * BKP + kp];
                af[ma][2] = Ab[r * BKP + kp + 4];
                af[ma][3] = Ab[(r + 8) * BKP + kp + 4];
            }
#pragma unroll
            for (int na = 0; na < 4; na++) {
                const int nn = wn0 + na * 8 + g;
                bf[na][0] = Bb[nn * BKP + kp];
                bf[na][1] = Bb[nn * BKP + kp + 4];
            }
#pragma unroll
            for (int ma = 0; ma < 4; ma++)
#pragma unroll
                for (int na = 0; na < 4; na++)
                    asm volatile(
                        "mma.sync.aligned.m16n8k16.row.col.f32.bf16.bf16.f32 "
                        "{%0,%1,%2,%3}, {%4,%5,%6,%7}, {%8,%9}, {%0,%1,%2,%3};"
                        : "+f"(c[ma][na][0]), "+f"(c[ma][na][1]),
                          "+f"(c[ma][na][2]), "+f"(c[ma][na][3])
                        : "r"(af[ma][0]), "r"(af[ma][1]), "r"(af[ma][2]), "r"(af[ma][3]),
                          "r"(bf[na][0]), "r"(bf[na][1]));
        }

        if (more) {
            uint32_t* An = sm + (cur ^ 1) * BUFU;
            uint32_t* Bn = An + 2560;
            *reinterpret_cast<uint4*>(&An[r0 * BKP + kq0 * 4]) = pa0;
            *reinterpret_cast<uint4*>(&An[r1 * BKP + kq1 * 4]) = pa1;
            *reinterpret_cast<uint4*>(&Bn[r0 * BKP + kq0 * 4]) = pb0;
            *reinterpret_cast<uint4*>(&Bn[r1 * BKP + kq1 * 4]) = pb1;
        }
        __syncthreads();
    }

    // epilogue
#pragma unroll
    for (int ma = 0; ma < 4; ma++) {
        const int row = bm0 + wm0 + ma * 16 + g;
#pragma unroll
        for (int na = 0; na < 4; na++) {
            const int col = bn0 + wn0 + na * 8 + q * 2;
            float v0 = c[ma][na][0], v1 = c[ma][na][1];
            float v2 = c[ma][na][2], v3 = c[ma][na][3];
            if (bias) {
                float bx = bias[col], by = bias[col + 1];
                v0 += bx; v1 += by; v2 += bx; v3 += by;
            }
            if (dorelu) {
                v0 = fmaxf(v0, 0.f); v1 = fmaxf(v1, 0.f);
                v2 = fmaxf(v2, 0.f); v3 = fmaxf(v3, 0.f);
            }
            *reinterpret_cast<float2*>(C + (size_t)row * ldc + col) = make_float2(v0, v1);
            *reinterpret_cast<float2*>(C + (size_t)(row + 8) * ldc + col) = make_float2(v2, v3);
        }
    }
}

// ----------------------------------------------------------------------------
// Split kernels: fp32 -> bf16 triple layout
// A' = [hi | lo | hi] along K ; B' = [hi | hi | lo] (with transpose)
// ----------------------------------------------------------------------------
__global__ void split_a_kernel(const float* __restrict__ A, int lda, int M, int K,
                               int K64, int KP, __nv_bfloat16* __restrict__ out)
{
    long long idx = (long long)blockIdx.x * blockDim.x + threadIdx.x;
    long long total = (long long)M * K64;
    if (idx >= total) return;
    int row = (int)(idx / K64);
    int kk = (int)(idx % K64);
    float v = (kk < K) ? A[(size_t)row * lda + kk] : 0.f;
    __nv_bfloat16 hi = __float2bfloat16(v);
    __nv_bfloat16 lo = __float2bfloat16(v - __bfloat162float(hi));
    __nv_bfloat16* o = out + (size_t)row * KP;
    o[kk] = hi;
    o[K64 + kk] = lo;
    o[2 * K64 + kk] = hi;
}

__global__ void split_b_kernel(const float* __restrict__ W, int ldw, int K, int N,
                               int K64, int KP, __nv_bfloat16* __restrict__ out)
{
    __shared__ float t[32][33];
    int kk0 = blockIdx.y * 32, n0 = blockIdx.x * 32;
    int tx = threadIdx.x, ty = threadIdx.y;   // 32x8
#pragma unroll
    for (int j = 0; j < 32; j += 8) {
        int kk = kk0 + ty + j, n = n0 + tx;
        t[ty + j][tx] = (kk < K && n < N) ? W[(size_t)kk * ldw + n] : 0.f;
    }
    __syncthreads();
#pragma unroll
    for (int j = 0; j < 32; j += 8) {
        int n = n0 + ty + j, kk = kk0 + tx;
        if (n < N && kk < K64) {
            float v = t[tx][ty + j];
            __nv_bfloat16 hi = __float2bfloat16(v);
            __nv_bfloat16 lo = __float2bfloat16(v - __bfloat162float(hi));
            __nv_bfloat16* o = out + (size_t)n * KP;
            o[kk] = hi;
            o[K64 + kk] = hi;
            o[2 * K64 + kk] = lo;
        }
    }
}

// ----------------------------------------------------------------------------
// Non-GEMM kernels (unchanged from passing R5 kernel)
// ----------------------------------------------------------------------------
__global__ void zero_kernel(float4* p, int n4) {
    int i = blockIdx.x * blockDim.x + threadIdx.x;
    int stride = gridDim.x * blockDim.x;
    float4 z = make_float4(0.f, 0.f, 0.f, 0.f);
    for (; i < n4; i += stride) p[i] = z;
}

__global__ void build_h0_kernel(const float* __restrict__ entity,
                                const float* __restrict__ nontext,
                                const float* __restrict__ topic,
                                int n_text, int n_nodes)
{
    int n = blockIdx.x;
    if (n >= n_nodes) return;
    float* dst = g_h0 + (size_t)n * D0PAD;
    const float* src = (n < n_text) ? (entity + (size_t)n * EMB) : nontext;
    for (int j = threadIdx.x; j < D0PAD; j += blockDim.x) {
        float v;
        if (j < EMB)          v = src[j];
        else if (j < EMB + 2) v = topic[(size_t)n * 2 + (j - EMB)];
        else                  v = 0.f;
        dst[j] = v;
    }
}

__global__ void relcat_kernel(const float* __restrict__ rel, int n_rel) {
    int i = blockIdx.x * blockDim.x + threadIdx.x;
    if (i >= RELSLOT * EMB) return;
    int row = i / EMB;
    g_relcat[i] = (row < n_rel) ? rel[i] : 0.f;
}

__global__ void deg_kernel(const int* __restrict__ h_id, const int* __restrict__ t_id, int E) {
    int i = blockIdx.x * blockDim.x + threadIdx.x;
    if (i >= 2 * E) return;
    int dst = (i < E) ? t_id[i] : h_id[i - E];
    atomicAdd(&g_deg[dst], 1.0f);
}

__global__ void edge_msg_kernel(const int* __restrict__ h_id, const int* __restrict__ t_id,
                                const int* __restrict__ r_id, int E)
{
    int e = blockIdx.x;
    int src, dst, rel;
    if (e < E) { src = h_id[e]; dst = t_id[e]; rel = r_id[e]; }
    else { int e2 = e - E; src = t_id[e2]; dst = h_id[e2]; rel = RELSLOT + r_id[e2]; }
    int j = threadIdx.x;
    const float4 pv = reinterpret_cast<const float4*>(g_Pmsg + (size_t)src * EMB)[j];
    const float4 qv = reinterpret_cast<const float4*>(g_Q + (size_t)rel * EMB)[j];
    float4 m;
    m.x = fmaxf(pv.x + qv.x, 0.f);
    m.y = fmaxf(pv.y + qv.y, 0.f);
    m.z = fmaxf(pv.z + qv.z, 0.f);
    m.w = fmaxf(pv.w + qv.w, 0.f);
    atomicAdd(reinterpret_cast<float4*>(g_agg + (size_t)dst * EMB) + j, m);
}

__global__ void node_update_kernel(int n_nodes, int layer) {
    int i = blockIdx.x * blockDim.x + threadIdx.x;
    int total = n_nodes * (EMB / 4);
    if (i >= total) return;
    int n = i >> 8;
    int j4 = i & 255;
    float inv = 1.0f / fmaxf(g_deg[n], 1.0f);
    float4 ps = reinterpret_cast<const float4*>(g_Pself + (size_t)n * EMB)[j4];
    float4 ag = reinterpret_cast<const float4*>(g_agg + (size_t)n * EMB)[j4];
    float4 v;
    v.x = fmaxf(ps.x + ag.x * inv, 0.f);
    v.y = fmaxf(ps.y + ag.y * inv, 0.f);
    v.z = fmaxf(ps.z + ag.z * inv, 0.f);
    v.w = fmaxf(ps.w + ag.w * inv, 0.f);
    reinterpret_cast<float4*>(g_hnode + (size_t)n * 2 * EMB + (size_t)layer * EMB)[j4] = v;
}

__global__ void qb_kernel(const float* __restrict__ q, const float* __restrict__ predw1,
                          const float* __restrict__ predb1)
{
    int j = blockIdx.x * blockDim.x + threadIdx.x;
    if (j >= EMB) return;
    float acc = 0.f;
    for (int k = 0; k < EMB; k++) acc += q[k] * predw1[(size_t)k * EMB + j];
    g_qb[j] = acc + predb1[j];
}

__device__ __forceinline__ void threefry2x32(unsigned k0, unsigned k1,
                                             unsigned& x0, unsigned& x1)
{
    unsigned ks2 = k0 ^ k1 ^ 0x1BD11BDAu;
    x0 += k0; x1 += k1;
#define TFR(r) { x0 += x1; x1 = (x1 << (r)) | (x1 >> (32 - (r))); x1 ^= x0; }
    TFR(13) TFR(15) TFR(26) TFR(6)
    x0 += k1;  x1 += ks2 + 1u;
    TFR(17) TFR(29) TFR(16) TFR(24)
    x0 += ks2; x1 += k0 + 2u;
    TFR(13) TFR(15) TFR(26) TFR(6)
    x0 += k0;  x1 += k1 + 3u;
    TFR(17) TFR(29) TFR(16) TFR(24)
    x0 += k1;  x1 += ks2 + 4u;
    TFR(13) TFR(15) TFR(26) TFR(6)
    x0 += ks2; x1 += k0 + 5u;
#undef TFR
}

__device__ __forceinline__ float gumbel_noise(int e) {
    unsigned x0 = 0u;
    unsigned x1 = (unsigned)e;
    threefry2x32(0u, 42u, x0, x1);
    unsigned bits = x0 ^ x1;
    float f = __uint_as_float((bits >> 9) | 0x3f800000u) - 1.0f;
    float u = fmaxf(1e-10f, f + 1e-10f);
    return -logf(-logf(u));
}

__global__ void edge_logits_kernel(const int* __restrict__ h_id, const int* __restrict__ t_id,
                                   const int* __restrict__ r_id, int E,
                                   const float* __restrict__ w2, const float* __restrict__ b2)
{
    int e = blockIdx.x;
    int src, dst, rel;
    if (e < E) { src = h_id[e]; dst = t_id[e]; rel = r_id[e]; }
    else { int e2 = e - E; src = t_id[e2]; dst = h_id[e2]; rel = RELSLOT + r_id[e2]; }
    int tid = threadIdx.x;
    float4 a  = reinterpret_cast<const float4*>(g_AB + (size_t)src * 2 * EMB)[tid];
    float4 b  = reinterpret_cast<const float4*>(g_AB + (size_t)dst * 2 * EMB + EMB)[tid];
    float4 rr = reinterpret_cast<const float4*>(g_Q + (size_t)rel * EMB)[tid];
    float4 qv = reinterpret_cast<const float4*>(g_qb)[tid];
    float4 w  = reinterpret_cast<const float4*>(w2)[tid];
    float acc = fmaxf(qv.x + a.x + rr.x + b.x, 0.f) * w.x
              + fmaxf(qv.y + a.y + rr.y + b.y, 0.f) * w.y
              + fmaxf(qv.z + a.z + rr.z + b.z, 0.f) * w.z
              + fmaxf(qv.w + a.w + rr.w + b.w, 0.f) * w.w;
#pragma unroll
    for (int o = 16; o; o >>= 1) acc += __shfl_xor_sync(0xffffffffu, acc, o);
    __shared__ float sred[8];
    if ((tid & 31) == 0) sred[tid >> 5] = acc;
    __syncthreads();
    if (tid == 0) {
        float s = 0.f;
#pragma unroll
        for (int wdx = 0; wdx < 8; wdx++) s += sred[wdx];
        g_y[e] = s + b2[0] + gumbel_noise(e);
    }
}

__device__ __forceinline__ unsigned f2key(float v) {
    unsigned b = __float_as_uint(v);
    return (b & 0x80000000u) ? ~b : (b | 0x80000000u);
}

__global__ void topk_kernel(int n, int K) {
    __shared__ unsigned hist[256];
    __shared__ unsigned s_prefix;
    __shared__ int s_krem;
    __shared__ int s_cnt;
    int tid = threadIdx.x;
    if (tid == 0) { s_prefix = 0; s_krem = K; s_cnt = 0; }
    __syncthreads();
    for (int pass = 3; pass >= 0; pass--) {
        int shift = pass * 8;
        if (tid < 256) hist[tid] = 0;
        __syncthreads();
        unsigned prefix = s_prefix;
        for (int i = tid; i < n; i += blockDim.x) {
            unsigned key = f2key(g_y[i]);
            bool match = (pass == 3) || ((key >> (shift + 8)) == (prefix >> (shift + 8)));
            if (match) atomicAdd(&hist[(key >> shift) & 255], 1u);
        }
        __syncthreads();
        if (tid == 0) {
            int krem = s_krem;
            unsigned cum = 0;
            int b = 255;
            for (; b >= 0; b--) {
                if (cum + hist[b] >= (unsigned)krem) break;
                cum += hist[b];
            }
            if (b < 0) b = 0;
            s_prefix = prefix | ((unsigned)b << shift);
            s_krem = krem - (int)cum;
        }
        __syncthreads();
    }
    unsigned T = s_prefix;
    int rem = s_krem;
    for (int i = tid; i < n; i += blockDim.x) {
        if (f2key(g_y[i]) == T) {
            int p = atomicAdd(&s_cnt, 1);
            if (p < MAX_TIES) g_tie[p] = i;
        }
    }
    __syncthreads();
    if (tid == 0) {
        int c = s_cnt < MAX_TIES ? s_cnt : MAX_TIES;
        for (int a = 1; a < c; a++) {
            int v = g_tie[a];
            int b = a - 1;
            while (b >= 0 && g_tie[b] > v) { g_tie[b + 1] = g_tie[b]; b--; }
            g_tie[b + 1] = v;
        }
        if (rem > c) rem = c;
        if (rem < 0) rem = 0;
        g_T = T;
        g_rem = rem;
    }
}

__global__ void output_kernel(float* __restrict__ out, int n) {
    int i = blockIdx.x * blockDim.x + threadIdx.x;
    if (i >= n) return;
    unsigned key = f2key(g_y[i]);
    float o = 0.f;
    unsigned T = g_T;
    if (key > T) o = 1.f;
    else if (key == T) {
        int rem = g_rem;
        for (int t = 0; t < rem; t++)
            if (g_tie[t] == i) { o = 1.f; break; }
    }
    out[i] = o;
}

// ----------------------------------------------------------------------------
// Host-side helpers
// ----------------------------------------------------------------------------
static void split_a(const float* A, int lda, int M, int K, int K64, int KP, __nv_bfloat16* out) {
    long long total = (long long)M * K64;
    int blocks = (int)((total + 255) / 256);
    split_a_kernel<<<blocks, 256>>>(A, lda, M, K, K64, KP, out);
}
static void split_b(const float* W, int ldw, int K, int N, int K64, int KP, __nv_bfloat16* out) {
    dim3 grid((N + 31) / 32, (K64 + 31) / 32);
    split_b_kernel<<<grid, dim3(32, 8)>>>(W, ldw, K, N, K64, KP, out);
}
static void gemm(const __nv_bfloat16* A, const __nv_bfloat16* B, float* C, int ldc,
                 int M, int N, int KP, const float* bias, int relu) {
    dim3 grid(N / BN, M / BM);
    gemm_mma<<<grid, 256>>>(A, B, C, ldc, KP, bias, relu);
}

extern "C" void kernel_launch(void* const* d_in, const int* in_sizes, int n_in,
                              void* d_out, int out_size)
{
    const int* h_id = (const int*)d_in[0];
    const int* t_id = (const int*)d_in[1];
    const int* r_id = (const int*)d_in[2];
    const int s = (n_in >= 25) ? 1 : 0;
    const int b0 = 3 + s;
    const float* q_emb   = (const float*)d_in[b0 + 0];
    const float* entity  = (const float*)d_in[b0 + 1];
    const float* rel     = (const float*)d_in[b0 + 2];
    const float* topic   = (const float*)d_in[b0 + 3];
    const float* nontext = (const float*)d_in[b0 + 4];
    const float* wself1  = (const float*)d_in[b0 + 5];
    const float* bself1  = (const float*)d_in[b0 + 6];
    const float* wmsg1   = (const float*)d_in[b0 + 7];
    const float* bmsg1   = (const float*)d_in[b0 + 8];
    const float* wself2  = (const float*)d_in[b0 + 9];
    const float* bself2  = (const float*)d_in[b0 + 10];
    const float* wmsg2   = (const float*)d_in[b0 + 11];
    const float* bmsg2   = (const float*)d_in[b0 + 12];
    const float* revw1   = (const float*)d_in[b0 + 13];
    const float* revb1   = (const float*)d_in[b0 + 14];
    const float* revw2   = (const float*)d_in[b0 + 15];
    const float* revb2   = (const float*)d_in[b0 + 16];
    const float* predw1  = (const float*)d_in[b0 + 17];
    const float* predb1  = (const float*)d_in[b0 + 18];
    const float* predw2  = (const float*)d_in[b0 + 19];
    const float* predb2  = (const float*)d_in[b0 + 20];

    const int E       = in_sizes[0];
    const int n_text  = in_sizes[b0 + 1] / EMB;
    const int n_rel   = in_sizes[b0 + 2] / EMB;
    const int n_nodes = in_sizes[b0 + 3] / 2;
    const int d0      = in_sizes[b0 + 5] / EMB;   // 1026
    const int E2      = 2 * E;
    if (n_nodes > MAXN || E2 > MAXE2 || n_rel > RELSLOT) return;

    float *p_h0, *p_relcat, *p_revh, *p_Q, *p_Pself, *p_Pmsg, *p_agg, *p_hnode, *p_AB, *p_deg;
    __nv_bfloat16 *p_sa, *p_sarel, *p_sb;
    cudaGetSymbolAddress((void**)&p_h0,     g_h0);
    cudaGetSymbolAddress((void**)&p_relcat, g_relcat);
    cudaGetSymbolAddress((void**)&p_revh,   g_revh);
    cudaGetSymbolAddress((void**)&p_Q,      g_Q);
    cudaGetSymbolAddress((void**)&p_Pself,  g_Pself);
    cudaGetSymbolAddress((void**)&p_Pmsg,   g_Pmsg);
    cudaGetSymbolAddress((void**)&p_agg,    g_agg);
    cudaGetSymbolAddress((void**)&p_hnode,  g_hnode);
    cudaGetSymbolAddress((void**)&p_AB,     g_AB);
    cudaGetSymbolAddress((void**)&p_deg,    g_deg);
    cudaGetSymbolAddress((void**)&p_sa,     g_sa);
    cudaGetSymbolAddress((void**)&p_sarel,  g_sarel);
    cudaGetSymbolAddress((void**)&p_sb,     g_sb);

    // ---- prep ----
    zero_kernel<<<1024, 256>>>((float4*)p_agg, MAXN * EMB / 4);
    zero_kernel<<<32, 256>>>((float4*)p_deg, MAXN / 4);
    build_h0_kernel<<<n_nodes, 256>>>(entity, nontext, topic, n_text, n_nodes);
    relcat_kernel<<<(RELSLOT * EMB + 255) / 256, 256>>>(rel, n_rel);
    deg_kernel<<<(E2 + 255) / 256, 256>>>(h_id, t_id, E);

    // ---- reverse-relation MLP ----
    split_a(p_relcat, EMB, RELSLOT, EMB, 1024, 3072, p_sa);
    split_b(revw1, EMB, EMB, EMB, 1024, 3072, p_sb);
    gemm(p_sa, p_sb, p_revh, EMB, RELSLOT, EMB, 3072, revb1, 1);
    split_a(p_revh, EMB, RELSLOT, EMB, 1024, 3072, p_sa);
    split_b(revw2, EMB, EMB, EMB, 1024, 3072, p_sb);
    gemm(p_sa, p_sb, p_relcat + (size_t)RELSLOT * EMB, EMB, RELSLOT, EMB, 3072, revb2, 0);

    // relation A' table (fwd+rev), reused for all 3 Q projections
    split_a(p_relcat, EMB, 2 * RELSLOT, EMB, 1024, 3072, p_sarel);

    // ---- SAGE layer 1 ----
    split_b(wmsg1 + (size_t)d0 * EMB, EMB, EMB, EMB, 1024, 3072, p_sb);
    gemm(p_sarel, p_sb, p_Q, EMB, 2 * RELSLOT, EMB, 3072, nullptr, 0);
    split_a(p_h0, D0PAD, MAXN, D0PAD, 1088, 3264, p_sa);
    split_b(wmsg1, EMB, d0, EMB, 1088, 3264, p_sb);
    gemm(p_sa, p_sb, p_Pmsg, EMB, MAXN, EMB, 3264, bmsg1, 0);
    split_b(wself1, EMB, d0, EMB, 1088, 3264, p_sb);
    gemm(p_sa, p_sb, p_Pself, EMB, MAXN, EMB, 3264, bself1, 0);
    edge_msg_kernel<<<E2, 256>>>(h_id, t_id, r_id, E);
    node_update_kernel<<<(n_nodes * (EMB / 4) + 255) / 256, 256>>>(n_nodes, 0);

    // ---- SAGE layer 2 ----
    zero_kernel<<<1024, 256>>>((float4*)p_agg, MAXN * EMB / 4);
    split_b(wmsg2 + (size_t)EMB * EMB, EMB, EMB, EMB, 1024, 3072, p_sb);
    gemm(p_sarel, p_sb, p_Q, EMB, 2 * RELSLOT, EMB, 3072, nullptr, 0);
    split_a(p_hnode, 2 * EMB, MAXN, EMB, 1024, 3072, p_sa);   // h1
    split_b(wmsg2, EMB, EMB, EMB, 1024, 3072, p_sb);
    gemm(p_sa, p_sb, p_Pmsg, EMB, MAXN, EMB, 3072, bmsg2, 0);
    split_b(wself2, EMB, EMB, EMB, 1024, 3072, p_sb);
    gemm(p_sa, p_sb, p_Pself, EMB, MAXN, EMB, 3072, bself2, 0);
    edge_msg_kernel<<<E2, 256>>>(h_id, t_id, r_id, E);
    node_update_kernel<<<(n_nodes * (EMB / 4) + 255) / 256, 256>>>(n_nodes, 1);

    // ---- predictor projections ----
    split_b(predw1 + (size_t)3 * EMB * EMB, EMB, EMB, EMB, 1024, 3072, p_sb);
    gemm(p_sarel, p_sb, p_Q, EMB, 2 * RELSLOT, EMB, 3072, nullptr, 0);
    split_a(p_hnode, 2 * EMB, MAXN, 2 * EMB, 2048, 6144, p_sa);
    split_b(predw1 + (size_t)EMB * EMB, EMB, 2 * EMB, EMB, 2048, 6144, p_sb);
    gemm(p_sa, p_sb, p_AB, 2 * EMB, MAXN, EMB, 6144, nullptr, 0);
    split_b(predw1 + (size_t)4 * EMB * EMB, EMB, 2 * EMB, EMB, 2048, 6144, p_sb);
    gemm(p_sa, p_sb, p_AB + EMB, 2 * EMB, MAXN, EMB, 6144, nullptr, 0);
    qb_kernel<<<4, 256>>>(q_emb, predw1, predb1);

    // ---- edge logits + gumbel + exact top-K ----
    edge_logits_kernel<<<E2, 256>>>(h_id, t_id, r_id, E, predw2, predb2);
    topk_kernel<<<1, 1024>>>(E2, 512);
    output_kernel<<<(E2 + 255) / 256, 256>>>((float*)d_out, E2);
}

// round 13
// speedup vs baseline: 2.4662x; 1.4175x over previous
#include <cuda_runtime.h>
#include <cuda_bf16.h>
#include <math.h>
#include <stdint.h>

#define EMB 1024
#define D0PAD 1032
#define MAXN 22016
#define RELSLOT 2048
#define MAXE2 40960
#define MAX_TIES 1024
#define KPMAX 6144

// ---------------- mma.sync GEMM tile config ----------------
#define BM 128
#define BN 128
#define BK 32                 // bf16 per K-chunk
#define STAGE_BYTES 16384     // A 8KB + B 8KB
#define GSMEM (4 * STAGE_BYTES)

// ----------------------------------------------------------------------------
// Static scratch
// ----------------------------------------------------------------------------
__device__ float g_h0[(size_t)MAXN * D0PAD];
__device__ float g_relcat[(size_t)2 * RELSLOT * EMB];
__device__ float g_revh[(size_t)RELSLOT * EMB];
__device__ float g_Q[(size_t)2 * RELSLOT * EMB];
__device__ float g_Pself[(size_t)MAXN * EMB];
__device__ float g_Pmsg[(size_t)MAXN * EMB];
__device__ float g_agg[(size_t)MAXN * EMB];
__device__ float g_hnode[(size_t)MAXN * 2 * EMB];   // [h1 | h2]
__device__ float g_AB[(size_t)MAXN * 2 * EMB];      // [Asrc | Bdst]
__device__ float g_deg[MAXN];
__device__ float g_qb[EMB];
__device__ float g_y[MAXE2];
__device__ unsigned g_T;
__device__ int g_rem;
__device__ int g_tie[MAX_TIES];
// bf16 split operand buffers
__device__ __nv_bfloat16 g_sa[(size_t)MAXN * KPMAX];           // A' big
__device__ __nv_bfloat16 g_sarel[(size_t)2 * RELSLOT * 3072];  // relcat A' (reused 3x)
__device__ __nv_bfloat16 g_sb[(size_t)EMB * KPMAX];            // B'

// ----------------------------------------------------------------------------
// helpers
// ----------------------------------------------------------------------------
__device__ __forceinline__ uint32_t smem_u32(const void* p) {
    uint32_t a;
    asm("{ .reg .u64 t; cvta.to.shared.u64 t, %1; cvt.u32.u64 %0, t; }" : "=r"(a) : "l"(p));
    return a;
}
// 64B rows, 4x16B chunks, XOR swizzle: conflict-free for cp.async stores + ldmatrix
__device__ __forceinline__ int sw64(int row, int chk) {
    return row * 64 + (((chk) ^ ((row >> 1) & 3)) << 4);
}
__device__ __forceinline__ void cp16(uint32_t sa, const void* gp) {
    uint64_t ga;
    asm("cvta.to.global.u64 %0, %1;" : "=l"(ga) : "l"(gp));
    asm volatile("cp.async.cg.shared.global [%0], [%1], 16;" :: "r"(sa), "l"(ga) : "memory");
}

// ----------------------------------------------------------------------------
// bf16 split GEMM via mma.sync.m16n8k16 + ldmatrix + cp.async 4-stage pipeline
// C[M,N] = A'[M,KP] · B'[N,KP]^T (+bias)(+relu). M%128==0, N%128==0, KP%32==0.
// grid = (N/128, M/128), 256 threads = 8 warps (2 m x 4 n), warp tile 64x32.
// ----------------------------------------------------------------------------
__global__ __launch_bounds__(256, 2)
void gemm_mma(const __nv_bfloat16* __restrict__ A, const __nv_bfloat16* __restrict__ B,
              float* __restrict__ C, int ldc, int KP,
              const float* __restrict__ bias, int dorelu)
{
    extern __shared__ __align__(1024) char smem[];
    const int tid  = threadIdx.x;
    const int wid  = tid >> 5;
    const int lane = tid & 31;
    const int bm0 = blockIdx.y * BM;
    const int bn0 = blockIdx.x * BN;
    const int wm0 = (wid & 1) * 64;
    const int wn0 = (wid >> 1) * 32;
    const uint32_t sbase = smem_u32(smem);

    // cp.async source/dest indices: each thread handles chunks {tid, tid+256} per operand
    const int arow0 = tid >> 2, achk = tid & 3;   // rows arow0 and arow0+64

    // ldmatrix per-lane address components
    const int midx = lane >> 3, mr = lane & 7;
    int aRowB[4], aRx[4];
#pragma unroll
    for (int ma = 0; ma < 4; ma++) {
        int r = wm0 + ma * 16 + (midx & 1) * 8 + mr;
        aRowB[ma] = r * 64; aRx[ma] = (r >> 1) & 3;
    }
    const int aCs = midx >> 1;
    int bRowB[2], bRx[2];
#pragma unroll
    for (int p = 0; p < 2; p++) {
        int r = wn0 + p * 16 + (midx >> 1) * 8 + mr;
        bRowB[p] = r * 64; bRx[p] = (r >> 1) & 3;
    }
    const int bCs = midx & 1;

    float c[4][4][4];
#pragma unroll
    for (int ma = 0; ma < 4; ma++)
#pragma unroll
        for (int na = 0; na < 4; na++)
#pragma unroll
            for (int i = 0; i < 4; i++) c[ma][na][i] = 0.f;

    const int nchunk = KP >> 5;

    auto issue_stage = [&](int ck) {
        if (ck < nchunk) {
            const int kc = ck * BK;
            const uint32_t st = sbase + (ck & 3) * STAGE_BYTES;
            cp16(st + sw64(arow0, achk),      A + (size_t)(bm0 + arow0) * KP + kc + achk * 8);
            cp16(st + sw64(arow0 + 64, achk), A + (size_t)(bm0 + arow0 + 64) * KP + kc + achk * 8);
            cp16(st + 8192 + sw64(arow0, achk),      B + (size_t)(bn0 + arow0) * KP + kc + achk * 8);
            cp16(st + 8192 + sw64(arow0 + 64, achk), B + (size_t)(bn0 + arow0 + 64) * KP + kc + achk * 8);
        }
        asm volatile("cp.async.commit_group;" ::: "memory");
    };

    issue_stage(0);
    issue_stage(1);
    issue_stage(2);

    for (int ck = 0; ck < nchunk; ck++) {
        asm volatile("cp.async.wait_group 2;" ::: "memory");
        __syncthreads();
        issue_stage(ck + 3);

        const uint32_t stA = sbase + (ck & 3) * STAGE_BYTES;
        const uint32_t stB = stA + 8192;
#pragma unroll
        for (int s = 0; s < 2; s++) {
            uint32_t af[4][4], bf[4][2];
#pragma unroll
            for (int ma = 0; ma < 4; ma++) {
                uint32_t ad = stA + aRowB[ma] + ((((s << 1) + aCs) ^ aRx[ma]) << 4);
                asm volatile("ldmatrix.sync.aligned.m8n8.x4.shared.b16 {%0,%1,%2,%3}, [%4];"
                             : "=r"(af[ma][0]), "=r"(af[ma][1]), "=r"(af[ma][2]), "=r"(af[ma][3])
                             : "r"(ad));
            }
#pragma unroll
            for (int p = 0; p < 2; p++) {
                uint32_t bd = stB + bRowB[p] + ((((s << 1) + bCs) ^ bRx[p]) << 4);
                asm volatile("ldmatrix.sync.aligned.m8n8.x4.shared.b16 {%0,%1,%2,%3}, [%4];"
                             : "=r"(bf[2 * p][0]), "=r"(bf[2 * p][1]),
                               "=r"(bf[2 * p + 1][0]), "=r"(bf[2 * p + 1][1])
                             : "r"(bd));
            }
#pragma unroll
            for (int ma = 0; ma < 4; ma++)
#pragma unroll
                for (int na = 0; na < 4; na++)
                    asm volatile(
                        "mma.sync.aligned.m16n8k16.row.col.f32.bf16.bf16.f32 "
                        "{%0,%1,%2,%3}, {%4,%5,%6,%7}, {%8,%9}, {%0,%1,%2,%3};"
                        : "+f"(c[ma][na][0]), "+f"(c[ma][na][1]),
                          "+f"(c[ma][na][2]), "+f"(c[ma][na][3])
                        : "r"(af[ma][0]), "r"(af[ma][1]), "r"(af[ma][2]), "r"(af[ma][3]),
                          "r"(bf[na][0]), "r"(bf[na][1]));
        }
    }

    // epilogue
    const int g = lane >> 2;
    const int q = lane & 3;
#pragma unroll
    for (int ma = 0; ma < 4; ma++) {
        const int row = bm0 + wm0 + ma * 16 + g;
#pragma unroll
        for (int na = 0; na < 4; na++) {
            const int col = bn0 + wn0 + na * 8 + q * 2;
            float v0 = c[ma][na][0], v1 = c[ma][na][1];
            float v2 = c[ma][na][2], v3 = c[ma][na][3];
            if (bias) {
                float bx = bias[col], by = bias[col + 1];
                v0 += bx; v1 += by; v2 += bx; v3 += by;
            }
            if (dorelu) {
                v0 = fmaxf(v0, 0.f); v1 = fmaxf(v1, 0.f);
                v2 = fmaxf(v2, 0.f); v3 = fmaxf(v3, 0.f);
            }
            *reinterpret_cast<float2*>(C + (size_t)row * ldc + col) = make_float2(v0, v1);
            *reinterpret_cast<float2*>(C + (size_t)(row + 8) * ldc + col) = make_float2(v2, v3);
        }
    }
}

// ----------------------------------------------------------------------------
// Split kernels: fp32 -> bf16 triple layout
// A' = [hi | lo | hi] along K ; B' = [hi | hi | lo] (with transpose)
// ----------------------------------------------------------------------------
__global__ void split_a_kernel(const float* __restrict__ A, int lda, int M, int K,
                               int K64, int KP, __nv_bfloat16* __restrict__ out)
{
    long long idx = (long long)blockIdx.x * blockDim.x + threadIdx.x;
    long long total = (long long)M * K64;
    if (idx >= total) return;
    int row = (int)(idx / K64);
    int kk = (int)(idx % K64);
    float v = (kk < K) ? A[(size_t)row * lda + kk] : 0.f;
    __nv_bfloat16 hi = __float2bfloat16(v);
    __nv_bfloat16 lo = __float2bfloat16(v - __bfloat162float(hi));
    __nv_bfloat16* o = out + (size_t)row * KP;
    o[kk] = hi;
    o[K64 + kk] = lo;
    o[2 * K64 + kk] = hi;
}

__global__ void split_b_kernel(const float* __restrict__ W, int ldw, int K, int N,
                               int K64, int KP, __nv_bfloat16* __restrict__ out)
{
    __shared__ float t[32][33];
    int kk0 = blockIdx.y * 32, n0 = blockIdx.x * 32;
    int tx = threadIdx.x, ty = threadIdx.y;   // 32x8
#pragma unroll
    for (int j = 0; j < 32; j += 8) {
        int kk = kk0 + ty + j, n = n0 + tx;
        t[ty + j][tx] = (kk < K && n < N) ? W[(size_t)kk * ldw + n] : 0.f;
    }
    __syncthreads();
#pragma unroll
    for (int j = 0; j < 32; j += 8) {
        int n = n0 + ty + j, kk = kk0 + tx;
        if (n < N && kk < K64) {
            float v = t[tx][ty + j];
            __nv_bfloat16 hi = __float2bfloat16(v);
            __nv_bfloat16 lo = __float2bfloat16(v - __bfloat162float(hi));
            __nv_bfloat16* o = out + (size_t)n * KP;
            o[kk] = hi;
            o[K64 + kk] = hi;
            o[2 * K64 + kk] = lo;
        }
    }
}

// ----------------------------------------------------------------------------
// Non-GEMM kernels (unchanged)
// ----------------------------------------------------------------------------
__global__ void zero_kernel(float4* p, int n4) {
    int i = blockIdx.x * blockDim.x + threadIdx.x;
    int stride = gridDim.x * blockDim.x;
    float4 z = make_float4(0.f, 0.f, 0.f, 0.f);
    for (; i < n4; i += stride) p[i] = z;
}

__global__ void build_h0_kernel(const float* __restrict__ entity,
                                const float* __restrict__ nontext,
                                const float* __restrict__ topic,
                                int n_text, int n_nodes)
{
    int n = blockIdx.x;
    if (n >= n_nodes) return;
    float* dst = g_h0 + (size_t)n * D0PAD;
    const float* src = (n < n_text) ? (entity + (size_t)n * EMB) : nontext;
    for (int j = threadIdx.x; j < D0PAD; j += blockDim.x) {
        float v;
        if (j < EMB)          v = src[j];
        else if (j < EMB + 2) v = topic[(size_t)n * 2 + (j - EMB)];
        else                  v = 0.f;
        dst[j] = v;
    }
}

__global__ void relcat_kernel(const float* __restrict__ rel, int n_rel) {
    int i = blockIdx.x * blockDim.x + threadIdx.x;
    if (i >= RELSLOT * EMB) return;
    int row = i / EMB;
    g_relcat[i] = (row < n_rel) ? rel[i] : 0.f;
}

__global__ void deg_kernel(const int* __restrict__ h_id, const int* __restrict__ t_id, int E) {
    int i = blockIdx.x * blockDim.x + threadIdx.x;
    if (i >= 2 * E) return;
    int dst = (i < E) ? t_id[i] : h_id[i - E];
    atomicAdd(&g_deg[dst], 1.0f);
}

__global__ void edge_msg_kernel(const int* __restrict__ h_id, const int* __restrict__ t_id,
                                const int* __restrict__ r_id, int E)
{
    int e = blockIdx.x;
    int src, dst, rel;
    if (e < E) { src = h_id[e]; dst = t_id[e]; rel = r_id[e]; }
    else { int e2 = e - E; src = t_id[e2]; dst = h_id[e2]; rel = RELSLOT + r_id[e2]; }
    int j = threadIdx.x;
    const float4 pv = reinterpret_cast<const float4*>(g_Pmsg + (size_t)src * EMB)[j];
    const float4 qv = reinterpret_cast<const float4*>(g_Q + (size_t)rel * EMB)[j];
    float4 m;
    m.x = fmaxf(pv.x + qv.x, 0.f);
    m.y = fmaxf(pv.y + qv.y, 0.f);
    m.z = fmaxf(pv.z + qv.z, 0.f);
    m.w = fmaxf(pv.w + qv.w, 0.f);
    atomicAdd(reinterpret_cast<float4*>(g_agg + (size_t)dst * EMB) + j, m);
}

__global__ void node_update_kernel(int n_nodes, int layer) {
    int i = blockIdx.x * blockDim.x + threadIdx.x;
    int total = n_nodes * (EMB / 4);
    if (i >= total) return;
    int n = i >> 8;
    int j4 = i & 255;
    float inv = 1.0f / fmaxf(g_deg[n], 1.0f);
    float4 ps = reinterpret_cast<const float4*>(g_Pself + (size_t)n * EMB)[j4];
    float4 ag = reinterpret_cast<const float4*>(g_agg + (size_t)n * EMB)[j4];
    float4 v;
    v.x = fmaxf(ps.x + ag.x * inv, 0.f);
    v.y = fmaxf(ps.y + ag.y * inv, 0.f);
    v.z = fmaxf(ps.z + ag.z * inv, 0.f);
    v.w = fmaxf(ps.w + ag.w * inv, 0.f);
    reinterpret_cast<float4*>(g_hnode + (size_t)n * 2 * EMB + (size_t)layer * EMB)[j4] = v;
}

__global__ void qb_kernel(const float* __restrict__ q, const float* __restrict__ predw1,
                          const float* __restrict__ predb1)
{
    int j = blockIdx.x * blockDim.x + threadIdx.x;
    if (j >= EMB) return;
    float acc = 0.f;
    for (int k = 0; k < EMB; k++) acc += q[k] * predw1[(size_t)k * EMB + j];
    g_qb[j] = acc + predb1[j];
}

__device__ __forceinline__ void threefry2x32(unsigned k0, unsigned k1,
                                             unsigned& x0, unsigned& x1)
{
    unsigned ks2 = k0 ^ k1 ^ 0x1BD11BDAu;
    x0 += k0; x1 += k1;
#define TFR(r) { x0 += x1; x1 = (x1 << (r)) | (x1 >> (32 - (r))); x1 ^= x0; }
    TFR(13) TFR(15) TFR(26) TFR(6)
    x0 += k1;  x1 += ks2 + 1u;
    TFR(17) TFR(29) TFR(16) TFR(24)
    x0 += ks2; x1 += k0 + 2u;
    TFR(13) TFR(15) TFR(26) TFR(6)
    x0 += k0;  x1 += k1 + 3u;
    TFR(17) TFR(29) TFR(16) TFR(24)
    x0 += k1;  x1 += ks2 + 4u;
    TFR(13) TFR(15) TFR(26) TFR(6)
    x0 += ks2; x1 += k0 + 5u;
#undef TFR
}

__device__ __forceinline__ float gumbel_noise(int e) {
    unsigned x0 = 0u;
    unsigned x1 = (unsigned)e;
    threefry2x32(0u, 42u, x0, x1);
    unsigned bits = x0 ^ x1;
    float f = __uint_as_float((bits >> 9) | 0x3f800000u) - 1.0f;
    float u = fmaxf(1e-10f, f + 1e-10f);
    return -logf(-logf(u));
}

__global__ void edge_logits_kernel(const int* __restrict__ h_id, const int* __restrict__ t_id,
                                   const int* __restrict__ r_id, int E,
                                   const float* __restrict__ w2, const float* __restrict__ b2)
{
    int e = blockIdx.x;
    int src, dst, rel;
    if (e < E) { src = h_id[e]; dst = t_id[e]; rel = r_id[e]; }
    else { int e2 = e - E; src = t_id[e2]; dst = h_id[e2]; rel = RELSLOT + r_id[e2]; }
    int tid = threadIdx.x;
    float4 a  = reinterpret_cast<const float4*>(g_AB + (size_t)src * 2 * EMB)[tid];
    float4 b  = reinterpret_cast<const float4*>(g_AB + (size_t)dst * 2 * EMB + EMB)[tid];
    float4 rr = reinterpret_cast<const float4*>(g_Q + (size_t)rel * EMB)[tid];
    float4 qv = reinterpret_cast<const float4*>(g_qb)[tid];
    float4 w  = reinterpret_cast<const float4*>(w2)[tid];
    float acc = fmaxf(qv.x + a.x + rr.x + b.x, 0.f) * w.x
              + fmaxf(qv.y + a.y + rr.y + b.y, 0.f) * w.y
              + fmaxf(qv.z + a.z + rr.z + b.z, 0.f) * w.z
              + fmaxf(qv.w + a.w + rr.w + b.w, 0.f) * w.w;
#pragma unroll
    for (int o = 16; o; o >>= 1) acc += __shfl_xor_sync(0xffffffffu, acc, o);
    __shared__ float sred[8];
    if ((tid & 31) == 0) sred[tid >> 5] = acc;
    __syncthreads();
    if (tid == 0) {
        float s = 0.f;
#pragma unroll
        for (int wdx = 0; wdx < 8; wdx++) s += sred[wdx];
        g_y[e] = s + b2[0] + gumbel_noise(e);
    }
}

__device__ __forceinline__ unsigned f2key(float v) {
    unsigned b = __float_as_uint(v);
    return (b & 0x80000000u) ? ~b : (b | 0x80000000u);
}

__global__ void topk_kernel(int n, int K) {
    __shared__ unsigned hist[256];
    __shared__ unsigned s_prefix;
    __shared__ int s_krem;
    __shared__ int s_cnt;
    int tid = threadIdx.x;
    if (tid == 0) { s_prefix = 0; s_krem = K; s_cnt = 0; }
    __syncthreads();
    for (int pass = 3; pass >= 0; pass--) {
        int shift = pass * 8;
        if (tid < 256) hist[tid] = 0;
        __syncthreads();
        unsigned prefix = s_prefix;
        for (int i = tid; i < n; i += blockDim.x) {
            unsigned key = f2key(g_y[i]);
            bool match = (pass == 3) || ((key >> (shift + 8)) == (prefix >> (shift + 8)));
            if (match) atomicAdd(&hist[(key >> shift) & 255], 1u);
        }
        __syncthreads();
        if (tid == 0) {
            int krem = s_krem;
            unsigned cum = 0;
            int b = 255;
            for (; b >= 0; b--) {
                if (cum + hist[b] >= (unsigned)krem) break;
                cum += hist[b];
            }
            if (b < 0) b = 0;
            s_prefix = prefix | ((unsigned)b << shift);
            s_krem = krem - (int)cum;
        }
        __syncthreads();
    }
    unsigned T = s_prefix;
    int rem = s_krem;
    for (int i = tid; i < n; i += blockDim.x) {
        if (f2key(g_y[i]) == T) {
            int p = atomicAdd(&s_cnt, 1);
            if (p < MAX_TIES) g_tie[p] = i;
        }
    }
    __syncthreads();
    if (tid == 0) {
        int c = s_cnt < MAX_TIES ? s_cnt : MAX_TIES;
        for (int a = 1; a < c; a++) {
            int v = g_tie[a];
            int b = a - 1;
            while (b >= 0 && g_tie[b] > v) { g_tie[b + 1] = g_tie[b]; b--; }
            g_tie[b + 1] = v;
        }
        if (rem > c) rem = c;
        if (rem < 0) rem = 0;
        g_T = T;
        g_rem = rem;
    }
}

__global__ void output_kernel(float* __restrict__ out, int n) {
    int i = blockIdx.x * blockDim.x + threadIdx.x;
    if (i >= n) return;
    unsigned key = f2key(g_y[i]);
    float o = 0.f;
    unsigned T = g_T;
    if (key > T) o = 1.f;
    else if (key == T) {
        int rem = g_rem;
        for (int t = 0; t < rem; t++)
            if (g_tie[t] == i) { o = 1.f; break; }
    }
    out[i] = o;
}

// ----------------------------------------------------------------------------
// Host-side helpers
// ----------------------------------------------------------------------------
static void split_a(const float* A, int lda, int M, int K, int K64, int KP, __nv_bfloat16* out) {
    long long total = (long long)M * K64;
    int blocks = (int)((total + 255) / 256);
    split_a_kernel<<<blocks, 256>>>(A, lda, M, K, K64, KP, out);
}
static void split_b(const float* W, int ldw, int K, int N, int K64, int KP, __nv_bfloat16* out) {
    dim3 grid((N + 31) / 32, (K64 + 31) / 32);
    split_b_kernel<<<grid, dim3(32, 8)>>>(W, ldw, K, N, K64, KP, out);
}
static void gemm(const __nv_bfloat16* A, const __nv_bfloat16* B, float* C, int ldc,
                 int M, int N, int KP, const float* bias, int relu) {
    dim3 grid(N / BN, M / BM);
    gemm_mma<<<grid, 256, GSMEM>>>(A, B, C, ldc, KP, bias, relu);
}

extern "C" void kernel_launch(void* const* d_in, const int* in_sizes, int n_in,
                              void* d_out, int out_size)
{
    cudaFuncSetAttribute(gemm_mma, cudaFuncAttributeMaxDynamicSharedMemorySize, GSMEM);

    const int* h_id = (const int*)d_in[0];
    const int* t_id = (const int*)d_in[1];
    const int* r_id = (const int*)d_in[2];
    const int s = (n_in >= 25) ? 1 : 0;
    const int b0 = 3 + s;
    const float* q_emb   = (const float*)d_in[b0 + 0];
    const float* entity  = (const float*)d_in[b0 + 1];
    const float* rel     = (const float*)d_in[b0 + 2];
    const float* topic   = (const float*)d_in[b0 + 3];
    const float* nontext = (const float*)d_in[b0 + 4];
    const float* wself1  = (const float*)d_in[b0 + 5];
    const float* bself1  = (const float*)d_in[b0 + 6];
    const float* wmsg1   = (const float*)d_in[b0 + 7];
    const float* bmsg1   = (const float*)d_in[b0 + 8];
    const float* wself2  = (const float*)d_in[b0 + 9];
    const float* bself2  = (const float*)d_in[b0 + 10];
    const float* wmsg2   = (const float*)d_in[b0 + 11];
    const float* bmsg2   = (const float*)d_in[b0 + 12];
    const float* revw1   = (const float*)d_in[b0 + 13];
    const float* revb1   = (const float*)d_in[b0 + 14];
    const float* revw2   = (const float*)d_in[b0 + 15];
    const float* revb2   = (const float*)d_in[b0 + 16];
    const float* predw1  = (const float*)d_in[b0 + 17];
    const float* predb1  = (const float*)d_in[b0 + 18];
    const float* predw2  = (const float*)d_in[b0 + 19];
    const float* predb2  = (const float*)d_in[b0 + 20];

    const int E       = in_sizes[0];
    const int n_text  = in_sizes[b0 + 1] / EMB;
    const int n_rel   = in_sizes[b0 + 2] / EMB;
    const int n_nodes = in_sizes[b0 + 3] / 2;
    const int d0      = in_sizes[b0 + 5] / EMB;   // 1026
    const int E2      = 2 * E;
    if (n_nodes > MAXN || E2 > MAXE2 || n_rel > RELSLOT) return;

    float *p_h0, *p_relcat, *p_revh, *p_Q, *p_Pself, *p_Pmsg, *p_agg, *p_hnode, *p_AB, *p_deg;
    __nv_bfloat16 *p_sa, *p_sarel, *p_sb;
    cudaGetSymbolAddress((void**)&p_h0,     g_h0);
    cudaGetSymbolAddress((void**)&p_relcat, g_relcat);
    cudaGetSymbolAddress((void**)&p_revh,   g_revh);
    cudaGetSymbolAddress((void**)&p_Q,      g_Q);
    cudaGetSymbolAddress((void**)&p_Pself,  g_Pself);
    cudaGetSymbolAddress((void**)&p_Pmsg,   g_Pmsg);
    cudaGetSymbolAddress((void**)&p_agg,    g_agg);
    cudaGetSymbolAddress((void**)&p_hnode,  g_hnode);
    cudaGetSymbolAddress((void**)&p_AB,     g_AB);
    cudaGetSymbolAddress((void**)&p_deg,    g_deg);
    cudaGetSymbolAddress((void**)&p_sa,     g_sa);
    cudaGetSymbolAddress((void**)&p_sarel,  g_sarel);
    cudaGetSymbolAddress((void**)&p_sb,     g_sb);

    // ---- prep ----
    zero_kernel<<<1024, 256>>>((float4*)p_agg, MAXN * EMB / 4);
    zero_kernel<<<32, 256>>>((float4*)p_deg, MAXN / 4);
    build_h0_kernel<<<n_nodes, 256>>>(entity, nontext, topic, n_text, n_nodes);
    relcat_kernel<<<(RELSLOT * EMB + 255) / 256, 256>>>(rel, n_rel);
    deg_kernel<<<(E2 + 255) / 256, 256>>>(h_id, t_id, E);

    // ---- reverse-relation MLP ----
    split_a(p_relcat, EMB, RELSLOT, EMB, 1024, 3072, p_sa);
    split_b(revw1, EMB, EMB, EMB, 1024, 3072, p_sb);
    gemm(p_sa, p_sb, p_revh, EMB, RELSLOT, EMB, 3072, revb1, 1);
    split_a(p_revh, EMB, RELSLOT, EMB, 1024, 3072, p_sa);
    split_b(revw2, EMB, EMB, EMB, 1024, 3072, p_sb);
    gemm(p_sa, p_sb, p_relcat + (size_t)RELSLOT * EMB, EMB, RELSLOT, EMB, 3072, revb2, 0);

    // relation A' table (fwd+rev), reused for all 3 Q projections
    split_a(p_relcat, EMB, 2 * RELSLOT, EMB, 1024, 3072, p_sarel);

    // ---- SAGE layer 1 ----
    split_b(wmsg1 + (size_t)d0 * EMB, EMB, EMB, EMB, 1024, 3072, p_sb);
    gemm(p_sarel, p_sb, p_Q, EMB, 2 * RELSLOT, EMB, 3072, nullptr, 0);
    split_a(p_h0, D0PAD, MAXN, D0PAD, 1088, 3264, p_sa);
    split_b(wmsg1, EMB, d0, EMB, 1088, 3264, p_sb);
    gemm(p_sa, p_sb, p_Pmsg, EMB, MAXN, EMB, 3264, bmsg1, 0);
    split_b(wself1, EMB, d0, EMB, 1088, 3264, p_sb);
    gemm(p_sa, p_sb, p_Pself, EMB, MAXN, EMB, 3264, bself1, 0);
    edge_msg_kernel<<<E2, 256>>>(h_id, t_id, r_id, E);
    node_update_kernel<<<(n_nodes * (EMB / 4) + 255) / 256, 256>>>(n_nodes, 0);

    // ---- SAGE layer 2 ----
    zero_kernel<<<1024, 256>>>((float4*)p_agg, MAXN * EMB / 4);
    split_b(wmsg2 + (size_t)EMB * EMB, EMB, EMB, EMB, 1024, 3072, p_sb);
    gemm(p_sarel, p_sb, p_Q, EMB, 2 * RELSLOT, EMB, 3072, nullptr, 0);
    split_a(p_hnode, 2 * EMB, MAXN, EMB, 1024, 3072, p_sa);   // h1
    split_b(wmsg2, EMB, EMB, EMB, 1024, 3072, p_sb);
    gemm(p_sa, p_sb, p_Pmsg, EMB, MAXN, EMB, 3072, bmsg2, 0);
    split_b(wself2, EMB, EMB, EMB, 1024, 3072, p_sb);
    gemm(p_sa, p_sb, p_Pself, EMB, MAXN, EMB, 3072, bself2, 0);
    edge_msg_kernel<<<E2, 256>>>(h_id, t_id, r_id, E);
    node_update_kernel<<<(n_nodes * (EMB / 4) + 255) / 256, 256>>>(n_nodes, 1);

    // ---- predictor projections ----
    split_b(predw1 + (size_t)3 * EMB * EMB, EMB, EMB, EMB, 1024, 3072, p_sb);
    gemm(p_sarel, p_sb, p_Q, EMB, 2 * RELSLOT, EMB, 3072, nullptr, 0);
    split_a(p_hnode, 2 * EMB, MAXN, 2 * EMB, 2048, 6144, p_sa);
    split_b(predw1 + (size_t)EMB * EMB, EMB, 2 * EMB, EMB, 2048, 6144, p_sb);
    gemm(p_sa, p_sb, p_AB, 2 * EMB, MAXN, EMB, 6144, nullptr, 0);
    split_b(predw1 + (size_t)4 * EMB * EMB, EMB, 2 * EMB, EMB, 2048, 6144, p_sb);
    gemm(p_sa, p_sb, p_AB + EMB, 2 * EMB, MAXN, EMB, 6144, nullptr, 0);
    qb_kernel<<<4, 256>>>(q_emb, predw1, predb1);

    // ---- edge logits + gumbel + exact top-K ----
    edge_logits_kernel<<<E2, 256>>>(h_id, t_id, r_id, E, predw2, predb2);
    topk_kernel<<<1, 1024>>>(E2, 512);
    output_kernel<<<(E2 + 255) / 256, 256>>>((float*)d_out, E2);
}

// round 14
// speedup vs baseline: 2.8134x; 1.1408x over previous
#include <cuda_runtime.h>
#include <cuda_bf16.h>
#include <math.h>
#include <stdint.h>

#define EMB 1024
#define D0PAD 1032
#define MAXN 22016
#define RELSLOT 2048
#define MAXE2 40960
#define MAX_TIES 1024
#define KPMAX 6144

// ---------------- mma.sync GEMM tile config ----------------
#define BM 128
#define BN 128
#define BK 32                 // bf16 per K-chunk
#define STAGE_BYTES 16384     // A 8KB + B 8KB
#define GSMEM (4 * STAGE_BYTES)

// ----------------------------------------------------------------------------
// Static scratch
// ----------------------------------------------------------------------------
__device__ float g_h0[(size_t)MAXN * D0PAD];
__device__ float g_relcat[(size_t)2 * RELSLOT * EMB];
__device__ float g_revh[(size_t)RELSLOT * EMB];
__device__ float g_Q[(size_t)2 * RELSLOT * EMB];
__device__ float g_Pself[(size_t)MAXN * EMB];
__device__ float g_Pmsg[(size_t)MAXN * EMB];
__device__ float g_agg[(size_t)MAXN * EMB];
__device__ float g_hnode[(size_t)MAXN * 2 * EMB];   // [h1 | h2]
__device__ float g_AB[(size_t)MAXN * 2 * EMB];      // [Asrc | Bdst]
__device__ float g_deg[MAXN];
__device__ float g_qb[EMB];
__device__ float g_y[MAXE2];
__device__ unsigned g_T;
__device__ int g_rem;
__device__ int g_tie[MAX_TIES];
// bf16 split operand buffers
__device__ __nv_bfloat16 g_sa[(size_t)MAXN * KPMAX];           // A' big
__device__ __nv_bfloat16 g_sarel[(size_t)2 * RELSLOT * 3072];  // relcat A' (reused 3x)
__device__ __nv_bfloat16 g_sb[(size_t)EMB * KPMAX];            // B'

// ----------------------------------------------------------------------------
// helpers
// ----------------------------------------------------------------------------
__device__ __forceinline__ uint32_t smem_u32(const void* p) {
    uint32_t a;
    asm("{ .reg .u64 t; cvta.to.shared.u64 t, %1; cvt.u32.u64 %0, t; }" : "=r"(a) : "l"(p));
    return a;
}
// 64B rows, 4x16B chunks, XOR swizzle: conflict-free for cp.async stores + ldmatrix
__device__ __forceinline__ int sw64(int row, int chk) {
    return row * 64 + (((chk) ^ ((row >> 1) & 3)) << 4);
}
__device__ __forceinline__ void cp16(uint32_t sa, const void* gp) {
    uint64_t ga;
    asm("cvta.to.global.u64 %0, %1;" : "=l"(ga) : "l"(gp));
    asm volatile("cp.async.cg.shared.global [%0], [%1], 16;" :: "r"(sa), "l"(ga) : "memory");
}

// ----------------------------------------------------------------------------
// bf16 split GEMM: mma.sync.m16n8k16 + ldmatrix + cp.async 4-stage pipeline.
// 128 threads = 4 warps (2m x 2n), warp tile 64x64.
// C[M,N] = A'[M,KP] · B'[N,KP]^T (+bias)(+relu). M%128==0, N%128==0, KP%32==0.
// ----------------------------------------------------------------------------
__global__ __launch_bounds__(128, 2)
void gemm_mma(const __nv_bfloat16* __restrict__ A, const __nv_bfloat16* __restrict__ B,
              float* __restrict__ C, int ldc, int KP,
              const float* __restrict__ bias, int dorelu)
{
    extern __shared__ __align__(1024) char smem[];
    const int tid  = threadIdx.x;
    const int wid  = tid >> 5;
    const int lane = tid & 31;
    const int bm0 = blockIdx.y * BM;
    const int bn0 = blockIdx.x * BN;
    const int wm0 = (wid & 1) * 64;
    const int wn0 = (wid >> 1) * 64;
    const uint32_t sbase = smem_u32(smem);

    // cp.async: 128 threads, each handles rows {r0, r0+32, r0+64, r0+96}, one 16B chunk
    const int arow0 = tid >> 2, achk = tid & 3;

    // ldmatrix per-lane address components
    const int midx = lane >> 3, mr = lane & 7;
    int aRowB[4], aRx[4];
#pragma unroll
    for (int ma = 0; ma < 4; ma++) {
        int r = wm0 + ma * 16 + (midx & 1) * 8 + mr;
        aRowB[ma] = r * 64; aRx[ma] = (r >> 1) & 3;
    }
    const int aCs = midx >> 1;
    int bRowB[4], bRx[4];
#pragma unroll
    for (int p = 0; p < 4; p++) {
        int r = wn0 + p * 16 + (midx >> 1) * 8 + mr;
        bRowB[p] = r * 64; bRx[p] = (r >> 1) & 3;
    }
    const int bCs = midx & 1;

    float c[4][8][4];
#pragma unroll
    for (int ma = 0; ma < 4; ma++)
#pragma unroll
        for (int na = 0; na < 8; na++)
#pragma unroll
            for (int i = 0; i < 4; i++) c[ma][na][i] = 0.f;

    const int nchunk = KP >> 5;

    auto issue_stage = [&](int ck) {
        if (ck < nchunk) {
            const int kc = ck * BK;
            const uint32_t st = sbase + (ck & 3) * STAGE_BYTES;
#pragma unroll
            for (int rr = 0; rr < 4; rr++) {
                const int row = arow0 + rr * 32;
                cp16(st + sw64(row, achk),        A + (size_t)(bm0 + row) * KP + kc + achk * 8);
                cp16(st + 8192 + sw64(row, achk), B + (size_t)(bn0 + row) * KP + kc + achk * 8);
            }
        }
        asm volatile("cp.async.commit_group;" ::: "memory");
    };

    issue_stage(0);
    issue_stage(1);
    issue_stage(2);

    for (int ck = 0; ck < nchunk; ck++) {
        asm volatile("cp.async.wait_group 2;" ::: "memory");
        __syncthreads();
        issue_stage(ck + 3);

        const uint32_t stA = sbase + (ck & 3) * STAGE_BYTES;
        const uint32_t stB = stA + 8192;
#pragma unroll
        for (int s = 0; s < 2; s++) {
            uint32_t af[4][4], bf[8][2];
#pragma unroll
            for (int ma = 0; ma < 4; ma++) {
                uint32_t ad = stA + aRowB[ma] + ((((s << 1) + aCs) ^ aRx[ma]) << 4);
                asm volatile("ldmatrix.sync.aligned.m8n8.x4.shared.b16 {%0,%1,%2,%3}, [%4];"
                             : "=r"(af[ma][0]), "=r"(af[ma][1]), "=r"(af[ma][2]), "=r"(af[ma][3])
                             : "r"(ad));
            }
#pragma unroll
            for (int p = 0; p < 4; p++) {
                uint32_t bd = stB + bRowB[p] + ((((s << 1) + bCs) ^ bRx[p]) << 4);
                asm volatile("ldmatrix.sync.aligned.m8n8.x4.shared.b16 {%0,%1,%2,%3}, [%4];"
                             : "=r"(bf[2 * p][0]), "=r"(bf[2 * p][1]),
                               "=r"(bf[2 * p + 1][0]), "=r"(bf[2 * p + 1][1])
                             : "r"(bd));
            }
#pragma unroll
            for (int ma = 0; ma < 4; ma++)
#pragma unroll
                for (int na = 0; na < 8; na++)
                    asm volatile(
                        "mma.sync.aligned.m16n8k16.row.col.f32.bf16.bf16.f32 "
                        "{%0,%1,%2,%3}, {%4,%5,%6,%7}, {%8,%9}, {%0,%1,%2,%3};"
                        : "+f"(c[ma][na][0]), "+f"(c[ma][na][1]),
                          "+f"(c[ma][na][2]), "+f"(c[ma][na][3])
                        : "r"(af[ma][0]), "r"(af[ma][1]), "r"(af[ma][2]), "r"(af[ma][3]),
                          "r"(bf[na][0]), "r"(bf[na][1]));
        }
    }

    // epilogue
    const int g = lane >> 2;
    const int q = lane & 3;
#pragma unroll
    for (int ma = 0; ma < 4; ma++) {
        const int row = bm0 + wm0 + ma * 16 + g;
#pragma unroll
        for (int na = 0; na < 8; na++) {
            const int col = bn0 + wn0 + na * 8 + q * 2;
            float v0 = c[ma][na][0], v1 = c[ma][na][1];
            float v2 = c[ma][na][2], v3 = c[ma][na][3];
            if (bias) {
                float bx = bias[col], by = bias[col + 1];
                v0 += bx; v1 += by; v2 += bx; v3 += by;
            }
            if (dorelu) {
                v0 = fmaxf(v0, 0.f); v1 = fmaxf(v1, 0.f);
                v2 = fmaxf(v2, 0.f); v3 = fmaxf(v3, 0.f);
            }
            *reinterpret_cast<float2*>(C + (size_t)row * ldc + col) = make_float2(v0, v1);
            *reinterpret_cast<float2*>(C + (size_t)(row + 8) * ldc + col) = make_float2(v2, v3);
        }
    }
}

// ----------------------------------------------------------------------------
// Split kernels: fp32 -> bf16 triple layout
// A' = [hi | lo | hi] along K ; B' = [hi | hi | lo] (with transpose)
// ----------------------------------------------------------------------------
__global__ void split_a_kernel(const float* __restrict__ A, int lda, int M, int K,
                               int K64, int KP, __nv_bfloat16* __restrict__ out)
{
    long long idx = (long long)blockIdx.x * blockDim.x + threadIdx.x;
    long long total = (long long)M * K64;
    if (idx >= total) return;
    int row = (int)(idx / K64);
    int kk = (int)(idx % K64);
    float v = (kk < K) ? A[(size_t)row * lda + kk] : 0.f;
    __nv_bfloat16 hi = __float2bfloat16(v);
    __nv_bfloat16 lo = __float2bfloat16(v - __bfloat162float(hi));
    __nv_bfloat16* o = out + (size_t)row * KP;
    o[kk] = hi;
    o[K64 + kk] = lo;
    o[2 * K64 + kk] = hi;
}

__global__ void split_b_kernel(const float* __restrict__ W, int ldw, int K, int N,
                               int K64, int KP, __nv_bfloat16* __restrict__ out)
{
    __shared__ float t[32][33];
    int kk0 = blockIdx.y * 32, n0 = blockIdx.x * 32;
    int tx = threadIdx.x, ty = threadIdx.y;   // 32x8
#pragma unroll
    for (int j = 0; j < 32; j += 8) {
        int kk = kk0 + ty + j, n = n0 + tx;
        t[ty + j][tx] = (kk < K && n < N) ? W[(size_t)kk * ldw + n] : 0.f;
    }
    __syncthreads();
#pragma unroll
    for (int j = 0; j < 32; j += 8) {
        int n = n0 + ty + j, kk = kk0 + tx;
        if (n < N && kk < K64) {
            float v = t[tx][ty + j];
            __nv_bfloat16 hi = __float2bfloat16(v);
            __nv_bfloat16 lo = __float2bfloat16(v - __bfloat162float(hi));
            __nv_bfloat16* o = out + (size_t)n * KP;
            o[kk] = hi;
            o[K64 + kk] = hi;
            o[2 * K64 + kk] = lo;
        }
    }
}

// ----------------------------------------------------------------------------
// Non-GEMM kernels (unchanged)
// ----------------------------------------------------------------------------
__global__ void zero_kernel(float4* p, int n4) {
    int i = blockIdx.x * blockDim.x + threadIdx.x;
    int stride = gridDim.x * blockDim.x;
    float4 z = make_float4(0.f, 0.f, 0.f, 0.f);
    for (; i < n4; i += stride) p[i] = z;
}

__global__ void build_h0_kernel(const float* __restrict__ entity,
                                const float* __restrict__ nontext,
                                const float* __restrict__ topic,
                                int n_text, int n_nodes)
{
    int n = blockIdx.x;
    if (n >= n_nodes) return;
    float* dst = g_h0 + (size_t)n * D0PAD;
    const float* src = (n < n_text) ? (entity + (size_t)n * EMB) : nontext;
    for (int j = threadIdx.x; j < D0PAD; j += blockDim.x) {
        float v;
        if (j < EMB)          v = src[j];
        else if (j < EMB + 2) v = topic[(size_t)n * 2 + (j - EMB)];
        else                  v = 0.f;
        dst[j] = v;
    }
}

__global__ void relcat_kernel(const float* __restrict__ rel, int n_rel) {
    int i = blockIdx.x * blockDim.x + threadIdx.x;
    if (i >= RELSLOT * EMB) return;
    int row = i / EMB;
    g_relcat[i] = (row < n_rel) ? rel[i] : 0.f;
}

__global__ void deg_kernel(const int* __restrict__ h_id, const int* __restrict__ t_id, int E) {
    int i = blockIdx.x * blockDim.x + threadIdx.x;
    if (i >= 2 * E) return;
    int dst = (i < E) ? t_id[i] : h_id[i - E];
    atomicAdd(&g_deg[dst], 1.0f);
}

__global__ void edge_msg_kernel(const int* __restrict__ h_id, const int* __restrict__ t_id,
                                const int* __restrict__ r_id, int E)
{
    int e = blockIdx.x;
    int src, dst, rel;
    if (e < E) { src = h_id[e]; dst = t_id[e]; rel = r_id[e]; }
    else { int e2 = e - E; src = t_id[e2]; dst = h_id[e2]; rel = RELSLOT + r_id[e2]; }
    int j = threadIdx.x;
    const float4 pv = reinterpret_cast<const float4*>(g_Pmsg + (size_t)src * EMB)[j];
    const float4 qv = reinterpret_cast<const float4*>(g_Q + (size_t)rel * EMB)[j];
    float4 m;
    m.x = fmaxf(pv.x + qv.x, 0.f);
    m.y = fmaxf(pv.y + qv.y, 0.f);
    m.z = fmaxf(pv.z + qv.z, 0.f);
    m.w = fmaxf(pv.w + qv.w, 0.f);
    atomicAdd(reinterpret_cast<float4*>(g_agg + (size_t)dst * EMB) + j, m);
}

__global__ void node_update_kernel(int n_nodes, int layer) {
    int i = blockIdx.x * blockDim.x + threadIdx.x;
    int total = n_nodes * (EMB / 4);
    if (i >= total) return;
    int n = i >> 8;
    int j4 = i & 255;
    float inv = 1.0f / fmaxf(g_deg[n], 1.0f);
    float4 ps = reinterpret_cast<const float4*>(g_Pself + (size_t)n * EMB)[j4];
    float4 ag = reinterpret_cast<const float4*>(g_agg + (size_t)n * EMB)[j4];
    float4 v;
    v.x = fmaxf(ps.x + ag.x * inv, 0.f);
    v.y = fmaxf(ps.y + ag.y * inv, 0.f);
    v.z = fmaxf(ps.z + ag.z * inv, 0.f);
    v.w = fmaxf(ps.w + ag.w * inv, 0.f);
    reinterpret_cast<float4*>(g_hnode + (size_t)n * 2 * EMB + (size_t)layer * EMB)[j4] = v;
}

__global__ void qb_kernel(const float* __restrict__ q, const float* __restrict__ predw1,
                          const float* __restrict__ predb1)
{
    int j = blockIdx.x * blockDim.x + threadIdx.x;
    if (j >= EMB) return;
    float acc = 0.f;
    for (int k = 0; k < EMB; k++) acc += q[k] * predw1[(size_t)k * EMB + j];
    g_qb[j] = acc + predb1[j];
}

__device__ __forceinline__ void threefry2x32(unsigned k0, unsigned k1,
                                             unsigned& x0, unsigned& x1)
{
    unsigned ks2 = k0 ^ k1 ^ 0x1BD11BDAu;
    x0 += k0; x1 += k1;
#define TFR(r) { x0 += x1; x1 = (x1 << (r)) | (x1 >> (32 - (r))); x1 ^= x0; }
    TFR(13) TFR(15) TFR(26) TFR(6)
    x0 += k1;  x1 += ks2 + 1u;
    TFR(17) TFR(29) TFR(16) TFR(24)
    x0 += ks2; x1 += k0 + 2u;
    TFR(13) TFR(15) TFR(26) TFR(6)
    x0 += k0;  x1 += k1 + 3u;
    TFR(17) TFR(29) TFR(16) TFR(24)
    x0 += k1;  x1 += ks2 + 4u;
    TFR(13) TFR(15) TFR(26) TFR(6)
    x0 += ks2; x1 += k0 + 5u;
#undef TFR
}

__device__ __forceinline__ float gumbel_noise(int e) {
    unsigned x0 = 0u;
    unsigned x1 = (unsigned)e;
    threefry2x32(0u, 42u, x0, x1);
    unsigned bits = x0 ^ x1;
    float f = __uint_as_float((bits >> 9) | 0x3f800000u) - 1.0f;
    float u = fmaxf(1e-10f, f + 1e-10f);
    return -logf(-logf(u));
}

__global__ void edge_logits_kernel(const int* __restrict__ h_id, const int* __restrict__ t_id,
                                   const int* __restrict__ r_id, int E,
                                   const float* __restrict__ w2, const float* __restrict__ b2)
{
    int e = blockIdx.x;
    int src, dst, rel;
    if (e < E) { src = h_id[e]; dst = t_id[e]; rel = r_id[e]; }
    else { int e2 = e - E; src = t_id[e2]; dst = h_id[e2]; rel = RELSLOT + r_id[e2]; }
    int tid = threadIdx.x;
    float4 a  = reinterpret_cast<const float4*>(g_AB + (size_t)src * 2 * EMB)[tid];
    float4 b  = reinterpret_cast<const float4*>(g_AB + (size_t)dst * 2 * EMB + EMB)[tid];
    float4 rr = reinterpret_cast<const float4*>(g_Q + (size_t)rel * EMB)[tid];
    float4 qv = reinterpret_cast<const float4*>(g_qb)[tid];
    float4 w  = reinterpret_cast<const float4*>(w2)[tid];
    float acc = fmaxf(qv.x + a.x + rr.x + b.x, 0.f) * w.x
              + fmaxf(qv.y + a.y + rr.y + b.y, 0.f) * w.y
              + fmaxf(qv.z + a.z + rr.z + b.z, 0.f) * w.z
              + fmaxf(qv.w + a.w + rr.w + b.w, 0.f) * w.w;
#pragma unroll
    for (int o = 16; o; o >>= 1) acc += __shfl_xor_sync(0xffffffffu, acc, o);
    __shared__ float sred[8];
    if ((tid & 31) == 0) sred[tid >> 5] = acc;
    __syncthreads();
    if (tid == 0) {
        float s = 0.f;
#pragma unroll
        for (int wdx = 0; wdx < 8; wdx++) s += sred[wdx];
        g_y[e] = s + b2[0] + gumbel_noise(e);
    }
}

__device__ __forceinline__ unsigned f2key(float v) {
    unsigned b = __float_as_uint(v);
    return (b & 0x80000000u) ? ~b : (b | 0x80000000u);
}

__global__ void topk_kernel(int n, int K) {
    __shared__ unsigned hist[256];
    __shared__ unsigned s_prefix;
    __shared__ int s_krem;
    __shared__ int s_cnt;
    int tid = threadIdx.x;
    if (tid == 0) { s_prefix = 0; s_krem = K; s_cnt = 0; }
    __syncthreads();
    for (int pass = 3; pass >= 0; pass--) {
        int shift = pass * 8;
        if (tid < 256) hist[tid] = 0;
        __syncthreads();
        unsigned prefix = s_prefix;
        for (int i = tid; i < n; i += blockDim.x) {
            unsigned key = f2key(g_y[i]);
            bool match = (pass == 3) || ((key >> (shift + 8)) == (prefix >> (shift + 8)));
            if (match) atomicAdd(&hist[(key >> shift) & 255], 1u);
        }
        __syncthreads();
        if (tid == 0) {
            int krem = s_krem;
            unsigned cum = 0;
            int b = 255;
            for (; b >= 0; b--) {
                if (cum + hist[b] >= (unsigned)krem) break;
                cum += hist[b];
            }
            if (b < 0) b = 0;
            s_prefix = prefix | ((unsigned)b << shift);
            s_krem = krem - (int)cum;
        }
        __syncthreads();
    }
    unsigned T = s_prefix;
    int rem = s_krem;
    for (int i = tid; i < n; i += blockDim.x) {
        if (f2key(g_y[i]) == T) {
            int p = atomicAdd(&s_cnt, 1);
            if (p < MAX_TIES) g_tie[p] = i;
        }
    }
    __syncthreads();
    if (tid == 0) {
        int c = s_cnt < MAX_TIES ? s_cnt : MAX_TIES;
        for (int a = 1; a < c; a++) {
            int v = g_tie[a];
            int b = a - 1;
            while (b >= 0 && g_tie[b] > v) { g_tie[b + 1] = g_tie[b]; b--; }
            g_tie[b + 1] = v;
        }
        if (rem > c) rem = c;
        if (rem < 0) rem = 0;
        g_T = T;
        g_rem = rem;
    }
}

__global__ void output_kernel(float* __restrict__ out, int n) {
    int i = blockIdx.x * blockDim.x + threadIdx.x;
    if (i >= n) return;
    unsigned key = f2key(g_y[i]);
    float o = 0.f;
    unsigned T = g_T;
    if (key > T) o = 1.f;
    else if (key == T) {
        int rem = g_rem;
        for (int t = 0; t < rem; t++)
            if (g_tie[t] == i) { o = 1.f; break; }
    }
    out[i] = o;
}

// ----------------------------------------------------------------------------
// Host-side helpers
// ----------------------------------------------------------------------------
static void split_a(const float* A, int lda, int M, int K, int K64, int KP, __nv_bfloat16* out) {
    long long total = (long long)M * K64;
    int blocks = (int)((total + 255) / 256);
    split_a_kernel<<<blocks, 256>>>(A, lda, M, K, K64, KP, out);
}
static void split_b(const float* W, int ldw, int K, int N, int K64, int KP, __nv_bfloat16* out) {
    dim3 grid((N + 31) / 32, (K64 + 31) / 32);
    split_b_kernel<<<grid, dim3(32, 8)>>>(W, ldw, K, N, K64, KP, out);
}
static void gemm(const __nv_bfloat16* A, const __nv_bfloat16* B, float* C, int ldc,
                 int M, int N, int KP, const float* bias, int relu) {
    dim3 grid(N / BN, M / BM);
    gemm_mma<<<grid, 128, GSMEM>>>(A, B, C, ldc, KP, bias, relu);
}

extern "C" void kernel_launch(void* const* d_in, const int* in_sizes, int n_in,
                              void* d_out, int out_size)
{
    cudaFuncSetAttribute(gemm_mma, cudaFuncAttributeMaxDynamicSharedMemorySize, GSMEM);

    const int* h_id = (const int*)d_in[0];
    const int* t_id = (const int*)d_in[1];
    const int* r_id = (const int*)d_in[2];
    const int s = (n_in >= 25) ? 1 : 0;
    const int b0 = 3 + s;
    const float* q_emb   = (const float*)d_in[b0 + 0];
    const float* entity  = (const float*)d_in[b0 + 1];
    const float* rel     = (const float*)d_in[b0 + 2];
    const float* topic   = (const float*)d_in[b0 + 3];
    const float* nontext = (const float*)d_in[b0 + 4];
    const float* wself1  = (const float*)d_in[b0 + 5];
    const float* bself1  = (const float*)d_in[b0 + 6];
    const float* wmsg1   = (const float*)d_in[b0 + 7];
    const float* bmsg1   = (const float*)d_in[b0 + 8];
    const float* wself2  = (const float*)d_in[b0 + 9];
    const float* bself2  = (const float*)d_in[b0 + 10];
    const float* wmsg2   = (const float*)d_in[b0 + 11];
    const float* bmsg2   = (const float*)d_in[b0 + 12];
    const float* revw1   = (const float*)d_in[b0 + 13];
    const float* revb1   = (const float*)d_in[b0 + 14];
    const float* revw2   = (const float*)d_in[b0 + 15];
    const float* revb2   = (const float*)d_in[b0 + 16];
    const float* predw1  = (const float*)d_in[b0 + 17];
    const float* predb1  = (const float*)d_in[b0 + 18];
    const float* predw2  = (const float*)d_in[b0 + 19];
    const float* predb2  = (const float*)d_in[b0 + 20];

    const int E       = in_sizes[0];
    const int n_text  = in_sizes[b0 + 1] / EMB;
    const int n_rel   = in_sizes[b0 + 2] / EMB;
    const int n_nodes = in_sizes[b0 + 3] / 2;
    const int d0      = in_sizes[b0 + 5] / EMB;   // 1026
    const int E2      = 2 * E;
    if (n_nodes > MAXN || E2 > MAXE2 || n_rel > RELSLOT) return;

    float *p_h0, *p_relcat, *p_revh, *p_Q, *p_Pself, *p_Pmsg, *p_agg, *p_hnode, *p_AB, *p_deg;
    __nv_bfloat16 *p_sa, *p_sarel, *p_sb;
    cudaGetSymbolAddress((void**)&p_h0,     g_h0);
    cudaGetSymbolAddress((void**)&p_relcat, g_relcat);
    cudaGetSymbolAddress((void**)&p_revh,   g_revh);
    cudaGetSymbolAddress((void**)&p_Q,      g_Q);
    cudaGetSymbolAddress((void**)&p_Pself,  g_Pself);
    cudaGetSymbolAddress((void**)&p_Pmsg,   g_Pmsg);
    cudaGetSymbolAddress((void**)&p_agg,    g_agg);
    cudaGetSymbolAddress((void**)&p_hnode,  g_hnode);
    cudaGetSymbolAddress((void**)&p_AB,     g_AB);
    cudaGetSymbolAddress((void**)&p_deg,    g_deg);
    cudaGetSymbolAddress((void**)&p_sa,     g_sa);
    cudaGetSymbolAddress((void**)&p_sarel,  g_sarel);
    cudaGetSymbolAddress((void**)&p_sb,     g_sb);

    // ---- prep ----
    zero_kernel<<<1024, 256>>>((float4*)p_agg, MAXN * EMB / 4);
    zero_kernel<<<32, 256>>>((float4*)p_deg, MAXN / 4);
    build_h0_kernel<<<n_nodes, 256>>>(entity, nontext, topic, n_text, n_nodes);
    relcat_kernel<<<(RELSLOT * EMB + 255) / 256, 256>>>(rel, n_rel);
    deg_kernel<<<(E2 + 255) / 256, 256>>>(h_id, t_id, E);

    // ---- reverse-relation MLP ----
    split_a(p_relcat, EMB, RELSLOT, EMB, 1024, 3072, p_sa);
    split_b(revw1, EMB, EMB, EMB, 1024, 3072, p_sb);
    gemm(p_sa, p_sb, p_revh, EMB, RELSLOT, EMB, 3072, revb1, 1);
    split_a(p_revh, EMB, RELSLOT, EMB, 1024, 3072, p_sa);
    split_b(revw2, EMB, EMB, EMB, 1024, 3072, p_sb);
    gemm(p_sa, p_sb, p_relcat + (size_t)RELSLOT * EMB, EMB, RELSLOT, EMB, 3072, revb2, 0);

    // relation A' table (fwd+rev), reused for all 3 Q projections
    split_a(p_relcat, EMB, 2 * RELSLOT, EMB, 1024, 3072, p_sarel);

    // ---- SAGE layer 1 ----
    split_b(wmsg1 + (size_t)d0 * EMB, EMB, EMB, EMB, 1024, 3072, p_sb);
    gemm(p_sarel, p_sb, p_Q, EMB, 2 * RELSLOT, EMB, 3072, nullptr, 0);
    split_a(p_h0, D0PAD, MAXN, D0PAD, 1088, 3264, p_sa);
    split_b(wmsg1, EMB, d0, EMB, 1088, 3264, p_sb);
    gemm(p_sa, p_sb, p_Pmsg, EMB, MAXN, EMB, 3264, bmsg1, 0);
    split_b(wself1, EMB, d0, EMB, 1088, 3264, p_sb);
    gemm(p_sa, p_sb, p_Pself, EMB, MAXN, EMB, 3264, bself1, 0);
    edge_msg_kernel<<<E2, 256>>>(h_id, t_id, r_id, E);
    node_update_kernel<<<(n_nodes * (EMB / 4) + 255) / 256, 256>>>(n_nodes, 0);

    // ---- SAGE layer 2 ----
    zero_kernel<<<1024, 256>>>((float4*)p_agg, MAXN * EMB / 4);
    split_b(wmsg2 + (size_t)EMB * EMB, EMB, EMB, EMB, 1024, 3072, p_sb);
    gemm(p_sarel, p_sb, p_Q, EMB, 2 * RELSLOT, EMB, 3072, nullptr, 0);
    split_a(p_hnode, 2 * EMB, MAXN, EMB, 1024, 3072, p_sa);   // h1
    split_b(wmsg2, EMB, EMB, EMB, 1024, 3072, p_sb);
    gemm(p_sa, p_sb, p_Pmsg, EMB, MAXN, EMB, 3072, bmsg2, 0);
    split_b(wself2, EMB, EMB, EMB, 1024, 3072, p_sb);
    gemm(p_sa, p_sb, p_Pself, EMB, MAXN, EMB, 3072, bself2, 0);
    edge_msg_kernel<<<E2, 256>>>(h_id, t_id, r_id, E);
    node_update_kernel<<<(n_nodes * (EMB / 4) + 255) / 256, 256>>>(n_nodes, 1);

    // ---- predictor projections ----
    split_b(predw1 + (size_t)3 * EMB * EMB, EMB, EMB, EMB, 1024, 3072, p_sb);
    gemm(p_sarel, p_sb, p_Q, EMB, 2 * RELSLOT, EMB, 3072, nullptr, 0);
    split_a(p_hnode, 2 * EMB, MAXN, 2 * EMB, 2048, 6144, p_sa);
    split_b(predw1 + (size_t)EMB * EMB, EMB, 2 * EMB, EMB, 2048, 6144, p_sb);
    gemm(p_sa, p_sb, p_AB, 2 * EMB, MAXN, EMB, 6144, nullptr, 0);
    split_b(predw1 + (size_t)4 * EMB * EMB, EMB, 2 * EMB, EMB, 2048, 6144, p_sb);
    gemm(p_sa, p_sb, p_AB + EMB, 2 * EMB, MAXN, EMB, 6144, nullptr, 0);
    qb_kernel<<<4, 256>>>(q_emb, predw1, predb1);

    // ---- edge logits + gumbel + exact top-K ----
    edge_logits_kernel<<<E2, 256>>>(h_id, t_id, r_id, E, predw2, predb2);
    topk_kernel<<<1, 1024>>>(E2, 512);
    output_kernel<<<(E2 + 255) / 256, 256>>>((float*)d_out, E2);
}

// round 15
// speedup vs baseline: 2.8953x; 1.0291x over previous
#include <cuda_runtime.h>
#include <cuda_bf16.h>
#include <math.h>
#include <stdint.h>

#define EMB 1024
#define D0PAD 1032
#define MAXN 22016
#define RELSLOT 2048
#define MAXE2 40960
#define MAX_TIES 1024
#define KPMAX 6144

// ---------------- mma.sync GEMM tile config ----------------
#define BM 128
#define BN 128
#define BK 64                  // bf16 per K-chunk
#define STAGE_BYTES 32768      // A 16KB + B 16KB
#define NSTAGE 3
#define GSMEM (NSTAGE * STAGE_BYTES)

// ----------------------------------------------------------------------------
// Static scratch
// ----------------------------------------------------------------------------
__device__ float g_h0[(size_t)MAXN * D0PAD];
__device__ float g_relcat[(size_t)2 * RELSLOT * EMB];
__device__ float g_revh[(size_t)RELSLOT * EMB];
__device__ float g_Q[(size_t)2 * RELSLOT * 3072];   // merged [Q1|Q2|Qpred], ldc=3072
__device__ float g_P[(size_t)MAXN * 2 * EMB];       // merged [Pmsg|Pself], ldc=2048
__device__ float g_agg[(size_t)MAXN * EMB];
__device__ float g_hnode[(size_t)MAXN * 2 * EMB];   // [h1 | h2]
__device__ float g_AB[(size_t)MAXN * 2 * EMB];      // [Asrc | Bdst], ldc=2048
__device__ float g_deg[MAXN];
__device__ float g_qb[EMB];
__device__ float g_bias2[2 * EMB];
__device__ float g_y[MAXE2];
__device__ unsigned g_T;
__device__ int g_rem;
__device__ int g_tie[MAX_TIES];
// bf16 split operand buffers
__device__ __nv_bfloat16 g_sa[(size_t)MAXN * KPMAX];           // A' big
__device__ __nv_bfloat16 g_sarel[(size_t)2 * RELSLOT * 3072];  // relcat A'
__device__ __nv_bfloat16 g_sb[(size_t)2048 * KPMAX];           // B' (multi-block)

// ----------------------------------------------------------------------------
// helpers
// ----------------------------------------------------------------------------
__device__ __forceinline__ uint32_t smem_u32(const void* p) {
    uint32_t a;
    asm("{ .reg .u64 t; cvta.to.shared.u64 t, %1; cvt.u32.u64 %0, t; }" : "=r"(a) : "l"(p));
    return a;
}
// 128B rows, 8x16B chunks, XOR swizzle (chunk ^ (row&7)): conflict-free for
// cp.async store phases and all ldmatrix phases.
__device__ __forceinline__ int sw128(int row, int chk) {
    return row * 128 + (((chk) ^ (row & 7)) << 4);
}
__device__ __forceinline__ void cp16(uint32_t sa, const void* gp) {
    uint64_t ga;
    asm("cvta.to.global.u64 %0, %1;" : "=l"(ga) : "l"(gp));
    asm volatile("cp.async.cg.shared.global [%0], [%1], 16;" :: "r"(sa), "l"(ga) : "memory");
}

// ----------------------------------------------------------------------------
// bf16 split GEMM: mma.sync.m16n8k16 + ldmatrix + cp.async 3-stage, BK=64.
// 128 threads = 4 warps (2m x 2n), warp tile 64x64.
// C[M,N] = A'[M,KP] · B'[N,KP]^T (+bias)(+relu). M%128==0, N%128==0, KP%64==0.
// ----------------------------------------------------------------------------
__global__ __launch_bounds__(128, 2)
void gemm_mma(const __nv_bfloat16* __restrict__ A, const __nv_bfloat16* __restrict__ B,
              float* __restrict__ C, int ldc, int KP,
              const float* __restrict__ bias, int dorelu)
{
    extern __shared__ __align__(1024) char smem[];
    const int tid  = threadIdx.x;
    const int wid  = tid >> 5;
    const int lane = tid & 31;
    const int bm0 = blockIdx.y * BM;
    const int bn0 = blockIdx.x * BN;
    const int wm0 = (wid & 1) * 64;
    const int wn0 = (wid >> 1) * 64;
    const uint32_t sbase = smem_u32(smem);

    // ldmatrix per-lane address components
    const int midx = lane >> 3, mr = lane & 7;
    int aRowB[4], aRx[4];
#pragma unroll
    for (int ma = 0; ma < 4; ma++) {
        int r = wm0 + ma * 16 + (midx & 1) * 8 + mr;
        aRowB[ma] = r * 128; aRx[ma] = r & 7;
    }
    const int aCs = midx >> 1;
    int bRowB[4], bRx[4];
#pragma unroll
    for (int p = 0; p < 4; p++) {
        int r = wn0 + p * 16 + (midx >> 1) * 8 + mr;
        bRowB[p] = r * 128; bRx[p] = r & 7;
    }
    const int bCs = midx & 1;

    float c[4][8][4];
#pragma unroll
    for (int ma = 0; ma < 4; ma++)
#pragma unroll
        for (int na = 0; na < 8; na++)
#pragma unroll
            for (int i = 0; i < 4; i++) c[ma][na][i] = 0.f;

    const int nchunk = KP >> 6;

    auto issue_stage = [&](int ck) {
        if (ck < nchunk) {
            const int kc = ck * BK;
            const uint32_t st = sbase + (ck % NSTAGE) * STAGE_BYTES;
#pragma unroll
            for (int i = 0; i < 8; i++) {
                const int u = tid + 128 * i;
                const int row = u >> 3, chk = u & 7;
                cp16(st + sw128(row, chk),         A + (size_t)(bm0 + row) * KP + kc + chk * 8);
                cp16(st + 16384 + sw128(row, chk), B + (size_t)(bn0 + row) * KP + kc + chk * 8);
            }
        }
        asm volatile("cp.async.commit_group;" ::: "memory");
    };

    issue_stage(0);
    issue_stage(1);

    for (int ck = 0; ck < nchunk; ck++) {
        asm volatile("cp.async.wait_group 1;" ::: "memory");
        __syncthreads();
        issue_stage(ck + 2);

        const uint32_t stA = sbase + (ck % NSTAGE) * STAGE_BYTES;
        const uint32_t stB = stA + 16384;
#pragma unroll
        for (int s = 0; s < 4; s++) {
            uint32_t af[4][4], bf[8][2];
#pragma unroll
            for (int ma = 0; ma < 4; ma++) {
                uint32_t ad = stA + aRowB[ma] + ((((s << 1) + aCs) ^ aRx[ma]) << 4);
                asm volatile("ldmatrix.sync.aligned.m8n8.x4.shared.b16 {%0,%1,%2,%3}, [%4];"
                             : "=r"(af[ma][0]), "=r"(af[ma][1]), "=r"(af[ma][2]), "=r"(af[ma][3])
                             : "r"(ad));
            }
#pragma unroll
            for (int p = 0; p < 4; p++) {
                uint32_t bd = stB + bRowB[p] + ((((s << 1) + bCs) ^ bRx[p]) << 4);
                asm volatile("ldmatrix.sync.aligned.m8n8.x4.shared.b16 {%0,%1,%2,%3}, [%4];"
                             : "=r"(bf[2 * p][0]), "=r"(bf[2 * p][1]),
                               "=r"(bf[2 * p + 1][0]), "=r"(bf[2 * p + 1][1])
                             : "r"(bd));
            }
#pragma unroll
            for (int ma = 0; ma < 4; ma++)
#pragma unroll
                for (int na = 0; na < 8; na++)
                    asm volatile(
                        "mma.sync.aligned.m16n8k16.row.col.f32.bf16.bf16.f32 "
                        "{%0,%1,%2,%3}, {%4,%5,%6,%7}, {%8,%9}, {%0,%1,%2,%3};"
                        : "+f"(c[ma][na][0]), "+f"(c[ma][na][1]),
                          "+f"(c[ma][na][2]), "+f"(c[ma][na][3])
                        : "r"(af[ma][0]), "r"(af[ma][1]), "r"(af[ma][2]), "r"(af[ma][3]),
                          "r"(bf[na][0]), "r"(bf[na][1]));
        }
    }

    // epilogue
    const int g = lane >> 2;
    const int q = lane & 3;
#pragma unroll
    for (int ma = 0; ma < 4; ma++) {
        const int row = bm0 + wm0 + ma * 16 + g;
#pragma unroll
        for (int na = 0; na < 8; na++) {
            const int col = bn0 + wn0 + na * 8 + q * 2;
            float v0 = c[ma][na][0], v1 = c[ma][na][1];
            float v2 = c[ma][na][2], v3 = c[ma][na][3];
            if (bias) {
                float bx = bias[col], by = bias[col + 1];
                v0 += bx; v1 += by; v2 += bx; v3 += by;
            }
            if (dorelu) {
                v0 = fmaxf(v0, 0.f); v1 = fmaxf(v1, 0.f);
                v2 = fmaxf(v2, 0.f); v3 = fmaxf(v3, 0.f);
            }
            *reinterpret_cast<float2*>(C + (size_t)row * ldc + col) = make_float2(v0, v1);
            *reinterpret_cast<float2*>(C + (size_t)(row + 8) * ldc + col) = make_float2(v2, v3);
        }
    }
}

// ----------------------------------------------------------------------------
// Split kernels: fp32 -> bf16 triple layout
// A' = [hi | lo | hi] along K ; B' = [hi | hi | lo] (with transpose)
// ----------------------------------------------------------------------------
__global__ void split_a_kernel(const float* __restrict__ A, int lda, int M, int K,
                               int K64, int KP, __nv_bfloat16* __restrict__ out)
{
    long long idx = (long long)blockIdx.x * blockDim.x + threadIdx.x;
    long long total = (long long)M * K64;
    if (idx >= total) return;
    int row = (int)(idx / K64);
    int kk = (int)(idx % K64);
    float v = (kk < K) ? A[(size_t)row * lda + kk] : 0.f;
    __nv_bfloat16 hi = __float2bfloat16(v);
    __nv_bfloat16 lo = __float2bfloat16(v - __bfloat162float(hi));
    __nv_bfloat16* o = out + (size_t)row * KP;
    o[kk] = hi;
    o[K64 + kk] = lo;
    o[2 * K64 + kk] = hi;
}

__global__ void split_b_kernel(const float* __restrict__ W, int ldw, int K, int N,
                               int K64, int KP, __nv_bfloat16* __restrict__ out)
{
    __shared__ float t[32][33];
    int kk0 = blockIdx.y * 32, n0 = blockIdx.x * 32;
    int tx = threadIdx.x, ty = threadIdx.y;   // 32x8
#pragma unroll
    for (int j = 0; j < 32; j += 8) {
        int kk = kk0 + ty + j, n = n0 + tx;
        t[ty + j][tx] = (kk < K && n < N) ? W[(size_t)kk * ldw + n] : 0.f;
    }
    __syncthreads();
#pragma unroll
    for (int j = 0; j < 32; j += 8) {
        int n = n0 + ty + j, kk = kk0 + tx;
        if (n < N && kk < K64) {
            float v = t[tx][ty + j];
            __nv_bfloat16 hi = __float2bfloat16(v);
            __nv_bfloat16 lo = __float2bfloat16(v - __bfloat162float(hi));
            __nv_bfloat16* o = out + (size_t)n * KP;
            o[kk] = hi;
            o[K64 + kk] = hi;
            o[2 * K64 + kk] = lo;
        }
    }
}

// ----------------------------------------------------------------------------
// Non-GEMM kernels
// ----------------------------------------------------------------------------
__global__ void zero_kernel(float4* p, int n4) {
    int i = blockIdx.x * blockDim.x + threadIdx.x;
    int stride = gridDim.x * blockDim.x;
    float4 z = make_float4(0.f, 0.f, 0.f, 0.f);
    for (; i < n4; i += stride) p[i] = z;
}

__global__ void build_h0_kernel(const float* __restrict__ entity,
                                const float* __restrict__ nontext,
                                const float* __restrict__ topic,
                                int n_text, int n_nodes)
{
    int n = blockIdx.x;
    if (n >= n_nodes) return;
    float* dst = g_h0 + (size_t)n * D0PAD;
    const float* src = (n < n_text) ? (entity + (size_t)n * EMB) : nontext;
    for (int j = threadIdx.x; j < D0PAD; j += blockDim.x) {
        float v;
        if (j < EMB)          v = src[j];
        else if (j < EMB + 2) v = topic[(size_t)n * 2 + (j - EMB)];
        else                  v = 0.f;
        dst[j] = v;
    }
}

__global__ void relcat_kernel(const float* __restrict__ rel, int n_rel) {
    int i = blockIdx.x * blockDim.x + threadIdx.x;
    if (i >= RELSLOT * EMB) return;
    int row = i / EMB;
    g_relcat[i] = (row < n_rel) ? rel[i] : 0.f;
}

__global__ void deg_kernel(const int* __restrict__ h_id, const int* __restrict__ t_id, int E) {
    int i = blockIdx.x * blockDim.x + threadIdx.x;
    if (i >= 2 * E) return;
    int dst = (i < E) ? t_id[i] : h_id[i - E];
    atomicAdd(&g_deg[dst], 1.0f);
}

__global__ void concat_bias_kernel(const float* __restrict__ b1, const float* __restrict__ b2) {
    int i = blockIdx.x * blockDim.x + threadIdx.x;
    if (i < EMB) g_bias2[i] = b1[i];
    else if (i < 2 * EMB) g_bias2[i] = b2[i - EMB];
}

// msg = relu(P[src,0:1024] + Q[rel, qoff:qoff+1024]); agg[dst] += msg
__global__ void edge_msg_kernel(const int* __restrict__ h_id, const int* __restrict__ t_id,
                                const int* __restrict__ r_id, int E, int qoff4)
{
    int e = blockIdx.x;
    int src, dst, rel;
    if (e < E) { src = h_id[e]; dst = t_id[e]; rel = r_id[e]; }
    else { int e2 = e - E; src = t_id[e2]; dst = h_id[e2]; rel = RELSLOT + r_id[e2]; }
    int j = threadIdx.x;
    const float4 pv = reinterpret_cast<const float4*>(g_P)[(size_t)src * 512 + j];
    const float4 qv = reinterpret_cast<const float4*>(g_Q)[(size_t)rel * 768 + qoff4 + j];
    float4 m;
    m.x = fmaxf(pv.x + qv.x, 0.f);
    m.y = fmaxf(pv.y + qv.y, 0.f);
    m.z = fmaxf(pv.z + qv.z, 0.f);
    m.w = fmaxf(pv.w + qv.w, 0.f);
    atomicAdd(reinterpret_cast<float4*>(g_agg + (size_t)dst * EMB) + j, m);
}

// h = relu(P[:,1024:2048] + agg/max(deg,1)) -> hnode[:, layer*EMB : ]
__global__ void node_update_kernel(int n_nodes, int layer) {
    int i = blockIdx.x * blockDim.x + threadIdx.x;
    int total = n_nodes * (EMB / 4);
    if (i >= total) return;
    int n = i >> 8;
    int j4 = i & 255;
    float inv = 1.0f / fmaxf(g_deg[n], 1.0f);
    float4 ps = reinterpret_cast<const float4*>(g_P)[(size_t)n * 512 + 256 + j4];
    float4 ag = reinterpret_cast<const float4*>(g_agg + (size_t)n * EMB)[j4];
    float4 v;
    v.x = fmaxf(ps.x + ag.x * inv, 0.f);
    v.y = fmaxf(ps.y + ag.y * inv, 0.f);
    v.z = fmaxf(ps.z + ag.z * inv, 0.f);
    v.w = fmaxf(ps.w + ag.w * inv, 0.f);
    reinterpret_cast<float4*>(g_hnode + (size_t)n * 2 * EMB + (size_t)layer * EMB)[j4] = v;
}

__global__ void qb_kernel(const float* __restrict__ q, const float* __restrict__ predw1,
                          const float* __restrict__ predb1)
{
    int j = blockIdx.x * blockDim.x + threadIdx.x;
    if (j >= EMB) return;
    float acc = 0.f;
    for (int k = 0; k < EMB; k++) acc += q[k] * predw1[(size_t)k * EMB + j];
    g_qb[j] = acc + predb1[j];
}

__device__ __forceinline__ void threefry2x32(unsigned k0, unsigned k1,
                                             unsigned& x0, unsigned& x1)
{
    unsigned ks2 = k0 ^ k1 ^ 0x1BD11BDAu;
    x0 += k0; x1 += k1;
#define TFR(r) { x0 += x1; x1 = (x1 << (r)) | (x1 >> (32 - (r))); x1 ^= x0; }
    TFR(13) TFR(15) TFR(26) TFR(6)
    x0 += k1;  x1 += ks2 + 1u;
    TFR(17) TFR(29) TFR(16) TFR(24)
    x0 += ks2; x1 += k0 + 2u;
    TFR(13) TFR(15) TFR(26) TFR(6)
    x0 += k0;  x1 += k1 + 3u;
    TFR(17) TFR(29) TFR(16) TFR(24)
    x0 += k1;  x1 += ks2 + 4u;
    TFR(13) TFR(15) TFR(26) TFR(6)
    x0 += ks2; x1 += k0 + 5u;
#undef TFR
}

__device__ __forceinline__ float gumbel_noise(int e) {
    unsigned x0 = 0u;
    unsigned x1 = (unsigned)e;
    threefry2x32(0u, 42u, x0, x1);
    unsigned bits = x0 ^ x1;
    float f = __uint_as_float((bits >> 9) | 0x3f800000u) - 1.0f;
    float u = fmaxf(1e-10f, f + 1e-10f);
    return -logf(-logf(u));
}

__global__ void edge_logits_kernel(const int* __restrict__ h_id, const int* __restrict__ t_id,
                                   const int* __restrict__ r_id, int E,
                                   const float* __restrict__ w2, const float* __restrict__ b2)
{
    int e = blockIdx.x;
    int src, dst, rel;
    if (e < E) { src = h_id[e]; dst = t_id[e]; rel = r_id[e]; }
    else { int e2 = e - E; src = t_id[e2]; dst = h_id[e2]; rel = RELSLOT + r_id[e2]; }
    int tid = threadIdx.x;
    float4 a  = reinterpret_cast<const float4*>(g_AB)[(size_t)src * 512 + tid];
    float4 b  = reinterpret_cast<const float4*>(g_AB)[(size_t)dst * 512 + 256 + tid];
    float4 rr = reinterpret_cast<const float4*>(g_Q)[(size_t)rel * 768 + 512 + tid];
    float4 qv = reinterpret_cast<const float4*>(g_qb)[tid];
    float4 w  = reinterpret_cast<const float4*>(w2)[tid];
    float acc = fmaxf(qv.x + a.x + rr.x + b.x, 0.f) * w.x
              + fmaxf(qv.y + a.y + rr.y + b.y, 0.f) * w.y
              + fmaxf(qv.z + a.z + rr.z + b.z, 0.f) * w.z
              + fmaxf(qv.w + a.w + rr.w + b.w, 0.f) * w.w;
#pragma unroll
    for (int o = 16; o; o >>= 1) acc += __shfl_xor_sync(0xffffffffu, acc, o);
    __shared__ float sred[8];
    if ((tid & 31) == 0) sred[tid >> 5] = acc;
    __syncthreads();
    if (tid == 0) {
        float s = 0.f;
#pragma unroll
        for (int wdx = 0; wdx < 8; wdx++) s += sred[wdx];
        g_y[e] = s + b2[0] + gumbel_noise(e);
    }
}

__device__ __forceinline__ unsigned f2key(float v) {
    unsigned b = __float_as_uint(v);
    return (b & 0x80000000u) ? ~b : (b | 0x80000000u);
}

__global__ void topk_kernel(int n, int K) {
    __shared__ unsigned hist[256];
    __shared__ unsigned s_prefix;
    __shared__ int s_krem;
    __shared__ int s_cnt;
    int tid = threadIdx.x;
    if (tid == 0) { s_prefix = 0; s_krem = K; s_cnt = 0; }
    __syncthreads();
    for (int pass = 3; pass >= 0; pass--) {
        int shift = pass * 8;
        if (tid < 256) hist[tid] = 0;
        __syncthreads();
        unsigned prefix = s_prefix;
        for (int i = tid; i < n; i += blockDim.x) {
            unsigned key = f2key(g_y[i]);
            bool match = (pass == 3) || ((key >> (shift + 8)) == (prefix >> (shift + 8)));
            if (match) atomicAdd(&hist[(key >> shift) & 255], 1u);
        }
        __syncthreads();
        if (tid == 0) {
            int krem = s_krem;
            unsigned cum = 0;
            int b = 255;
            for (; b >= 0; b--) {
                if (cum + hist[b] >= (unsigned)krem) break;
                cum += hist[b];
            }
            if (b < 0) b = 0;
            s_prefix = prefix | ((unsigned)b << shift);
            s_krem = krem - (int)cum;
        }
        __syncthreads();
    }
    unsigned T = s_prefix;
    int rem = s_krem;
    for (int i = tid; i < n; i += blockDim.x) {
        if (f2key(g_y[i]) == T) {
            int p = atomicAdd(&s_cnt, 1);
            if (p < MAX_TIES) g_tie[p] = i;
        }
    }
    __syncthreads();
    if (tid == 0) {
        int c = s_cnt < MAX_TIES ? s_cnt : MAX_TIES;
        for (int a = 1; a < c; a++) {
            int v = g_tie[a];
            int b = a - 1;
            while (b >= 0 && g_tie[b] > v) { g_tie[b + 1] = g_tie[b]; b--; }
            g_tie[b + 1] = v;
        }
        if (rem > c) rem = c;
        if (rem < 0) rem = 0;
        g_T = T;
        g_rem = rem;
    }
}

__global__ void output_kernel(float* __restrict__ out, int n) {
    int i = blockIdx.x * blockDim.x + threadIdx.x;
    if (i >= n) return;
    unsigned key = f2key(g_y[i]);
    float o = 0.f;
    unsigned T = g_T;
    if (key > T) o = 1.f;
    else if (key == T) {
        int rem = g_rem;
        for (int t = 0; t < rem; t++)
            if (g_tie[t] == i) { o = 1.f; break; }
    }
    out[i] = o;
}

// ----------------------------------------------------------------------------
// Host-side helpers
// ----------------------------------------------------------------------------
static void split_a(const float* A, int lda, int M, int K, int K64, int KP, __nv_bfloat16* out) {
    long long total = (long long)M * K64;
    int blocks = (int)((total + 255) / 256);
    split_a_kernel<<<blocks, 256>>>(A, lda, M, K, K64, KP, out);
}
static void split_b(const float* W, int ldw, int K, int N, int K64, int KP, __nv_bfloat16* out) {
    dim3 grid((N + 31) / 32, (K64 + 31) / 32);
    split_b_kernel<<<grid, dim3(32, 8)>>>(W, ldw, K, N, K64, KP, out);
}
static void gemm(const __nv_bfloat16* A, const __nv_bfloat16* B, float* C, int ldc,
                 int M, int N, int KP, const float* bias, int relu) {
    dim3 grid(N / BN, M / BM);
    gemm_mma<<<grid, 128, GSMEM>>>(A, B, C, ldc, KP, bias, relu);
}

extern "C" void kernel_launch(void* const* d_in, const int* in_sizes, int n_in,
                              void* d_out, int out_size)
{
    cudaFuncSetAttribute(gemm_mma, cudaFuncAttributeMaxDynamicSharedMemorySize, GSMEM);

    const int* h_id = (const int*)d_in[0];
    const int* t_id = (const int*)d_in[1];
    const int* r_id = (const int*)d_in[2];
    const int s = (n_in >= 25) ? 1 : 0;
    const int b0 = 3 + s;
    const float* q_emb   = (const float*)d_in[b0 + 0];
    const float* entity  = (const float*)d_in[b0 + 1];
    const float* rel     = (const float*)d_in[b0 + 2];
    const float* topic   = (const float*)d_in[b0 + 3];
    const float* nontext = (const float*)d_in[b0 + 4];
    const float* wself1  = (const float*)d_in[b0 + 5];
    const float* bself1  = (const float*)d_in[b0 + 6];
    const float* wmsg1   = (const float*)d_in[b0 + 7];
    const float* bmsg1   = (const float*)d_in[b0 + 8];
    const float* wself2  = (const float*)d_in[b0 + 9];
    const float* bself2  = (const float*)d_in[b0 + 10];
    const float* wmsg2   = (const float*)d_in[b0 + 11];
    const float* bmsg2   = (const float*)d_in[b0 + 12];
    const float* revw1   = (const float*)d_in[b0 + 13];
    const float* revb1   = (const float*)d_in[b0 + 14];
    const float* revw2   = (const float*)d_in[b0 + 15];
    const float* revb2   = (const float*)d_in[b0 + 16];
    const float* predw1  = (const float*)d_in[b0 + 17];
    const float* predb1  = (const float*)d_in[b0 + 18];
    const float* predw2  = (const float*)d_in[b0 + 19];
    const float* predb2  = (const float*)d_in[b0 + 20];

    const int E       = in_sizes[0];
    const int n_text  = in_sizes[b0 + 1] / EMB;
    const int n_rel   = in_sizes[b0 + 2] / EMB;
    const int n_nodes = in_sizes[b0 + 3] / 2;
    const int d0      = in_sizes[b0 + 5] / EMB;   // 1026
    const int E2      = 2 * E;
    if (n_nodes > MAXN || E2 > MAXE2 || n_rel > RELSLOT) return;

    float *p_h0, *p_relcat, *p_revh, *p_Q, *p_P, *p_agg, *p_hnode, *p_AB, *p_deg, *p_bias2;
    __nv_bfloat16 *p_sa, *p_sarel, *p_sb;
    cudaGetSymbolAddress((void**)&p_h0,     g_h0);
    cudaGetSymbolAddress((void**)&p_relcat, g_relcat);
    cudaGetSymbolAddress((void**)&p_revh,   g_revh);
    cudaGetSymbolAddress((void**)&p_Q,      g_Q);
    cudaGetSymbolAddress((void**)&p_P,      g_P);
    cudaGetSymbolAddress((void**)&p_agg,    g_agg);
    cudaGetSymbolAddress((void**)&p_hnode,  g_hnode);
    cudaGetSymbolAddress((void**)&p_AB,     g_AB);
    cudaGetSymbolAddress((void**)&p_deg,    g_deg);
    cudaGetSymbolAddress((void**)&p_bias2,  g_bias2);
    cudaGetSymbolAddress((void**)&p_sa,     g_sa);
    cudaGetSymbolAddress((void**)&p_sarel,  g_sarel);
    cudaGetSymbolAddress((void**)&p_sb,     g_sb);

    // ---- prep ----
    zero_kernel<<<1024, 256>>>((float4*)p_agg, MAXN * EMB / 4);
    zero_kernel<<<32, 256>>>((float4*)p_deg, MAXN / 4);
    build_h0_kernel<<<n_nodes, 256>>>(entity, nontext, topic, n_text, n_nodes);
    relcat_kernel<<<(RELSLOT * EMB + 255) / 256, 256>>>(rel, n_rel);
    deg_kernel<<<(E2 + 255) / 256, 256>>>(h_id, t_id, E);

    // ---- reverse-relation MLP ----
    split_a(p_relcat, EMB, RELSLOT, EMB, 1024, 3072, p_sa);
    split_b(revw1, EMB, EMB, EMB, 1024, 3072, p_sb);
    gemm(p_sa, p_sb, p_revh, EMB, RELSLOT, EMB, 3072, revb1, 1);
    split_a(p_revh, EMB, RELSLOT, EMB, 1024, 3072, p_sa);
    split_b(revw2, EMB, EMB, EMB, 1024, 3072, p_sb);
    gemm(p_sa, p_sb, p_relcat + (size_t)RELSLOT * EMB, EMB, RELSLOT, EMB, 3072, revb2, 0);

    // relation A' table (fwd+rev)
    split_a(p_relcat, EMB, 2 * RELSLOT, EMB, 1024, 3072, p_sarel);

    // ---- merged relation projections: Q = [Q1|Q2|Qpred], N=3072 ----
    split_b(wmsg1 + (size_t)d0 * EMB, EMB, EMB, EMB, 1024, 3072, p_sb);
    split_b(wmsg2 + (size_t)EMB * EMB, EMB, EMB, EMB, 1024, 3072, p_sb + (size_t)1024 * 3072);
    split_b(predw1 + (size_t)3 * EMB * EMB, EMB, EMB, EMB, 1024, 3072, p_sb + (size_t)2048 * 3072);
    gemm(p_sarel, p_sb, p_Q, 3072, 2 * RELSLOT, 3072, 3072, nullptr, 0);

    // ---- SAGE layer 1: merged [Pmsg|Pself], N=2048 ----
    split_a(p_h0, D0PAD, MAXN, D0PAD, 1088, 3264, p_sa);
    split_b(wmsg1, EMB, d0, EMB, 1088, 3264, p_sb);
    split_b(wself1, EMB, d0, EMB, 1088, 3264, p_sb + (size_t)1024 * 3264);
    concat_bias_kernel<<<8, 256>>>(bmsg1, bself1);
    gemm(p_sa, p_sb, p_P, 2048, MAXN, 2048, 3264, p_bias2, 0);
    edge_msg_kernel<<<E2, 256>>>(h_id, t_id, r_id, E, 0);
    node_update_kernel<<<(n_nodes * (EMB / 4) + 255) / 256, 256>>>(n_nodes, 0);

    // ---- SAGE layer 2 ----
    zero_kernel<<<1024, 256>>>((float4*)p_agg, MAXN * EMB / 4);
    split_a(p_hnode, 2 * EMB, MAXN, EMB, 1024, 3072, p_sa);   // h1
    split_b(wmsg2, EMB, EMB, EMB, 1024, 3072, p_sb);
    split_b(wself2, EMB, EMB, EMB, 1024, 3072, p_sb + (size_t)1024 * 3072);
    concat_bias_kernel<<<8, 256>>>(bmsg2, bself2);
    gemm(p_sa, p_sb, p_P, 2048, MAXN, 2048, 3072, p_bias2, 0);
    edge_msg_kernel<<<E2, 256>>>(h_id, t_id, r_id, E, 256);
    node_update_kernel<<<(n_nodes * (EMB / 4) + 255) / 256, 256>>>(n_nodes, 1);

    // ---- predictor projections: merged [Asrc|Bdst], N=2048 ----
    split_a(p_hnode, 2 * EMB, MAXN, 2 * EMB, 2048, 6144, p_sa);
    split_b(predw1 + (size_t)EMB * EMB, EMB, 2 * EMB, EMB, 2048, 6144, p_sb);
    split_b(predw1 + (size_t)4 * EMB * EMB, EMB, 2 * EMB, EMB, 2048, 6144, p_sb + (size_t)1024 * 6144);
    gemm(p_sa, p_sb, p_AB, 2048, MAXN, 2048, 6144, nullptr, 0);
    qb_kernel<<<4, 256>>>(q_emb, predw1, predb1);

    // ---- edge logits + gumbel + exact top-K ----
    edge_logits_kernel<<<E2, 256>>>(h_id, t_id, r_id, E, predw2, predb2);
    topk_kernel<<<1, 1024>>>(E2, 512);
    output_kernel<<<(E2 + 255) / 256, 256>>>((float*)d_out, E2);
}

// round 16
// speedup vs baseline: 3.0609x; 1.0572x over previous
#include <cuda_runtime.h>
#include <cuda_bf16.h>
#include <math.h>
#include <stdint.h>

#define EMB 1024
#define D0PAD 1032
#define MAXN 22016
#define RELSLOT 2048
#define MAXE2 40960
#define MAX_TIES 1024
#define KPMAX 6144

// ---------------- mma.sync GEMM tile config ----------------
#define BM 128
#define BN 128
#define BK 64                  // bf16 per K-chunk
#define STAGE_BYTES 32768      // A 16KB + B 16KB
#define NSTAGE 3
#define GSMEM (NSTAGE * STAGE_BYTES)

// ----------------------------------------------------------------------------
// Static scratch
// ----------------------------------------------------------------------------
__device__ float g_h0[(size_t)MAXN * D0PAD];
__device__ float g_relcat[(size_t)2 * RELSLOT * EMB];
__device__ float g_revh[(size_t)RELSLOT * EMB];
__device__ float g_Q[(size_t)2 * RELSLOT * 3072];   // merged [Q1|Q2|Qpred], ldc=3072
__device__ float g_P[(size_t)MAXN * 2 * EMB];       // merged [Pmsg|Pself], ldc=2048
__device__ float g_agg[(size_t)MAXN * EMB];
__device__ float g_hnode[(size_t)MAXN * 2 * EMB];   // [h1 | h2]
__device__ float g_AB[(size_t)MAXN * 2 * EMB];      // [Asrc | Bdst], ldc=2048
__device__ float g_deg[MAXN];
__device__ float g_qb[EMB];
__device__ float g_bias2a[2 * EMB];
__device__ float g_bias2b[2 * EMB];
__device__ float g_y[MAXE2];
__device__ unsigned g_T;
__device__ int g_rem;
__device__ int g_tie[MAX_TIES];
// bf16 split operand buffers
__device__ __nv_bfloat16 g_sa[(size_t)MAXN * KPMAX];            // A' (h0 / predictor)
__device__ __nv_bfloat16 g_sa2[(size_t)MAXN * 3072];            // A' layer2 (h1)
__device__ __nv_bfloat16 g_sarel[(size_t)2 * RELSLOT * 3072];   // relcat A'
__device__ __nv_bfloat16 g_sb[(size_t)4096 * KPMAX];            // B' (multi-block)

// ----------------------------------------------------------------------------
// helpers
// ----------------------------------------------------------------------------
__device__ __forceinline__ uint32_t smem_u32(const void* p) {
    uint32_t a;
    asm("{ .reg .u64 t; cvta.to.shared.u64 t, %1; cvt.u32.u64 %0, t; }" : "=r"(a) : "l"(p));
    return a;
}
// 128B rows, 8x16B chunks, XOR swizzle (chunk ^ (row&7)): conflict-free for
// cp.async store phases and all ldmatrix phases.
__device__ __forceinline__ int sw128(int row, int chk) {
    return row * 128 + (((chk) ^ (row & 7)) << 4);
}
__device__ __forceinline__ void cp16(uint32_t sa, const void* gp) {
    uint64_t ga;
    asm("cvta.to.global.u64 %0, %1;" : "=l"(ga) : "l"(gp));
    asm volatile("cp.async.cg.shared.global [%0], [%1], 16;" :: "r"(sa), "l"(ga) : "memory");
}
__device__ __forceinline__ unsigned short bfb(float x) {
    __nv_bfloat16 h = __float2bfloat16(x);
    return *reinterpret_cast<unsigned short*>(&h);
}
__device__ __forceinline__ float bff(unsigned short u) {
    __nv_bfloat16 h = *reinterpret_cast<__nv_bfloat16*>(&u);
    return __bfloat162float(h);
}

// ----------------------------------------------------------------------------
// Batched bf16 split GEMM: mma.sync.m16n8k16 + ldmatrix + cp.async 3-stage.
// One launch can carry TWO independent GEMMs (flat 1-D grid split at nb0).
// 128 threads = 4 warps (2m x 2n), warp tile 64x64, CTA tile 128x128.
// ----------------------------------------------------------------------------
struct GDesc {
    const __nv_bfloat16* A;
    const __nv_bfloat16* B;
    float* C;
    const float* bias;
    int ldc, KP, nbx, relu;
};

__global__ __launch_bounds__(128, 2)
void gemm_mma(GDesc d0, GDesc d1, int nb0)
{
    extern __shared__ __align__(1024) char smem[];
    GDesc d;
    int rb;
    if ((int)blockIdx.x < nb0) { d = d0; rb = blockIdx.x; }
    else                       { d = d1; rb = blockIdx.x - nb0; }
    const int bn0 = (rb % d.nbx) * BN;
    const int bm0 = (rb / d.nbx) * BM;

    const int tid  = threadIdx.x;
    const int wid  = tid >> 5;
    const int lane = tid & 31;
    const int wm0 = (wid & 1) * 64;
    const int wn0 = (wid >> 1) * 64;
    const uint32_t sbase = smem_u32(smem);
    const int KP = d.KP;

    // ldmatrix per-lane address components
    const int midx = lane >> 3, mr = lane & 7;
    int aRowB[4], aRx[4];
#pragma unroll
    for (int ma = 0; ma < 4; ma++) {
        int r = wm0 + ma * 16 + (midx & 1) * 8 + mr;
        aRowB[ma] = r * 128; aRx[ma] = r & 7;
    }
    const int aCs = midx >> 1;
    int bRowB[4], bRx[4];
#pragma unroll
    for (int p = 0; p < 4; p++) {
        int r = wn0 + p * 16 + (midx >> 1) * 8 + mr;
        bRowB[p] = r * 128; bRx[p] = r & 7;
    }
    const int bCs = midx & 1;

    float c[4][8][4];
#pragma unroll
    for (int ma = 0; ma < 4; ma++)
#pragma unroll
        for (int na = 0; na < 8; na++)
#pragma unroll
            for (int i = 0; i < 4; i++) c[ma][na][i] = 0.f;

    const int nchunk = KP >> 6;

    auto issue_stage = [&](int ck) {
        if (ck < nchunk) {
            const int kc = ck * BK;
            const uint32_t st = sbase + (ck % NSTAGE) * STAGE_BYTES;
#pragma unroll
            for (int i = 0; i < 8; i++) {
                const int u = tid + 128 * i;
                const int row = u >> 3, chk = u & 7;
                cp16(st + sw128(row, chk),         d.A + (size_t)(bm0 + row) * KP + kc + chk * 8);
                cp16(st + 16384 + sw128(row, chk), d.B + (size_t)(bn0 + row) * KP + kc + chk * 8);
            }
        }
        asm volatile("cp.async.commit_group;" ::: "memory");
    };

    issue_stage(0);
    issue_stage(1);

    for (int ck = 0; ck < nchunk; ck++) {
        asm volatile("cp.async.wait_group 1;" ::: "memory");
        __syncthreads();
        issue_stage(ck + 2);

        const uint32_t stA = sbase + (ck % NSTAGE) * STAGE_BYTES;
        const uint32_t stB = stA + 16384;
#pragma unroll
        for (int s = 0; s < 4; s++) {
            uint32_t af[4][4], bf[8][2];
#pragma unroll
            for (int ma = 0; ma < 4; ma++) {
                uint32_t ad = stA + aRowB[ma] + ((((s << 1) + aCs) ^ aRx[ma]) << 4);
                asm volatile("ldmatrix.sync.aligned.m8n8.x4.shared.b16 {%0,%1,%2,%3}, [%4];"
                             : "=r"(af[ma][0]), "=r"(af[ma][1]), "=r"(af[ma][2]), "=r"(af[ma][3])
                             : "r"(ad));
            }
#pragma unroll
            for (int p = 0; p < 4; p++) {
                uint32_t bd = stB + bRowB[p] + ((((s << 1) + bCs) ^ bRx[p]) << 4);
                asm volatile("ldmatrix.sync.aligned.m8n8.x4.shared.b16 {%0,%1,%2,%3}, [%4];"
                             : "=r"(bf[2 * p][0]), "=r"(bf[2 * p][1]),
                               "=r"(bf[2 * p + 1][0]), "=r"(bf[2 * p + 1][1])
                             : "r"(bd));
            }
#pragma unroll
            for (int ma = 0; ma < 4; ma++)
#pragma unroll
                for (int na = 0; na < 8; na++)
                    asm volatile(
                        "mma.sync.aligned.m16n8k16.row.col.f32.bf16.bf16.f32 "
                        "{%0,%1,%2,%3}, {%4,%5,%6,%7}, {%8,%9}, {%0,%1,%2,%3};"
                        : "+f"(c[ma][na][0]), "+f"(c[ma][na][1]),
                          "+f"(c[ma][na][2]), "+f"(c[ma][na][3])
                        : "r"(af[ma][0]), "r"(af[ma][1]), "r"(af[ma][2]), "r"(af[ma][3]),
                          "r"(bf[na][0]), "r"(bf[na][1]));
        }
    }

    // epilogue
    const int g = lane >> 2;
    const int q = lane & 3;
#pragma unroll
    for (int ma = 0; ma < 4; ma++) {
        const int row = bm0 + wm0 + ma * 16 + g;
#pragma unroll
        for (int na = 0; na < 8; na++) {
            const int col = bn0 + wn0 + na * 8 + q * 2;
            float v0 = c[ma][na][0], v1 = c[ma][na][1];
            float v2 = c[ma][na][2], v3 = c[ma][na][3];
            if (d.bias) {
                float bx = d.bias[col], by = d.bias[col + 1];
                v0 += bx; v1 += by; v2 += bx; v3 += by;
            }
            if (d.relu) {
                v0 = fmaxf(v0, 0.f); v1 = fmaxf(v1, 0.f);
                v2 = fmaxf(v2, 0.f); v3 = fmaxf(v3, 0.f);
            }
            *reinterpret_cast<float2*>(d.C + (size_t)row * d.ldc + col) = make_float2(v0, v1);
            *reinterpret_cast<float2*>(d.C + (size_t)(row + 8) * d.ldc + col) = make_float2(v2, v3);
        }
    }
}

// ----------------------------------------------------------------------------
// Split kernels: fp32 -> bf16 triple layout
// A' = [hi | lo | hi] along K ; B' = [hi | hi | lo] (with transpose)
// ----------------------------------------------------------------------------
__global__ void split_a_kernel(const float* __restrict__ A, int lda, int M, int K,
                               int K64, int KP, __nv_bfloat16* __restrict__ out)
{
    long long idx = (long long)blockIdx.x * blockDim.x + threadIdx.x;
    long long total = (long long)M * K64;
    if (idx >= total) return;
    int row = (int)(idx / K64);
    int kk = (int)(idx % K64);
    float v = (kk < K) ? A[(size_t)row * lda + kk] : 0.f;
    __nv_bfloat16 hi = __float2bfloat16(v);
    __nv_bfloat16 lo = __float2bfloat16(v - __bfloat162float(hi));
    __nv_bfloat16* o = out + (size_t)row * KP;
    o[kk] = hi;
    o[K64 + kk] = lo;
    o[2 * K64 + kk] = hi;
}

__global__ void split_b_kernel(const float* __restrict__ W, int ldw, int K, int N,
                               int K64, int KP, __nv_bfloat16* __restrict__ out)
{
    __shared__ float t[32][33];
    int kk0 = blockIdx.y * 32, n0 = blockIdx.x * 32;
    int tx = threadIdx.x, ty = threadIdx.y;   // 32x8
#pragma unroll
    for (int j = 0; j < 32; j += 8) {
        int kk = kk0 + ty + j, n = n0 + tx;
        t[ty + j][tx] = (kk < K && n < N) ? W[(size_t)kk * ldw + n] : 0.f;
    }
    __syncthreads();
#pragma unroll
    for (int j = 0; j < 32; j += 8) {
        int n = n0 + ty + j, kk = kk0 + tx;
        if (n < N && kk < K64) {
            float v = t[tx][ty + j];
            __nv_bfloat16 hi = __float2bfloat16(v);
            __nv_bfloat16 lo = __float2bfloat16(v - __bfloat162float(hi));
            __nv_bfloat16* o = out + (size_t)n * KP;
            o[kk] = hi;
            o[K64 + kk] = hi;
            o[2 * K64 + kk] = lo;
        }
    }
}

// ----------------------------------------------------------------------------
// Non-GEMM kernels
// ----------------------------------------------------------------------------
__global__ void zero_kernel(float4* p, int n4) {
    int i = blockIdx.x * blockDim.x + threadIdx.x;
    int stride = gridDim.x * blockDim.x;
    float4 z = make_float4(0.f, 0.f, 0.f, 0.f);
    for (; i < n4; i += stride) p[i] = z;
}

__global__ void build_h0_kernel(const float* __restrict__ entity,
                                const float* __restrict__ nontext,
                                const float* __restrict__ topic,
                                int n_text, int n_nodes)
{
    int n = blockIdx.x;
    if (n >= n_nodes) return;
    float* dst = g_h0 + (size_t)n * D0PAD;
    const float* src = (n < n_text) ? (entity + (size_t)n * EMB) : nontext;
    for (int j = threadIdx.x; j < D0PAD; j += blockDim.x) {
        float v;
        if (j < EMB)          v = src[j];
        else if (j < EMB + 2) v = topic[(size_t)n * 2 + (j - EMB)];
        else                  v = 0.f;
        dst[j] = v;
    }
}

__global__ void relcat_kernel(const float* __restrict__ rel, int n_rel) {
    int i = blockIdx.x * blockDim.x + threadIdx.x;
    if (i >= RELSLOT * EMB) return;
    int row = i / EMB;
    g_relcat[i] = (row < n_rel) ? rel[i] : 0.f;
}

__global__ void deg_kernel(const int* __restrict__ h_id, const int* __restrict__ t_id, int E) {
    int i = blockIdx.x * blockDim.x + threadIdx.x;
    if (i >= 2 * E) return;
    int dst = (i < E) ? t_id[i] : h_id[i - E];
    atomicAdd(&g_deg[dst], 1.0f);
}

__global__ void concat_bias_kernel(const float* __restrict__ b1, const float* __restrict__ b2,
                                   float* __restrict__ dst) {
    int i = blockIdx.x * blockDim.x + threadIdx.x;
    if (i < EMB) dst[i] = b1[i];
    else if (i < 2 * EMB) dst[i] = b2[i - EMB];
}

// msg = relu(P[src,0:1024] + Q[rel, qoff:qoff+1024]); agg[dst] += msg
__global__ void edge_msg_kernel(const int* __restrict__ h_id, const int* __restrict__ t_id,
                                const int* __restrict__ r_id, int E, int qoff4)
{
    int e = blockIdx.x;
    int src, dst, rel;
    if (e < E) { src = h_id[e]; dst = t_id[e]; rel = r_id[e]; }
    else { int e2 = e - E; src = t_id[e2]; dst = h_id[e2]; rel = RELSLOT + r_id[e2]; }
    int j = threadIdx.x;
    const float4 pv = reinterpret_cast<const float4*>(g_P)[(size_t)src * 512 + j];
    const float4 qv = reinterpret_cast<const float4*>(g_Q)[(size_t)rel * 768 + qoff4 + j];
    float4 m;
    m.x = fmaxf(pv.x + qv.x, 0.f);
    m.y = fmaxf(pv.y + qv.y, 0.f);
    m.z = fmaxf(pv.z + qv.z, 0.f);
    m.w = fmaxf(pv.w + qv.w, 0.f);
    atomicAdd(reinterpret_cast<float4*>(g_agg + (size_t)dst * EMB) + j, m);
}

// h = relu(P[:,1024:2048] + agg/max(deg,1)) -> hnode; also emit bf16 splits for
// the downstream GEMMs (layer==0: g_sa2 [KP=3072] + g_sa cols 0.. [KP=6144],
// and re-zero agg; layer==1: g_sa cols 1024.. [KP=6144]).
__global__ void node_update_kernel(int n_nodes, int layer) {
    int i = blockIdx.x * blockDim.x + threadIdx.x;
    int total = n_nodes * (EMB / 4);
    if (i >= total) return;
    int n = i >> 8;
    int j4 = i & 255;
    float inv = 1.0f / fmaxf(g_deg[n], 1.0f);
    float4 ps = reinterpret_cast<const float4*>(g_P)[(size_t)n * 512 + 256 + j4];
    float4 ag = reinterpret_cast<const float4*>(g_agg + (size_t)n * EMB)[j4];
    float4 v;
    v.x = fmaxf(ps.x + ag.x * inv, 0.f);
    v.y = fmaxf(ps.y + ag.y * inv, 0.f);
    v.z = fmaxf(ps.z + ag.z * inv, 0.f);
    v.w = fmaxf(ps.w + ag.w * inv, 0.f);
    reinterpret_cast<float4*>(g_hnode + (size_t)n * 2 * EMB + (size_t)layer * EMB)[j4] = v;

    ushort4 hi4 = make_ushort4(bfb(v.x), bfb(v.y), bfb(v.z), bfb(v.w));
    ushort4 lo4 = make_ushort4(bfb(v.x - bff(hi4.x)), bfb(v.y - bff(hi4.y)),
                               bfb(v.z - bff(hi4.z)), bfb(v.w - bff(hi4.w)));
    const int k = j4 * 4;
    if (layer == 0) {
        // layer-2 GEMM operand (KP=3072, K64=1024)
        __nv_bfloat16* o2 = g_sa2 + (size_t)n * 3072;
        *reinterpret_cast<ushort4*>(o2 + k)        = hi4;
        *reinterpret_cast<ushort4*>(o2 + 1024 + k) = lo4;
        *reinterpret_cast<ushort4*>(o2 + 2048 + k) = hi4;
        // predictor GEMM operand (KP=6144, K64=2048), h1 part
        __nv_bfloat16* oa = g_sa + (size_t)n * 6144;
        *reinterpret_cast<ushort4*>(oa + k)        = hi4;
        *reinterpret_cast<ushort4*>(oa + 2048 + k) = lo4;
        *reinterpret_cast<ushort4*>(oa + 4096 + k) = hi4;
        // re-zero agg for layer 2
        reinterpret_cast<float4*>(g_agg + (size_t)n * EMB)[j4] = make_float4(0.f, 0.f, 0.f, 0.f);
    } else {
        // predictor GEMM operand, h2 part
        __nv_bfloat16* oa = g_sa + (size_t)n * 6144;
        *reinterpret_cast<ushort4*>(oa + 1024 + k) = hi4;
        *reinterpret_cast<ushort4*>(oa + 3072 + k) = lo4;
        *reinterpret_cast<ushort4*>(oa + 5120 + k) = hi4;
    }
}

__global__ void qb_kernel(const float* __restrict__ q, const float* __restrict__ predw1,
                          const float* __restrict__ predb1)
{
    int j = blockIdx.x * blockDim.x + threadIdx.x;
    if (j >= EMB) return;
    float acc = 0.f;
    for (int k = 0; k < EMB; k++) acc += q[k] * predw1[(size_t)k * EMB + j];
    g_qb[j] = acc + predb1[j];
}

__device__ __forceinline__ void threefry2x32(unsigned k0, unsigned k1,
                                             unsigned& x0, unsigned& x1)
{
    unsigned ks2 = k0 ^ k1 ^ 0x1BD11BDAu;
    x0 += k0; x1 += k1;
#define TFR(r) { x0 += x1; x1 = (x1 << (r)) | (x1 >> (32 - (r))); x1 ^= x0; }
    TFR(13) TFR(15) TFR(26) TFR(6)
    x0 += k1;  x1 += ks2 + 1u;
    TFR(17) TFR(29) TFR(16) TFR(24)
    x0 += ks2; x1 += k0 + 2u;
    TFR(13) TFR(15) TFR(26) TFR(6)
    x0 += k0;  x1 += k1 + 3u;
    TFR(17) TFR(29) TFR(16) TFR(24)
    x0 += k1;  x1 += ks2 + 4u;
    TFR(13) TFR(15) TFR(26) TFR(6)
    x0 += ks2; x1 += k0 + 5u;
#undef TFR
}

__device__ __forceinline__ float gumbel_noise(int e) {
    unsigned x0 = 0u;
    unsigned x1 = (unsigned)e;
    threefry2x32(0u, 42u, x0, x1);
    unsigned bits = x0 ^ x1;
    float f = __uint_as_float((bits >> 9) | 0x3f800000u) - 1.0f;
    float u = fmaxf(1e-10f, f + 1e-10f);
    return -logf(-logf(u));
}

__global__ void edge_logits_kernel(const int* __restrict__ h_id, const int* __restrict__ t_id,
                                   const int* __restrict__ r_id, int E,
                                   const float* __restrict__ w2, const float* __restrict__ b2)
{
    int e = blockIdx.x;
    int src, dst, rel;
    if (e < E) { src = h_id[e]; dst = t_id[e]; rel = r_id[e]; }
    else { int e2 = e - E; src = t_id[e2]; dst = h_id[e2]; rel = RELSLOT + r_id[e2]; }
    int tid = threadIdx.x;
    float4 a  = reinterpret_cast<const float4*>(g_AB)[(size_t)src * 512 + tid];
    float4 b  = reinterpret_cast<const float4*>(g_AB)[(size_t)dst * 512 + 256 + tid];
    float4 rr = reinterpret_cast<const float4*>(g_Q)[(size_t)rel * 768 + 512 + tid];
    float4 qv = reinterpret_cast<const float4*>(g_qb)[tid];
    float4 w  = reinterpret_cast<const float4*>(w2)[tid];
    float acc = fmaxf(qv.x + a.x + rr.x + b.x, 0.f) * w.x
              + fmaxf(qv.y + a.y + rr.y + b.y, 0.f) * w.y
              + fmaxf(qv.z + a.z + rr.z + b.z, 0.f) * w.z
              + fmaxf(qv.w + a.w + rr.w + b.w, 0.f) * w.w;
#pragma unroll
    for (int o = 16; o; o >>= 1) acc += __shfl_xor_sync(0xffffffffu, acc, o);
    __shared__ float sred[8];
    if ((tid & 31) == 0) sred[tid >> 5] = acc;
    __syncthreads();
    if (tid == 0) {
        float s = 0.f;
#pragma unroll
        for (int wdx = 0; wdx < 8; wdx++) s += sred[wdx];
        g_y[e] = s + b2[0] + gumbel_noise(e);
    }
}

__device__ __forceinline__ unsigned f2key(float v) {
    unsigned b = __float_as_uint(v);
    return (b & 0x80000000u) ? ~b : (b | 0x80000000u);
}

__global__ void topk_kernel(int n, int K) {
    __shared__ unsigned hist[256];
    __shared__ unsigned s_prefix;
    __shared__ int s_krem;
    __shared__ int s_cnt;
    int tid = threadIdx.x;
    if (tid == 0) { s_prefix = 0; s_krem = K; s_cnt = 0; }
    __syncthreads();
    for (int pass = 3; pass >= 0; pass--) {
        int shift = pass * 8;
        if (tid < 256) hist[tid] = 0;
        __syncthreads();
        unsigned prefix = s_prefix;
        for (int i = tid; i < n; i += blockDim.x) {
            unsigned key = f2key(g_y[i]);
            bool match = (pass == 3) || ((key >> (shift + 8)) == (prefix >> (shift + 8)));
            if (match) atomicAdd(&hist[(key >> shift) & 255], 1u);
        }
        __syncthreads();
        if (tid == 0) {
            int krem = s_krem;
            unsigned cum = 0;
            int b = 255;
            for (; b >= 0; b--) {
                if (cum + hist[b] >= (unsigned)krem) break;
                cum += hist[b];
            }
            if (b < 0) b = 0;
            s_prefix = prefix | ((unsigned)b << shift);
            s_krem = krem - (int)cum;
        }
        __syncthreads();
    }
    unsigned T = s_prefix;
    int rem = s_krem;
    for (int i = tid; i < n; i += blockDim.x) {
        if (f2key(g_y[i]) == T) {
            int p = atomicAdd(&s_cnt, 1);
            if (p < MAX_TIES) g_tie[p] = i;
        }
    }
    __syncthreads();
    if (tid == 0) {
        int c = s_cnt < MAX_TIES ? s_cnt : MAX_TIES;
        for (int a = 1; a < c; a++) {
            int v = g_tie[a];
            int b = a - 1;
            while (b >= 0 && g_tie[b] > v) { g_tie[b + 1] = g_tie[b]; b--; }
            g_tie[b + 1] = v;
        }
        if (rem > c) rem = c;
        if (rem < 0) rem = 0;
        g_T = T;
        g_rem = rem;
    }
}

__global__ void output_kernel(float* __restrict__ out, int n) {
    int i = blockIdx.x * blockDim.x + threadIdx.x;
    if (i >= n) return;
    unsigned key = f2key(g_y[i]);
    float o = 0.f;
    unsigned T = g_T;
    if (key > T) o = 1.f;
    else if (key == T) {
        int rem = g_rem;
        for (int t = 0; t < rem; t++)
            if (g_tie[t] == i) { o = 1.f; break; }
    }
    out[i] = o;
}

// ----------------------------------------------------------------------------
// Host-side helpers
// ----------------------------------------------------------------------------
static void split_a(const float* A, int lda, int M, int K, int K64, int KP, __nv_bfloat16* out) {
    long long total = (long long)M * K64;
    int blocks = (int)((total + 255) / 256);
    split_a_kernel<<<blocks, 256>>>(A, lda, M, K, K64, KP, out);
}
static void split_b(const float* W, int ldw, int K, int N, int K64, int KP, __nv_bfloat16* out) {
    dim3 grid((N + 31) / 32, (K64 + 31) / 32);
    split_b_kernel<<<grid, dim3(32, 8)>>>(W, ldw, K, N, K64, KP, out);
}
static GDesc mk(const __nv_bfloat16* A, const __nv_bfloat16* B, float* C,
                int ldc, int N, int KP, const float* bias, int relu) {
    GDesc d; d.A = A; d.B = B; d.C = C; d.bias = bias;
    d.ldc = ldc; d.KP = KP; d.nbx = N / BN; d.relu = relu;
    return d;
}
static void gemm1(GDesc d, int M) {
    int nb = (M / BM) * d.nbx;
    gemm_mma<<<nb, 128, GSMEM>>>(d, d, nb);
}
static void gemm2(GDesc a, int Ma, GDesc b, int Mb) {
    int na = (Ma / BM) * a.nbx;
    int nb = (Mb / BM) * b.nbx;
    gemm_mma<<<na + nb, 128, GSMEM>>>(a, b, na);
}

extern "C" void kernel_launch(void* const* d_in, const int* in_sizes, int n_in,
                              void* d_out, int out_size)
{
    cudaFuncSetAttribute(gemm_mma, cudaFuncAttributeMaxDynamicSharedMemorySize, GSMEM);

    const int* h_id = (const int*)d_in[0];
    const int* t_id = (const int*)d_in[1];
    const int* r_id = (const int*)d_in[2];
    const int s = (n_in >= 25) ? 1 : 0;
    const int b0 = 3 + s;
    const float* q_emb   = (const float*)d_in[b0 + 0];
    const float* entity  = (const float*)d_in[b0 + 1];
    const float* rel     = (const float*)d_in[b0 + 2];
    const float* topic   = (const float*)d_in[b0 + 3];
    const float* nontext = (const float*)d_in[b0 + 4];
    const float* wself1  = (const float*)d_in[b0 + 5];
    const float* bself1  = (const float*)d_in[b0 + 6];
    const float* wmsg1   = (const float*)d_in[b0 + 7];
    const float* bmsg1   = (const float*)d_in[b0 + 8];
    const float* wself2  = (const float*)d_in[b0 + 9];
    const float* bself2  = (const float*)d_in[b0 + 10];
    const float* wmsg2   = (const float*)d_in[b0 + 11];
    const float* bmsg2   = (const float*)d_in[b0 + 12];
    const float* revw1   = (const float*)d_in[b0 + 13];
    const float* revb1   = (const float*)d_in[b0 + 14];
    const float* revw2   = (const float*)d_in[b0 + 15];
    const float* revb2   = (const float*)d_in[b0 + 16];
    const float* predw1  = (const float*)d_in[b0 + 17];
    const float* predb1  = (const float*)d_in[b0 + 18];
    const float* predw2  = (const float*)d_in[b0 + 19];
    const float* predb2  = (const float*)d_in[b0 + 20];

    const int E       = in_sizes[0];
    const int n_text  = in_sizes[b0 + 1] / EMB;
    const int n_rel   = in_sizes[b0 + 2] / EMB;
    const int n_nodes = in_sizes[b0 + 3] / 2;
    const int d0      = in_sizes[b0 + 5] / EMB;   // 1026
    const int E2      = 2 * E;
    if (n_nodes > MAXN || E2 > MAXE2 || n_rel > RELSLOT) return;

    float *p_h0, *p_relcat, *p_revh, *p_Q, *p_P, *p_agg, *p_AB, *p_deg, *p_ba, *p_bb;
    __nv_bfloat16 *p_sa, *p_sa2, *p_sarel, *p_sb;
    cudaGetSymbolAddress((void**)&p_h0,     g_h0);
    cudaGetSymbolAddress((void**)&p_relcat, g_relcat);
    cudaGetSymbolAddress((void**)&p_revh,   g_revh);
    cudaGetSymbolAddress((void**)&p_Q,      g_Q);
    cudaGetSymbolAddress((void**)&p_P,      g_P);
    cudaGetSymbolAddress((void**)&p_agg,    g_agg);
    cudaGetSymbolAddress((void**)&p_AB,     g_AB);
    cudaGetSymbolAddress((void**)&p_deg,    g_deg);
    cudaGetSymbolAddress((void**)&p_ba,     g_bias2a);
    cudaGetSymbolAddress((void**)&p_bb,     g_bias2b);
    cudaGetSymbolAddress((void**)&p_sa,     g_sa);
    cudaGetSymbolAddress((void**)&p_sa2,    g_sa2);
    cudaGetSymbolAddress((void**)&p_sarel,  g_sarel);
    cudaGetSymbolAddress((void**)&p_sb,     g_sb);

    // ---- prep ----
    zero_kernel<<<1024, 256>>>((float4*)p_agg, MAXN * EMB / 4);
    zero_kernel<<<32, 256>>>((float4*)p_deg, MAXN / 4);
    build_h0_kernel<<<n_nodes, 256>>>(entity, nontext, topic, n_text, n_nodes);
    relcat_kernel<<<(RELSLOT * EMB + 255) / 256, 256>>>(rel, n_rel);
    deg_kernel<<<(E2 + 255) / 256, 256>>>(h_id, t_id, E);
    concat_bias_kernel<<<8, 256>>>(bmsg1, bself1, p_ba);
    concat_bias_kernel<<<8, 256>>>(bmsg2, bself2, p_bb);
    qb_kernel<<<4, 256>>>(q_emb, predw1, predb1);

    // ---- reverse-relation MLP (serial chain) ----
    split_a(p_relcat, EMB, RELSLOT, EMB, 1024, 3072, p_sa);
    split_b(revw1, EMB, EMB, EMB, 1024, 3072, p_sb);
    gemm1(mk(p_sa, p_sb, p_revh, EMB, EMB, 3072, revb1, 1), RELSLOT);
    split_a(p_revh, EMB, RELSLOT, EMB, 1024, 3072, p_sa);
    split_b(revw2, EMB, EMB, EMB, 1024, 3072, p_sb);
    gemm1(mk(p_sa, p_sb, p_relcat + (size_t)RELSLOT * EMB, EMB, EMB, 3072, revb2, 0), RELSLOT);

    // relation A' table (fwd+rev)
    split_a(p_relcat, EMB, 2 * RELSLOT, EMB, 1024, 3072, p_sarel);

    // ---- batched: P1 (h0 projections) + Q (merged relation projections) ----
    // Q B' = [wmsg1_rel | wmsg2_rel | predw1_rel], N=3072, at p_sb
    split_b(wmsg1 + (size_t)d0 * EMB, EMB, EMB, EMB, 1024, 3072, p_sb);
    split_b(wmsg2 + (size_t)EMB * EMB, EMB, EMB, EMB, 1024, 3072, p_sb + (size_t)1024 * 3072);
    split_b(predw1 + (size_t)3 * EMB * EMB, EMB, EMB, EMB, 1024, 3072, p_sb + (size_t)2048 * 3072);
    // P1 A' (h0) and B' = [wmsg1 | wself1], N=2048, at p_sb + 3072*3072
    __nv_bfloat16* p_sbP = p_sb + (size_t)3072 * 3072;
    split_a(p_h0, D0PAD, MAXN, D0PAD, 1088, 3264, p_sa);
    split_b(wmsg1, EMB, d0, EMB, 1088, 3264, p_sbP);
    split_b(wself1, EMB, d0, EMB, 1088, 3264, p_sbP + (size_t)1024 * 3264);
    gemm2(mk(p_sa, p_sbP, p_P, 2048, 2048, 3264, p_ba, 0), MAXN,
          mk(p_sarel, p_sb, p_Q, 3072, 3072, 3072, nullptr, 0), 2 * RELSLOT);

    // ---- SAGE layer 1 edge pass ----
    edge_msg_kernel<<<E2, 256>>>(h_id, t_id, r_id, E, 0);
    node_update_kernel<<<(n_nodes * (EMB / 4) + 255) / 256, 256>>>(n_nodes, 0);

    // ---- SAGE layer 2 ----
    split_b(wmsg2, EMB, EMB, EMB, 1024, 3072, p_sb);
    split_b(wself2, EMB, EMB, EMB, 1024, 3072, p_sb + (size_t)1024 * 3072);
    gemm1(mk(p_sa2, p_sb, p_P, 2048, 2048, 3072, p_bb, 0), MAXN);
    edge_msg_kernel<<<E2, 256>>>(h_id, t_id, r_id, E, 256);
    node_update_kernel<<<(n_nodes * (EMB / 4) + 255) / 256, 256>>>(n_nodes, 1);

    // ---- predictor projections: merged [Asrc|Bdst], N=2048 (A' built in node_update) ----
    split_b(predw1 + (size_t)EMB * EMB, EMB, 2 * EMB, EMB, 2048, 6144, p_sb);
    split_b(predw1 + (size_t)4 * EMB * EMB, EMB, 2 * EMB, EMB, 2048, 6144, p_sb + (size_t)1024 * 6144);
    gemm1(mk(p_sa, p_sb, p_AB, 2048, 2048, 6144, nullptr, 0), MAXN);

    // ---- edge logits + gumbel + exact top-K ----
    edge_logits_kernel<<<E2, 256>>>(h_id, t_id, r_id, E, predw2, predb2);
    topk_kernel<<<1, 1024>>>(E2, 512);
    output_kernel<<<(E2 + 255) / 256, 256>>>((float*)d_out, E2);
}

// round 17
// speedup vs baseline: 3.0750x; 1.0046x over previous
#include <cuda_runtime.h>
#include <cuda_bf16.h>
#include <math.h>
#include <stdint.h>

#define EMB 1024
#define D0PAD 1032
#define MAXN 22016
#define RELSLOT 2048
#define MAXE2 40960
#define MAX_TIES 1024
#define KPMAX 6144

// ---------------- mma.sync GEMM tile config ----------------
#define BM 128
#define BN 128
#define BK 64
#define STAGE_BYTES 32768
#define NSTAGE 3
#define GSMEM (NSTAGE * STAGE_BYTES)

// ----------------------------------------------------------------------------
// Static scratch
// ----------------------------------------------------------------------------
__device__ float g_h0[(size_t)MAXN * D0PAD];
__device__ float g_relcat[(size_t)2 * RELSLOT * EMB];
__device__ float g_revh[(size_t)RELSLOT * EMB];
__device__ float g_Q[(size_t)2 * RELSLOT * 3072];   // merged [Q1|Q2|Qpred], ldc=3072
__device__ float g_P[(size_t)MAXN * 2 * EMB];       // merged [Pmsg|Pself], ldc=2048
__device__ float g_hnode[(size_t)MAXN * 2 * EMB];   // [h1 | h2]
__device__ float g_AB[(size_t)MAXN * 2 * EMB];      // [Asrc | Bdst], ldc=2048
__device__ float g_qb[EMB];
__device__ float g_bias2a[2 * EMB];
__device__ float g_bias2b[2 * EMB];
__device__ float g_y[MAXE2];
__device__ unsigned g_T;
__device__ int g_rem;
__device__ int g_tie[MAX_TIES];
// CSR
__device__ int g_cnt[MAXN];
__device__ int g_rowptr[MAXN + 1];
__device__ int g_fill[MAXN];
__device__ int g_eidx[MAXE2];
// bf16 split operand buffers
__device__ __nv_bfloat16 g_sa[(size_t)MAXN * KPMAX];            // A' (h0 / predictor)
__device__ __nv_bfloat16 g_sa2[(size_t)MAXN * 3072];            // A' (rev chain / h1)
__device__ __nv_bfloat16 g_sarel[(size_t)2 * RELSLOT * 3072];   // relcat A'
__device__ __nv_bfloat16 g_sb[(size_t)4096 * KPMAX];            // B' (multi-region)

// ----------------------------------------------------------------------------
// helpers
// ----------------------------------------------------------------------------
__device__ __forceinline__ uint32_t smem_u32(const void* p) {
    uint32_t a;
    asm("{ .reg .u64 t; cvta.to.shared.u64 t, %1; cvt.u32.u64 %0, t; }" : "=r"(a) : "l"(p));
    return a;
}
__device__ __forceinline__ int sw128(int row, int chk) {
    return row * 128 + (((chk) ^ (row & 7)) << 4);
}
__device__ __forceinline__ void cp16(uint32_t sa, const void* gp) {
    uint64_t ga;
    asm("cvta.to.global.u64 %0, %1;" : "=l"(ga) : "l"(gp));
    asm volatile("cp.async.cg.shared.global [%0], [%1], 16;" :: "r"(sa), "l"(ga) : "memory");
}
__device__ __forceinline__ unsigned short bfb(float x) {
    __nv_bfloat16 h = __float2bfloat16(x);
    return *reinterpret_cast<unsigned short*>(&h);
}
__device__ __forceinline__ float bff(unsigned short u) {
    __nv_bfloat16 h = *reinterpret_cast<__nv_bfloat16*>(&u);
    return __bfloat162float(h);
}

// ----------------------------------------------------------------------------
// Batched bf16 split GEMM (mma.sync + ldmatrix + cp.async 3-stage, BK=64)
// ----------------------------------------------------------------------------
struct GDesc {
    const __nv_bfloat16* A;
    const __nv_bfloat16* B;
    float* C;
    const float* bias;
    int ldc, KP, nbx, relu;
};

__global__ __launch_bounds__(128, 2)
void gemm_mma(GDesc d0, GDesc d1, int nb0)
{
    extern __shared__ __align__(1024) char smem[];
    GDesc d;
    int rb;
    if ((int)blockIdx.x < nb0) { d = d0; rb = blockIdx.x; }
    else                       { d = d1; rb = blockIdx.x - nb0; }
    const int bn0 = (rb % d.nbx) * BN;
    const int bm0 = (rb / d.nbx) * BM;

    const int tid  = threadIdx.x;
    const int wid  = tid >> 5;
    const int lane = tid & 31;
    const int wm0 = (wid & 1) * 64;
    const int wn0 = (wid >> 1) * 64;
    const uint32_t sbase = smem_u32(smem);
    const int KP = d.KP;

    const int midx = lane >> 3, mr = lane & 7;
    int aRowB[4], aRx[4];
#pragma unroll
    for (int ma = 0; ma < 4; ma++) {
        int r = wm0 + ma * 16 + (midx & 1) * 8 + mr;
        aRowB[ma] = r * 128; aRx[ma] = r & 7;
    }
    const int aCs = midx >> 1;
    int bRowB[4], bRx[4];
#pragma unroll
    for (int p = 0; p < 4; p++) {
        int r = wn0 + p * 16 + (midx >> 1) * 8 + mr;
        bRowB[p] = r * 128; bRx[p] = r & 7;
    }
    const int bCs = midx & 1;

    float c[4][8][4];
#pragma unroll
    for (int ma = 0; ma < 4; ma++)
#pragma unroll
        for (int na = 0; na < 8; na++)
#pragma unroll
            for (int i = 0; i < 4; i++) c[ma][na][i] = 0.f;

    const int nchunk = KP >> 6;

    auto issue_stage = [&](int ck) {
        if (ck < nchunk) {
            const int kc = ck * BK;
            const uint32_t st = sbase + (ck % NSTAGE) * STAGE_BYTES;
#pragma unroll
            for (int i = 0; i < 8; i++) {
                const int u = tid + 128 * i;
                const int row = u >> 3, chk = u & 7;
                cp16(st + sw128(row, chk),         d.A + (size_t)(bm0 + row) * KP + kc + chk * 8);
                cp16(st + 16384 + sw128(row, chk), d.B + (size_t)(bn0 + row) * KP + kc + chk * 8);
            }
        }
        asm volatile("cp.async.commit_group;" ::: "memory");
    };

    issue_stage(0);
    issue_stage(1);

    for (int ck = 0; ck < nchunk; ck++) {
        asm volatile("cp.async.wait_group 1;" ::: "memory");
        __syncthreads();
        issue_stage(ck + 2);

        const uint32_t stA = sbase + (ck % NSTAGE) * STAGE_BYTES;
        const uint32_t stB = stA + 16384;
#pragma unroll
        for (int s = 0; s < 4; s++) {
            uint32_t af[4][4], bf[8][2];
#pragma unroll
            for (int ma = 0; ma < 4; ma++) {
                uint32_t ad = stA + aRowB[ma] + ((((s << 1) + aCs) ^ aRx[ma]) << 4);
                asm volatile("ldmatrix.sync.aligned.m8n8.x4.shared.b16 {%0,%1,%2,%3}, [%4];"
                             : "=r"(af[ma][0]), "=r"(af[ma][1]), "=r"(af[ma][2]), "=r"(af[ma][3])
                             : "r"(ad));
            }
#pragma unroll
            for (int p = 0; p < 4; p++) {
                uint32_t bd = stB + bRowB[p] + ((((s << 1) + bCs) ^ bRx[p]) << 4);
                asm volatile("ldmatrix.sync.aligned.m8n8.x4.shared.b16 {%0,%1,%2,%3}, [%4];"
                             : "=r"(bf[2 * p][0]), "=r"(bf[2 * p][1]),
                               "=r"(bf[2 * p + 1][0]), "=r"(bf[2 * p + 1][1])
                             : "r"(bd));
            }
#pragma unroll
            for (int ma = 0; ma < 4; ma++)
#pragma unroll
                for (int na = 0; na < 8; na++)
                    asm volatile(
                        "mma.sync.aligned.m16n8k16.row.col.f32.bf16.bf16.f32 "
                        "{%0,%1,%2,%3}, {%4,%5,%6,%7}, {%8,%9}, {%0,%1,%2,%3};"
                        : "+f"(c[ma][na][0]), "+f"(c[ma][na][1]),
                          "+f"(c[ma][na][2]), "+f"(c[ma][na][3])
                        : "r"(af[ma][0]), "r"(af[ma][1]), "r"(af[ma][2]), "r"(af[ma][3]),
                          "r"(bf[na][0]), "r"(bf[na][1]));
        }
    }

    const int g = lane >> 2;
    const int q = lane & 3;
#pragma unroll
    for (int ma = 0; ma < 4; ma++) {
        const int row = bm0 + wm0 + ma * 16 + g;
#pragma unroll
        for (int na = 0; na < 8; na++) {
            const int col = bn0 + wn0 + na * 8 + q * 2;
            float v0 = c[ma][na][0], v1 = c[ma][na][1];
            float v2 = c[ma][na][2], v3 = c[ma][na][3];
            if (d.bias) {
                float bx = d.bias[col], by = d.bias[col + 1];
                v0 += bx; v1 += by; v2 += bx; v3 += by;
            }
            if (d.relu) {
                v0 = fmaxf(v0, 0.f); v1 = fmaxf(v1, 0.f);
                v2 = fmaxf(v2, 0.f); v3 = fmaxf(v3, 0.f);
            }
            *reinterpret_cast<float2*>(d.C + (size_t)row * d.ldc + col) = make_float2(v0, v1);
            *reinterpret_cast<float2*>(d.C + (size_t)(row + 8) * d.ldc + col) = make_float2(v2, v3);
        }
    }
}

// ----------------------------------------------------------------------------
// Split kernels
// ----------------------------------------------------------------------------
__global__ void split_a_kernel(const float* __restrict__ A, int lda, int M, int K,
                               int K64, int KP, __nv_bfloat16* __restrict__ out)
{
    long long idx = (long long)blockIdx.x * blockDim.x + threadIdx.x;
    long long total = (long long)M * K64;
    if (idx >= total) return;
    int row = (int)(idx / K64);
    int kk = (int)(idx % K64);
    float v = (kk < K) ? A[(size_t)row * lda + kk] : 0.f;
    __nv_bfloat16 hi = __float2bfloat16(v);
    __nv_bfloat16 lo = __float2bfloat16(v - __bfloat162float(hi));
    __nv_bfloat16* o = out + (size_t)row * KP;
    o[kk] = hi;
    o[K64 + kk] = lo;
    o[2 * K64 + kk] = hi;
}

__global__ void split_b_kernel(const float* __restrict__ W, int ldw, int K, int N,
                               int K64, int KP, __nv_bfloat16* __restrict__ out)
{
    __shared__ float t[32][33];
    int kk0 = blockIdx.y * 32, n0 = blockIdx.x * 32;
    int tx = threadIdx.x, ty = threadIdx.y;
#pragma unroll
    for (int j = 0; j < 32; j += 8) {
        int kk = kk0 + ty + j, n = n0 + tx;
        t[ty + j][tx] = (kk < K && n < N) ? W[(size_t)kk * ldw + n] : 0.f;
    }
    __syncthreads();
#pragma unroll
    for (int j = 0; j < 32; j += 8) {
        int n = n0 + ty + j, kk = kk0 + tx;
        if (n < N && kk < K64) {
            float v = t[tx][ty + j];
            __nv_bfloat16 hi = __float2bfloat16(v);
            __nv_bfloat16 lo = __float2bfloat16(v - __bfloat162float(hi));
            __nv_bfloat16* o = out + (size_t)n * KP;
            o[kk] = hi;
            o[K64 + kk] = hi;
            o[2 * K64 + kk] = lo;
        }
    }
}

// ----------------------------------------------------------------------------
// CSR build
// ----------------------------------------------------------------------------
__global__ void hist_kernel(const int* __restrict__ h_id, const int* __restrict__ t_id, int E) {
    int i = blockIdx.x * blockDim.x + threadIdx.x;
    if (i >= 2 * E) return;
    int dst = (i < E) ? t_id[i] : h_id[i - E];
    atomicAdd(&g_cnt[dst], 1);
}

__global__ void scan_kernel(int n_nodes, int E2) {   // 1 block, 256 threads
    __shared__ int ps[256];
    int tid = threadIdx.x;
    int chunk = (n_nodes + 255) / 256;
    int s = 0;
    for (int i = 0; i < chunk; i++) {
        int idx = tid * chunk + i;
        if (idx < n_nodes) s += g_cnt[idx];
    }
    ps[tid] = s;
    __syncthreads();
    for (int off = 1; off < 256; off <<= 1) {
        int v = (tid >= off) ? ps[tid - off] : 0;
        __syncthreads();
        if (tid >= off) ps[tid] += v;
        __syncthreads();
    }
    int run = (tid == 0) ? 0 : ps[tid - 1];
    for (int i = 0; i < chunk; i++) {
        int idx = tid * chunk + i;
        if (idx < n_nodes) {
            g_rowptr[idx] = run;
            g_fill[idx] = run;
            run += g_cnt[idx];
        }
    }
    if (tid == 0) g_rowptr[n_nodes] = E2;
}

__global__ void scatter_kernel(const int* __restrict__ h_id, const int* __restrict__ t_id, int E) {
    int i = blockIdx.x * blockDim.x + threadIdx.x;
    if (i >= 2 * E) return;
    int dst = (i < E) ? t_id[i] : h_id[i - E];
    int pos = atomicAdd(&g_fill[dst], 1);
    g_eidx[pos] = i;
}

// ----------------------------------------------------------------------------
// Other small kernels
// ----------------------------------------------------------------------------
__global__ void zero_kernel(float4* p, int n4) {
    int i = blockIdx.x * blockDim.x + threadIdx.x;
    int stride = gridDim.x * blockDim.x;
    float4 z = make_float4(0.f, 0.f, 0.f, 0.f);
    for (; i < n4; i += stride) p[i] = z;
}

__global__ void build_h0_kernel(const float* __restrict__ entity,
                                const float* __restrict__ nontext,
                                const float* __restrict__ topic,
                                int n_text, int n_nodes)
{
    int n = blockIdx.x;
    if (n >= n_nodes) return;
    float* dst = g_h0 + (size_t)n * D0PAD;
    const float* src = (n < n_text) ? (entity + (size_t)n * EMB) : nontext;
    for (int j = threadIdx.x; j < D0PAD; j += blockDim.x) {
        float v;
        if (j < EMB)          v = src[j];
        else if (j < EMB + 2) v = topic[(size_t)n * 2 + (j - EMB)];
        else                  v = 0.f;
        dst[j] = v;
    }
}

__global__ void relcat_kernel(const float* __restrict__ rel, int n_rel) {
    int i = blockIdx.x * blockDim.x + threadIdx.x;
    if (i >= RELSLOT * EMB) return;
    int row = i / EMB;
    g_relcat[i] = (row < n_rel) ? rel[i] : 0.f;
}

__global__ void concat_bias_kernel(const float* __restrict__ b1, const float* __restrict__ b2,
                                   float* __restrict__ dst) {
    int i = blockIdx.x * blockDim.x + threadIdx.x;
    if (i < EMB) dst[i] = b1[i];
    else if (i < 2 * EMB) dst[i] = b2[i - EMB];
}

__global__ void qb_kernel(const float* __restrict__ q, const float* __restrict__ predw1,
                          const float* __restrict__ predb1)
{
    int j = blockIdx.x * blockDim.x + threadIdx.x;
    if (j >= EMB) return;
    float acc = 0.f;
    for (int k = 0; k < EMB; k++) acc += q[k] * predw1[(size_t)k * EMB + j];
    g_qb[j] = acc + predb1[j];
}

// ----------------------------------------------------------------------------
// Fused SAGE layer: gather-reduce over CSR incoming edges + node update +
// bf16 split emission (replaces edge_msg + node_update + agg zero).
// Block = one dst node, 256 threads (one float4 lane each).
// ----------------------------------------------------------------------------
__global__ void sage_layer_kernel(const int* __restrict__ h_id, const int* __restrict__ t_id,
                                  const int* __restrict__ r_id, int E, int n_nodes,
                                  int layer, int qoff4)
{
    int n = blockIdx.x;
    if (n >= n_nodes) return;
    const int beg = g_rowptr[n], end = g_rowptr[n + 1];
    const int deg = end - beg;
    const int tid = threadIdx.x;
    __shared__ int lst[256];
    const bool small = (deg <= 256);
    if (small) {
        if (tid < deg) lst[tid] = g_eidx[beg + tid];
        __syncthreads();
        if (tid == 0 && deg > 1) {
            for (int a = 1; a < deg; a++) {
                int v = lst[a];
                int b = a - 1;
                while (b >= 0 && lst[b] > v) { lst[b + 1] = lst[b]; b--; }
                lst[b + 1] = v;
            }
        }
        __syncthreads();
    }
    float4 acc = make_float4(0.f, 0.f, 0.f, 0.f);
    for (int i = 0; i < deg; i++) {
        int e = small ? lst[i] : g_eidx[beg + i];
        int src, rel;
        if (e < E) { src = h_id[e]; rel = r_id[e]; }
        else       { src = t_id[e - E]; rel = RELSLOT + r_id[e - E]; }
        float4 pv = reinterpret_cast<const float4*>(g_P)[(size_t)src * 512 + tid];
        float4 qv = reinterpret_cast<const float4*>(g_Q)[(size_t)rel * 768 + qoff4 + tid];
        acc.x += fmaxf(pv.x + qv.x, 0.f);
        acc.y += fmaxf(pv.y + qv.y, 0.f);
        acc.z += fmaxf(pv.z + qv.z, 0.f);
        acc.w += fmaxf(pv.w + qv.w, 0.f);
    }
    float inv = 1.0f / (float)(deg > 1 ? deg : 1);
    float4 ps = reinterpret_cast<const float4*>(g_P)[(size_t)n * 512 + 256 + tid];
    float4 v;
    v.x = fmaxf(ps.x + acc.x * inv, 0.f);
    v.y = fmaxf(ps.y + acc.y * inv, 0.f);
    v.z = fmaxf(ps.z + acc.z * inv, 0.f);
    v.w = fmaxf(ps.w + acc.w * inv, 0.f);
    reinterpret_cast<float4*>(g_hnode + (size_t)n * 2 * EMB + (size_t)layer * EMB)[tid] = v;

    ushort4 hi4 = make_ushort4(bfb(v.x), bfb(v.y), bfb(v.z), bfb(v.w));
    ushort4 lo4 = make_ushort4(bfb(v.x - bff(hi4.x)), bfb(v.y - bff(hi4.y)),
                               bfb(v.z - bff(hi4.z)), bfb(v.w - bff(hi4.w)));
    const int k = tid * 4;
    if (layer == 0) {
        __nv_bfloat16* o2 = g_sa2 + (size_t)n * 3072;
        *reinterpret_cast<ushort4*>(o2 + k)        = hi4;
        *reinterpret_cast<ushort4*>(o2 + 1024 + k) = lo4;
        *reinterpret_cast<ushort4*>(o2 + 2048 + k) = hi4;
        __nv_bfloat16* oa = g_sa + (size_t)n * 6144;
        *reinterpret_cast<ushort4*>(oa + k)        = hi4;
        *reinterpret_cast<ushort4*>(oa + 2048 + k) = lo4;
        *reinterpret_cast<ushort4*>(oa + 4096 + k) = hi4;
    } else {
        __nv_bfloat16* oa = g_sa + (size_t)n * 6144;
        *reinterpret_cast<ushort4*>(oa + 1024 + k) = hi4;
        *reinterpret_cast<ushort4*>(oa + 3072 + k) = lo4;
        *reinterpret_cast<ushort4*>(oa + 5120 + k) = hi4;
    }
}

// ----------------------------------------------------------------------------
// RNG + logits + top-K + output
// ----------------------------------------------------------------------------
__device__ __forceinline__ void threefry2x32(unsigned k0, unsigned k1,
                                             unsigned& x0, unsigned& x1)
{
    unsigned ks2 = k0 ^ k1 ^ 0x1BD11BDAu;
    x0 += k0; x1 += k1;
#define TFR(r) { x0 += x1; x1 = (x1 << (r)) | (x1 >> (32 - (r))); x1 ^= x0; }
    TFR(13) TFR(15) TFR(26) TFR(6)
    x0 += k1;  x1 += ks2 + 1u;
    TFR(17) TFR(29) TFR(16) TFR(24)
    x0 += ks2; x1 += k0 + 2u;
    TFR(13) TFR(15) TFR(26) TFR(6)
    x0 += k0;  x1 += k1 + 3u;
    TFR(17) TFR(29) TFR(16) TFR(24)
    x0 += k1;  x1 += ks2 + 4u;
    TFR(13) TFR(15) TFR(26) TFR(6)
    x0 += ks2; x1 += k0 + 5u;
#undef TFR
}

__device__ __forceinline__ float gumbel_noise(int e) {
    unsigned x0 = 0u;
    unsigned x1 = (unsigned)e;
    threefry2x32(0u, 42u, x0, x1);
    unsigned bits = x0 ^ x1;
    float f = __uint_as_float((bits >> 9) | 0x3f800000u) - 1.0f;
    float u = fmaxf(1e-10f, f + 1e-10f);
    return -logf(-logf(u));
}

__global__ void edge_logits_kernel(const int* __restrict__ h_id, const int* __restrict__ t_id,
                                   const int* __restrict__ r_id, int E,
                                   const float* __restrict__ w2, const float* __restrict__ b2)
{
    int e = blockIdx.x;
    int src, dst, rel;
    if (e < E) { src = h_id[e]; dst = t_id[e]; rel = r_id[e]; }
    else { int e2 = e - E; src = t_id[e2]; dst = h_id[e2]; rel = RELSLOT + r_id[e2]; }
    int tid = threadIdx.x;
    float4 a  = reinterpret_cast<const float4*>(g_AB)[(size_t)src * 512 + tid];
    float4 b  = reinterpret_cast<const float4*>(g_AB)[(size_t)dst * 512 + 256 + tid];
    float4 rr = reinterpret_cast<const float4*>(g_Q)[(size_t)rel * 768 + 512 + tid];
    float4 qv = reinterpret_cast<const float4*>(g_qb)[tid];
    float4 w  = reinterpret_cast<const float4*>(w2)[tid];
    float acc = fmaxf(qv.x + a.x + rr.x + b.x, 0.f) * w.x
              + fmaxf(qv.y + a.y + rr.y + b.y, 0.f) * w.y
              + fmaxf(qv.z + a.z + rr.z + b.z, 0.f) * w.z
              + fmaxf(qv.w + a.w + rr.w + b.w, 0.f) * w.w;
#pragma unroll
    for (int o = 16; o; o >>= 1) acc += __shfl_xor_sync(0xffffffffu, acc, o);
    __shared__ float sred[8];
    if ((tid & 31) == 0) sred[tid >> 5] = acc;
    __syncthreads();
    if (tid == 0) {
        float s = 0.f;
#pragma unroll
        for (int wdx = 0; wdx < 8; wdx++) s += sred[wdx];
        g_y[e] = s + b2[0] + gumbel_noise(e);
    }
}

__device__ __forceinline__ unsigned f2key(float v) {
    unsigned b = __float_as_uint(v);
    return (b & 0x80000000u) ? ~b : (b | 0x80000000u);
}

__global__ void topk_kernel(int n, int K) {
    __shared__ unsigned hist[256];
    __shared__ unsigned s_prefix;
    __shared__ int s_krem;
    __shared__ int s_cnt;
    int tid = threadIdx.x;
    if (tid == 0) { s_prefix = 0; s_krem = K; s_cnt = 0; }
    __syncthreads();
    for (int pass = 3; pass >= 0; pass--) {
        int shift = pass * 8;
        if (tid < 256) hist[tid] = 0;
        __syncthreads();
        unsigned prefix = s_prefix;
        for (int i = tid; i < n; i += blockDim.x) {
            unsigned key = f2key(g_y[i]);
            bool match = (pass == 3) || ((key >> (shift + 8)) == (prefix >> (shift + 8)));
            if (match) atomicAdd(&hist[(key >> shift) & 255], 1u);
        }
        __syncthreads();
        if (tid == 0) {
            int krem = s_krem;
            unsigned cum = 0;
            int b = 255;
            for (; b >= 0; b--) {
                if (cum + hist[b] >= (unsigned)krem) break;
                cum += hist[b];
            }
            if (b < 0) b = 0;
            s_prefix = prefix | ((unsigned)b << shift);
            s_krem = krem - (int)cum;
        }
        __syncthreads();
    }
    unsigned T = s_prefix;
    int rem = s_krem;
    for (int i = tid; i < n; i += blockDim.x) {
        if (f2key(g_y[i]) == T) {
            int p = atomicAdd(&s_cnt, 1);
            if (p < MAX_TIES) g_tie[p] = i;
        }
    }
    __syncthreads();
    if (tid == 0) {
        int c = s_cnt < MAX_TIES ? s_cnt : MAX_TIES;
        for (int a = 1; a < c; a++) {
            int v = g_tie[a];
            int b = a - 1;
            while (b >= 0 && g_tie[b] > v) { g_tie[b + 1] = g_tie[b]; b--; }
            g_tie[b + 1] = v;
        }
        if (rem > c) rem = c;
        if (rem < 0) rem = 0;
        g_T = T;
        g_rem = rem;
    }
}

__global__ void output_kernel(float* __restrict__ out, int n) {
    int i = blockIdx.x * blockDim.x + threadIdx.x;
    if (i >= n) return;
    unsigned key = f2key(g_y[i]);
    float o = 0.f;
    unsigned T = g_T;
    if (key > T) o = 1.f;
    else if (key == T) {
        int rem = g_rem;
        for (int t = 0; t < rem; t++)
            if (g_tie[t] == i) { o = 1.f; break; }
    }
    out[i] = o;
}

// ----------------------------------------------------------------------------
// Host-side helpers
// ----------------------------------------------------------------------------
static void split_a(const float* A, int lda, int M, int K, int K64, int KP, __nv_bfloat16* out) {
    long long total = (long long)M * K64;
    int blocks = (int)((total + 255) / 256);
    split_a_kernel<<<blocks, 256>>>(A, lda, M, K, K64, KP, out);
}
static void split_b(const float* W, int ldw, int K, int N, int K64, int KP, __nv_bfloat16* out) {
    dim3 grid((N + 31) / 32, (K64 + 31) / 32);
    split_b_kernel<<<grid, dim3(32, 8)>>>(W, ldw, K, N, K64, KP, out);
}
static GDesc mk(const __nv_bfloat16* A, const __nv_bfloat16* B, float* C,
                int ldc, int N, int KP, const float* bias, int relu) {
    GDesc d; d.A = A; d.B = B; d.C = C; d.bias = bias;
    d.ldc = ldc; d.KP = KP; d.nbx = N / BN; d.relu = relu;
    return d;
}
static void gemm1(GDesc d, int M) {
    int nb = (M / BM) * d.nbx;
    gemm_mma<<<nb, 128, GSMEM>>>(d, d, nb);
}
static void gemm2(GDesc a, int Ma, GDesc b, int Mb) {
    int na = (Ma / BM) * a.nbx;
    int nb = (Mb / BM) * b.nbx;
    gemm_mma<<<na + nb, 128, GSMEM>>>(a, b, na);
}

extern "C" void kernel_launch(void* const* d_in, const int* in_sizes, int n_in,
                              void* d_out, int out_size)
{
    cudaFuncSetAttribute(gemm_mma, cudaFuncAttributeMaxDynamicSharedMemorySize, GSMEM);

    const int* h_id = (const int*)d_in[0];
    const int* t_id = (const int*)d_in[1];
    const int* r_id = (const int*)d_in[2];
    const int s = (n_in >= 25) ? 1 : 0;
    const int b0 = 3 + s;
    const float* q_emb   = (const float*)d_in[b0 + 0];
    const float* entity  = (const float*)d_in[b0 + 1];
    const float* rel     = (const float*)d_in[b0 + 2];
    const float* topic   = (const float*)d_in[b0 + 3];
    const float* nontext = (const float*)d_in[b0 + 4];
    const float* wself1  = (const float*)d_in[b0 + 5];
    const float* bself1  = (const float*)d_in[b0 + 6];
    const float* wmsg1   = (const float*)d_in[b0 + 7];
    const float* bmsg1   = (const float*)d_in[b0 + 8];
    const float* wself2  = (const float*)d_in[b0 + 9];
    const float* bself2  = (const float*)d_in[b0 + 10];
    const float* wmsg2   = (const float*)d_in[b0 + 11];
    const float* bmsg2   = (const float*)d_in[b0 + 12];
    const float* revw1   = (const float*)d_in[b0 + 13];
    const float* revb1   = (const float*)d_in[b0 + 14];
    const float* revw2   = (const float*)d_in[b0 + 15];
    const float* revb2   = (const float*)d_in[b0 + 16];
    const float* predw1  = (const float*)d_in[b0 + 17];
    const float* predb1  = (const float*)d_in[b0 + 18];
    const float* predw2  = (const float*)d_in[b0 + 19];
    const float* predb2  = (const float*)d_in[b0 + 20];

    const int E       = in_sizes[0];
    const int n_text  = in_sizes[b0 + 1] / EMB;
    const int n_rel   = in_sizes[b0 + 2] / EMB;
    const int n_nodes = in_sizes[b0 + 3] / 2;
    const int d0      = in_sizes[b0 + 5] / EMB;   // 1026
    const int E2      = 2 * E;
    if (n_nodes > MAXN || E2 > MAXE2 || n_rel > RELSLOT) return;

    float *p_h0, *p_relcat, *p_revh, *p_Q, *p_P, *p_AB, *p_ba, *p_bb;
    int *p_cnt;
    __nv_bfloat16 *p_sa, *p_sa2, *p_sarel, *p_sb;
    cudaGetSymbolAddress((void**)&p_h0,     g_h0);
    cudaGetSymbolAddress((void**)&p_relcat, g_relcat);
    cudaGetSymbolAddress((void**)&p_revh,   g_revh);
    cudaGetSymbolAddress((void**)&p_Q,      g_Q);
    cudaGetSymbolAddress((void**)&p_P,      g_P);
    cudaGetSymbolAddress((void**)&p_AB,     g_AB);
    cudaGetSymbolAddress((void**)&p_ba,     g_bias2a);
    cudaGetSymbolAddress((void**)&p_bb,     g_bias2b);
    cudaGetSymbolAddress((void**)&p_cnt,    g_cnt);
    cudaGetSymbolAddress((void**)&p_sa,     g_sa);
    cudaGetSymbolAddress((void**)&p_sa2,    g_sa2);
    cudaGetSymbolAddress((void**)&p_sarel,  g_sarel);
    cudaGetSymbolAddress((void**)&p_sb,     g_sb);

    // B' region offsets (concurrent-lifetime safe)
    __nv_bfloat16* sbQ    = p_sb;                                     // 3072 x 3072
    __nv_bfloat16* sbP    = p_sb + (size_t)3072 * 3072;               // 2048 x 3264
    __nv_bfloat16* sbR1   = sbP + (size_t)2048 * 3264;                // 1024 x 3072
    __nv_bfloat16* sbR2   = sbR1 + (size_t)1024 * 3072;               // 1024 x 3072

    // ---- prep ----
    zero_kernel<<<32, 256>>>((float4*)p_cnt, MAXN / 4);
    build_h0_kernel<<<n_nodes, 256>>>(entity, nontext, topic, n_text, n_nodes);
    relcat_kernel<<<(RELSLOT * EMB + 255) / 256, 256>>>(rel, n_rel);
    concat_bias_kernel<<<8, 256>>>(bmsg1, bself1, p_ba);
    concat_bias_kernel<<<8, 256>>>(bmsg2, bself2, p_bb);
    qb_kernel<<<4, 256>>>(q_emb, predw1, predb1);
    hist_kernel<<<(E2 + 255) / 256, 256>>>(h_id, t_id, E);
    scan_kernel<<<1, 256>>>(n_nodes, E2);
    scatter_kernel<<<(E2 + 255) / 256, 256>>>(h_id, t_id, E);

    // ---- splits for rev chain + P1 ----
    split_a(p_relcat, EMB, RELSLOT, EMB, 1024, 3072, p_sa2);          // relcat fwd A'
    split_b(revw1, EMB, EMB, EMB, 1024, 3072, sbR1);
    split_b(revw2, EMB, EMB, EMB, 1024, 3072, sbR2);
    split_a(p_h0, D0PAD, MAXN, D0PAD, 1088, 3264, p_sa);              // h0 A'
    split_b(wmsg1, EMB, d0, EMB, 1088, 3264, sbP);
    split_b(wself1, EMB, d0, EMB, 1088, 3264, sbP + (size_t)1024 * 3264);

    // ---- batched: P1 half-1 + rev1 ----
    gemm2(mk(p_sa, sbP, p_P, 2048, 2048, 3264, p_ba, 0), 11008,
          mk(p_sa2, sbR1, p_revh, EMB, EMB, 3072, revb1, 1), RELSLOT);
    split_a(p_revh, EMB, RELSLOT, EMB, 1024, 3072, p_sa2);            // revh A'
    // ---- batched: P1 half-2 + rev2 ----
    gemm2(mk(p_sa + (size_t)11008 * 3264, sbP, p_P + (size_t)11008 * 2048, 2048, 2048, 3264, p_ba, 0), 11008,
          mk(p_sa2, sbR2, p_relcat + (size_t)RELSLOT * EMB, EMB, EMB, 3072, revb2, 0), RELSLOT);

    // ---- merged relation projections Q (fwd+rev), N=3072 ----
    split_a(p_relcat, EMB, 2 * RELSLOT, EMB, 1024, 3072, p_sarel);
    split_b(wmsg1 + (size_t)d0 * EMB, EMB, EMB, EMB, 1024, 3072, sbQ);
    split_b(wmsg2 + (size_t)EMB * EMB, EMB, EMB, EMB, 1024, 3072, sbQ + (size_t)1024 * 3072);
    split_b(predw1 + (size_t)3 * EMB * EMB, EMB, EMB, EMB, 1024, 3072, sbQ + (size_t)2048 * 3072);
    gemm1(mk(p_sarel, sbQ, p_Q, 3072, 3072, 3072, nullptr, 0), 2 * RELSLOT);

    // ---- SAGE layer 1 (fused aggregate + update + splits) ----
    sage_layer_kernel<<<n_nodes, 256>>>(h_id, t_id, r_id, E, n_nodes, 0, 0);

    // ---- SAGE layer 2 ----
    split_b(wmsg2, EMB, EMB, EMB, 1024, 3072, sbQ);
    split_b(wself2, EMB, EMB, EMB, 1024, 3072, sbQ + (size_t)1024 * 3072);
    gemm1(mk(p_sa2, sbQ, p_P, 2048, 2048, 3072, p_bb, 0), MAXN);
    sage_layer_kernel<<<n_nodes, 256>>>(h_id, t_id, r_id, E, n_nodes, 1, 256);

    // ---- predictor projections (A' built in sage_layer), N=2048 ----
    split_b(predw1 + (size_t)EMB * EMB, EMB, 2 * EMB, EMB, 2048, 6144, sbQ);
    split_b(predw1 + (size_t)4 * EMB * EMB, EMB, 2 * EMB, EMB, 2048, 6144, sbQ + (size_t)1024 * 6144);
    gemm1(mk(p_sa, sbQ, p_AB, 2048, 2048, 6144, nullptr, 0), MAXN);

    // ---- edge logits + gumbel + exact top-K ----
    edge_logits_kernel<<<E2, 256>>>(h_id, t_id, r_id, E, predw2, predb2);
    topk_kernel<<<1, 1024>>>(E2, 512);
    output_kernel<<<(E2 + 255) / 256, 256>>>((float*)d_out, E2);
}